// round 10
// baseline (speedup 1.0000x reference)
#include <cuda_runtime.h>
#include <cuda_fp16.h>
#include <math.h>
#include <stdint.h>

#define NNODE 50000
#define NEDGE 500000
#define DMAX  256
#define EPS_SM 1e-16f
#define EPS_LN 1e-5f
#define NEG_SLOPE 0.2f

// ---------------- scratch (device globals) ----------------
__device__ __half g_h16[NNODE * DMAX];          // GEMM output (fp16)
__device__ float g_alpha[NEDGE * 4];            // edge exp scores (CSR order)
__device__ float g_denomA[NNODE * 4];
__device__ float g_denomB[NNODE * 4];
__device__ float g_score[NNODE * 8];            // ssrc | sdst
__device__ int   g_cnt[NNODE];
__device__ int   g_rptr[NNODE + 1];
__device__ int   g_fill[NNODE];
__device__ int   g_epos[NEDGE];                 // edge -> CSR slot
__device__ int   g_rcol[NEDGE];                 // neighbor col in CSR order
__device__ __half g_ahi[NNODE * 384];           // activation hi (fp16)
__device__ __half g_alo[NNODE * 384];           // activation lo (fp16)
__device__ __half g_wt[256 * 384];              // transposed weight fp16 [N][K]

// ================= PTX helpers =================
__device__ __forceinline__ uint32_t smem_u32(const void* p) {
    uint32_t a;
    asm("{ .reg .u64 t; cvta.to.shared.u64 t, %1; cvt.u32.u64 %0, t; }" : "=r"(a) : "l"(p));
    return a;
}

#define CPA16(dst, src, sz) \
    asm volatile("cp.async.cg.shared.global [%0], [%1], 16, %2;" \
                 :: "r"(dst), "l"(src), "r"(sz))
#define CPA_COMMIT() asm volatile("cp.async.commit_group;" ::: "memory")
#define CPA_WAIT(n)  asm volatile("cp.async.wait_group %0;" :: "n"(n) : "memory")

#define LDMX4(r0, r1, r2, r3, addr) \
    asm volatile("ldmatrix.sync.aligned.m8n8.x4.shared.b16 {%0,%1,%2,%3}, [%4];" \
                 : "=r"(r0), "=r"(r1), "=r"(r2), "=r"(r3) : "r"(addr))

__device__ __forceinline__ void mma16816h(float* c, const uint32_t* a, const uint32_t* b) {
    asm volatile(
        "mma.sync.aligned.m16n8k16.row.col.f32.f16.f16.f32 "
        "{%0,%1,%2,%3}, {%4,%5,%6,%7}, {%8,%9}, {%0,%1,%2,%3};"
        : "+f"(c[0]), "+f"(c[1]), "+f"(c[2]), "+f"(c[3])
        : "r"(a[0]), "r"(a[1]), "r"(a[2]), "r"(a[3]), "r"(b[0]), "r"(b[1]));
}

#define SWZ64(b) ((b) ^ (((b) >> 3) & 0x30))

// ---------------- small utility ----------------
__global__ void zero_i(int* p, int n) {
    int i = blockIdx.x * blockDim.x + threadIdx.x;
    if (i < n) p[i] = 0;
}

// ---------------- asplit + wprep1 + zero score/denomA ----------------
__global__ void asplit_fused_kernel(
    const float* __restrict__ A, __half* hi, __half* lo, int total,
    const float* __restrict__ W, __half* wt, int K, int Nn,
    float* score, int nscore, float* den, int nden)
{
    int i = blockIdx.x * blockDim.x + threadIdx.x;
    if (i < total) {
        float v = A[i];
        __half h = __float2half(v);
        hi[i] = h;
        lo[i] = __float2half(v - __half2float(h));
    }
    if (i < K * Nn) {
        int n = i / K, k = i - n * K;
        wt[i] = __float2half(W[(size_t)k * Nn + n]);
    }
    if (i < nscore) score[i] = 0.0f;
    if (i < nden) den[i] = 0.0f;
}

// ---------------- CSR build ----------------
__global__ void hist_kernel(const int* __restrict__ row, int* cnt, int e) {
    int i = blockIdx.x * blockDim.x + threadIdx.x;
    if (i < e) atomicAdd(&cnt[row[i]], 1);
}

__global__ void scan_kernel(const int* __restrict__ cnt, int* ptr, int* fill, int n) {
    __shared__ int sh[1024];
    __shared__ int carry;
    if (threadIdx.x == 0) carry = 0;
    __syncthreads();
    for (int base = 0; base < n; base += 1024) {
        int i = base + threadIdx.x;
        int v = (i < n) ? cnt[i] : 0;
        sh[threadIdx.x] = v;
        __syncthreads();
        for (int off = 1; off < 1024; off <<= 1) {
            int t = (threadIdx.x >= off) ? sh[threadIdx.x - off] : 0;
            __syncthreads();
            sh[threadIdx.x] += t;
            __syncthreads();
        }
        int excl = sh[threadIdx.x] - v;
        if (i < n) { ptr[i] = carry + excl; fill[i] = carry + excl; }
        __syncthreads();
        if (threadIdx.x == 1023) carry += sh[1023];
        __syncthreads();
    }
    if (threadIdx.x == 0) ptr[n] = carry;
}

__global__ void scatter_kernel(const int* __restrict__ row, const int* __restrict__ col,
                               int* fill, int* epos, int* rcol, int e) {
    int i = blockIdx.x * blockDim.x + threadIdx.x;
    if (i < e) {
        int pos = atomicAdd(&fill[row[i]], 1);
        epos[i] = pos;
        rcol[pos] = col[i];
    }
}

// ===== HMMA fp16 2-term GEMM 128x128 tile + fused attention scores =====
template <int NN, int KK>
__global__ __launch_bounds__(256, 2) void gemm_mma(
    const __half* __restrict__ Ahi, const __half* __restrict__ Alo,
    const __half* __restrict__ Bw,
    __half* __restrict__ C,
    const float* __restrict__ Av, const float* __restrict__ Dv,
    float* __restrict__ Ssrc, float* __restrict__ Sdst,
    int H, int Cc, int M)
{
    constexpr int BK = 32;
    constexpr int NCH = KK / BK;
    constexpr int STG = 24576;   // A hi 8K | A lo 8K | B 8K
    extern __shared__ char smem[];
    uint32_t sb = smem_u32(smem);

    int tid = threadIdx.x;
    int lane = tid & 31, wid = tid >> 5;
    int wm = wid & 3, wn = wid >> 2;
    int m0 = blockIdx.y * 128;
    int n0 = blockIdx.x * 128;

    int g = lane >> 3, lr = lane & 7;
    uint32_t aoff[2][2];
#pragma unroll
    for (int mt = 0; mt < 2; mt++)
#pragma unroll
        for (int ks = 0; ks < 2; ks++) {
            int row = wm * 32 + mt * 16 + (g & 1) * 8 + lr;
            int unit = ks * 2 + (g >> 1);
            aoff[mt][ks] = SWZ64(row * 64 + unit * 16);
        }
    uint32_t boff[4][2];
#pragma unroll
    for (int np = 0; np < 4; np++)
#pragma unroll
        for (int ks = 0; ks < 2; ks++) {
            int row = wn * 64 + np * 16 + (g >> 1) * 8 + lr;
            int unit = ks * 2 + (g & 1);
            boff[np][ks] = 16384u + SWZ64(row * 64 + unit * 16);
        }

    int r0 = tid >> 2, u0 = tid & 3;
    uint32_t sw0 = SWZ64(r0 * 64 + u0 * 16);
    uint32_t sw1 = SWZ64((r0 + 64) * 64 + u0 * 16);
    long bofs0 = (long)(n0 + r0) * KK + u0 * 8;
    long bofs1 = (long)(n0 + r0 + 64) * KK + u0 * 8;

    float acc[2][8][4];
#pragma unroll
    for (int mt = 0; mt < 2; mt++)
#pragma unroll
        for (int nt = 0; nt < 8; nt++)
#pragma unroll
            for (int j = 0; j < 4; j++) acc[mt][nt][j] = 0.f;

    auto load_stage = [&](int ch, uint32_t so) {
        int k0 = ch * BK;
        {
            int grow = m0 + r0;
            int sz = (grow < M) ? 16 : 0;
            long go = (long)((grow < M) ? grow : 0) * KK + k0 + u0 * 8;
            CPA16(sb + so + sw0, Ahi + go, sz);
            CPA16(sb + so + 8192 + sw0, Alo + go, sz);
        }
        {
            int grow = m0 + r0 + 64;
            int sz = (grow < M) ? 16 : 0;
            long go = (long)((grow < M) ? grow : 0) * KK + k0 + u0 * 8;
            CPA16(sb + so + sw1, Ahi + go, sz);
            CPA16(sb + so + 8192 + sw1, Alo + go, sz);
        }
        CPA16(sb + so + 16384 + sw0, Bw + bofs0 + k0, 16);
        CPA16(sb + so + 16384 + sw1, Bw + bofs1 + k0, 16);
    };

    auto compute_stage = [&](uint32_t so) {
#pragma unroll
        for (int ks = 0; ks < 2; ks++) {
            uint32_t ah[2][4], al[2][4], b[8][2];
#pragma unroll
            for (int mt = 0; mt < 2; mt++) {
                LDMX4(ah[mt][0], ah[mt][1], ah[mt][2], ah[mt][3], sb + so + aoff[mt][ks]);
                LDMX4(al[mt][0], al[mt][1], al[mt][2], al[mt][3], sb + so + 8192 + aoff[mt][ks]);
            }
#pragma unroll
            for (int np = 0; np < 4; np++)
                LDMX4(b[2 * np][0], b[2 * np][1], b[2 * np + 1][0], b[2 * np + 1][1],
                      sb + so + boff[np][ks]);
#pragma unroll
            for (int mt = 0; mt < 2; mt++)
#pragma unroll
                for (int nt = 0; nt < 8; nt++) {
                    mma16816h(acc[mt][nt], ah[mt], b[nt]);
                    mma16816h(acc[mt][nt], al[mt], b[nt]);
                }
        }
    };

    load_stage(0, 0);
    CPA_COMMIT();
    load_stage(1, STG);
    CPA_COMMIT();
#pragma unroll 1
    for (int ch = 0; ch < NCH; ch++) {
        uint32_t so = (uint32_t)(ch % 3) * STG;
        if (ch + 1 < NCH) { CPA_WAIT(1); } else { CPA_WAIT(0); }
        __syncthreads();
        if (ch + 2 < NCH) {
            load_stage(ch + 2, (uint32_t)((ch + 2) % 3) * STG);
            CPA_COMMIT();
        }
        compute_stage(so);
    }

    // ---- epilogue 1: fp16 h store ----
#pragma unroll
    for (int mt = 0; mt < 2; mt++) {
        int m = m0 + wm * 32 + mt * 16 + (lane >> 2);
#pragma unroll
        for (int nt = 0; nt < 8; nt++) {
            int n = n0 + wn * 64 + nt * 8 + (lane & 3) * 2;
            if (m < M)
                *reinterpret_cast<__half2*>(C + (size_t)m * NN + n) =
                    __floats2half2_rn(acc[mt][nt][0], acc[mt][nt][1]);
            if (m + 8 < M)
                *reinterpret_cast<__half2*>(C + (size_t)(m + 8) * NN + n) =
                    __floats2half2_rn(acc[mt][nt][2], acc[mt][nt][3]);
        }
    }

    // ---- epilogue 2: fused attention scores ----
    {
        int head = (n0 + wn * 64) / Cc;
        float av[16], dv[16];
#pragma unroll
        for (int nt = 0; nt < 8; nt++) {
            int c0 = (n0 + wn * 64 + nt * 8 + (lane & 3) * 2) - head * Cc;
            av[2 * nt] = Av[head * Cc + c0];
            av[2 * nt + 1] = Av[head * Cc + c0 + 1];
            dv[2 * nt] = Dv[head * Cc + c0];
            dv[2 * nt + 1] = Dv[head * Cc + c0 + 1];
        }
#pragma unroll
        for (int mt = 0; mt < 2; mt++) {
            float ps0 = 0.f, pd0 = 0.f, ps1 = 0.f, pd1 = 0.f;
#pragma unroll
            for (int nt = 0; nt < 8; nt++) {
                ps0 += acc[mt][nt][0] * av[2 * nt] + acc[mt][nt][1] * av[2 * nt + 1];
                pd0 += acc[mt][nt][0] * dv[2 * nt] + acc[mt][nt][1] * dv[2 * nt + 1];
                ps1 += acc[mt][nt][2] * av[2 * nt] + acc[mt][nt][3] * av[2 * nt + 1];
                pd1 += acc[mt][nt][2] * dv[2 * nt] + acc[mt][nt][3] * dv[2 * nt + 1];
            }
#pragma unroll
            for (int o = 1; o <= 2; o <<= 1) {
                ps0 += __shfl_xor_sync(0xffffffffu, ps0, o);
                pd0 += __shfl_xor_sync(0xffffffffu, pd0, o);
                ps1 += __shfl_xor_sync(0xffffffffu, ps1, o);
                pd1 += __shfl_xor_sync(0xffffffffu, pd1, o);
            }
            if ((lane & 3) == 0) {
                int m = m0 + wm * 32 + mt * 16 + (lane >> 2);
                if (m < M) {
                    atomicAdd(&Ssrc[m * H + head], ps0);
                    atomicAdd(&Sdst[m * H + head], pd0);
                }
                if (m + 8 < M) {
                    atomicAdd(&Ssrc[(m + 8) * H + head], ps1);
                    atomicAdd(&Sdst[(m + 8) * H + head], pd1);
                }
            }
        }
    }
}

// ---------------- edge scores H=4: write alpha at CSR slot ----------------
__global__ void edge_scores4_kernel(
    const int* __restrict__ row, const int* __restrict__ col, const float* __restrict__ ew,
    const int* __restrict__ epos,
    const float* __restrict__ ssrc, const float* __restrict__ sdst,
    float* __restrict__ aexp, float* __restrict__ denom, int e)
{
    int i = blockIdx.x * blockDim.x + threadIdx.x;
    if (i >= e) return;
    int r = row[i], c = col[i];
    float w = ew[i];
    float4 s4 = *reinterpret_cast<const float4*>(ssrc + (size_t)r * 4);
    float4 d4 = *reinterpret_cast<const float4*>(sdst + (size_t)c * 4);
    float4 o;
    float v;
    v = s4.x + d4.x; v = (v >= 0.f) ? v : NEG_SLOPE * v; o.x = expf(v * w);
    v = s4.y + d4.y; v = (v >= 0.f) ? v : NEG_SLOPE * v; o.y = expf(v * w);
    v = s4.z + d4.z; v = (v >= 0.f) ? v : NEG_SLOPE * v; o.z = expf(v * w);
    v = s4.w + d4.w; v = (v >= 0.f) ? v : NEG_SLOPE * v; o.w = expf(v * w);
    int p = epos[i];
    *reinterpret_cast<float4*>(aexp + (size_t)p * 4) = o;
    atomicAdd(&denom[c * 4 + 0], o.x);
    atomicAdd(&denom[c * 4 + 1], o.y);
    atomicAdd(&denom[c * 4 + 2], o.z);
    atomicAdd(&denom[c * 4 + 3], o.w);
}

// ---------------- edge scores H=1 ----------------
__global__ void edge_scores1_kernel(
    const int* __restrict__ row, const int* __restrict__ col, const float* __restrict__ ew,
    const int* __restrict__ epos,
    const float* __restrict__ ssrc, const float* __restrict__ sdst,
    float* __restrict__ aexp, float* __restrict__ denom, int e)
{
    int i = blockIdx.x * blockDim.x + threadIdx.x;
    if (i >= e) return;
    int r = row[i], c = col[i];
    float v = ssrc[r] + sdst[c];
    v = (v >= 0.f) ? v : NEG_SLOPE * v;
    v = expf(v * ew[i]);
    aexp[epos[i]] = v;
    atomicAdd(&denom[c], v);
}

// ===== fused aggregation(D=256,H=4) + bias + LN + ELU + fp16 split
//       + next-layer wprep + zero score/denom =====
__global__ __launch_bounds__(256) void aggln256_kernel(
    const __half* __restrict__ h, const float* __restrict__ aexp, const float* __restrict__ denom,
    const int* __restrict__ rcol, const int* __restrict__ rptr,
    const float* __restrict__ bias, const float* __restrict__ gam, const float* __restrict__ bet,
    __half* __restrict__ hi, __half* __restrict__ lo, int n,
    const float* __restrict__ Wnext, __half* wt, int K, int Nn,
    float* score_z, int nscore, float* den_z, int nden)
{
    int gt = blockIdx.x * blockDim.x + threadIdx.x;
    // folded side-work (consumers launch later)
    if (gt < nscore) score_z[gt] = 0.0f;
    if (gt < nden) den_z[gt] = 0.0f;
    if (Wnext && gt < K * Nn) {
        int nn = gt / K, k = gt - nn * K;
        wt[gt] = __float2half(Wnext[(size_t)k * Nn + nn]);
    }

    int warp = gt >> 5;
    int lane = threadIdx.x & 31;
    if (warp >= n) return;
    int hh = lane >> 3;
    float acc[8];
#pragma unroll
    for (int j = 0; j < 8; j++) acc[j] = 0.f;
    int s = rptr[warp], e1 = rptr[warp + 1];
    int i = s;
    for (; i + 1 < e1; i += 2) {
        int ca = rcol[i], cb = rcol[i + 1];
        float aa = aexp[(size_t)i * 4 + hh];
        float ab = aexp[(size_t)(i + 1) * 4 + hh];
        float wa = aa / (denom[(size_t)ca * 4 + hh] + EPS_SM);
        float wb = ab / (denom[(size_t)cb * 4 + hh] + EPS_SM);
        uint4 ra = *reinterpret_cast<const uint4*>(h + (size_t)ca * 256 + lane * 8);
        uint4 rb = *reinterpret_cast<const uint4*>(h + (size_t)cb * 256 + lane * 8);
        const __half2* pa = reinterpret_cast<const __half2*>(&ra);
        const __half2* pb = reinterpret_cast<const __half2*>(&rb);
#pragma unroll
        for (int j = 0; j < 4; j++) {
            float2 fa = __half22float2(pa[j]);
            float2 fb = __half22float2(pb[j]);
            acc[2 * j]     += wa * fa.x + wb * fb.x;
            acc[2 * j + 1] += wa * fa.y + wb * fb.y;
        }
    }
    if (i < e1) {
        int c = rcol[i];
        float a = aexp[(size_t)i * 4 + hh];
        float w = a / (denom[(size_t)c * 4 + hh] + EPS_SM);
        uint4 r = *reinterpret_cast<const uint4*>(h + (size_t)c * 256 + lane * 8);
        const __half2* p = reinterpret_cast<const __half2*>(&r);
#pragma unroll
        for (int j = 0; j < 4; j++) {
            float2 f = __half22float2(p[j]);
            acc[2 * j]     += w * f.x;
            acc[2 * j + 1] += w * f.y;
        }
    }
    const float4* bp = reinterpret_cast<const float4*>(bias + lane * 8);
    float4 b0 = bp[0], b1 = bp[1];
    acc[0] += b0.x; acc[1] += b0.y; acc[2] += b0.z; acc[3] += b0.w;
    acc[4] += b1.x; acc[5] += b1.y; acc[6] += b1.z; acc[7] += b1.w;
    float sum = 0.f, sumsq = 0.f;
#pragma unroll
    for (int j = 0; j < 8; j++) { sum += acc[j]; sumsq += acc[j] * acc[j]; }
#pragma unroll
    for (int o = 16; o; o >>= 1) {
        sum += __shfl_xor_sync(0xffffffffu, sum, o);
        sumsq += __shfl_xor_sync(0xffffffffu, sumsq, o);
    }
    float mu = sum * (1.0f / 256.0f);
    float var = sumsq * (1.0f / 256.0f) - mu * mu;
    float r = rsqrtf(var + EPS_LN);
    const float4* gp = reinterpret_cast<const float4*>(gam + lane * 8);
    const float4* ep = reinterpret_cast<const float4*>(bet + lane * 8);
    float4 g0 = gp[0], g1 = gp[1], e0 = ep[0], e1v = ep[1];
    float gg[8] = {g0.x, g0.y, g0.z, g0.w, g1.x, g1.y, g1.z, g1.w};
    float ee[8] = {e0.x, e0.y, e0.z, e0.w, e1v.x, e1v.y, e1v.z, e1v.w};
    union { __half2 h2[4]; uint4 u; } uh, ul;
#pragma unroll
    for (int j = 0; j < 4; j++) {
        float y0 = (acc[2 * j] - mu) * r * gg[2 * j] + ee[2 * j];
        float y1 = (acc[2 * j + 1] - mu) * r * gg[2 * j + 1] + ee[2 * j + 1];
        y0 = (y0 > 0.f) ? y0 : expm1f(y0);
        y1 = (y1 > 0.f) ? y1 : expm1f(y1);
        __half h0 = __float2half(y0), h1 = __float2half(y1);
        uh.h2[j] = __halves2half2(h0, h1);
        ul.h2[j] = __halves2half2(__float2half(y0 - __half2float(h0)),
                                  __float2half(y1 - __half2float(h1)));
    }
    *reinterpret_cast<uint4*>(hi + (size_t)warp * 256 + lane * 8) = uh.u;
    *reinterpret_cast<uint4*>(lo + (size_t)warp * 256 + lane * 8) = ul.u;
}

// ===== fused aggregation(D=128,H=1) + bias + final LN -> fp32 out =====
__global__ __launch_bounds__(256) void aggln128_kernel(
    const __half* __restrict__ h, const float* __restrict__ aexp, const float* __restrict__ denom,
    const int* __restrict__ rcol, const int* __restrict__ rptr,
    const float* __restrict__ bias, const float* __restrict__ gam, const float* __restrict__ bet,
    float* __restrict__ out, int n)
{
    int warp = (blockIdx.x * blockDim.x + threadIdx.x) >> 5;
    int lane = threadIdx.x & 31;
    if (warp >= n) return;
    float acc[4];
#pragma unroll
    for (int j = 0; j < 4; j++) acc[j] = 0.f;
    int s = rptr[warp], e1 = rptr[warp + 1];
    int i = s;
    for (; i + 1 < e1; i += 2) {
        int ca = rcol[i], cb = rcol[i + 1];
        float wa = aexp[i] / (denom[ca] + EPS_SM);
        float wb = aexp[i + 1] / (denom[cb] + EPS_SM);
        uint2 ra = *reinterpret_cast<const uint2*>(h + (size_t)ca * 128 + lane * 4);
        uint2 rb = *reinterpret_cast<const uint2*>(h + (size_t)cb * 128 + lane * 4);
        const __half2* pa = reinterpret_cast<const __half2*>(&ra);
        const __half2* pb = reinterpret_cast<const __half2*>(&rb);
#pragma unroll
        for (int j = 0; j < 2; j++) {
            float2 fa = __half22float2(pa[j]);
            float2 fb = __half22float2(pb[j]);
            acc[2 * j]     += wa * fa.x + wb * fb.x;
            acc[2 * j + 1] += wa * fa.y + wb * fb.y;
        }
    }
    if (i < e1) {
        int c = rcol[i];
        float w = aexp[i] / (denom[c] + EPS_SM);
        uint2 r = *reinterpret_cast<const uint2*>(h + (size_t)c * 128 + lane * 4);
        const __half2* p = reinterpret_cast<const __half2*>(&r);
#pragma unroll
        for (int j = 0; j < 2; j++) {
            float2 f = __half22float2(p[j]);
            acc[2 * j]     += w * f.x;
            acc[2 * j + 1] += w * f.y;
        }
    }
    float4 b0 = *reinterpret_cast<const float4*>(bias + lane * 4);
    acc[0] += b0.x; acc[1] += b0.y; acc[2] += b0.z; acc[3] += b0.w;
    float sum = 0.f, sumsq = 0.f;
#pragma unroll
    for (int j = 0; j < 4; j++) { sum += acc[j]; sumsq += acc[j] * acc[j]; }
#pragma unroll
    for (int o = 16; o; o >>= 1) {
        sum += __shfl_xor_sync(0xffffffffu, sum, o);
        sumsq += __shfl_xor_sync(0xffffffffu, sumsq, o);
    }
    float mu = sum * (1.0f / 128.0f);
    float var = sumsq * (1.0f / 128.0f) - mu * mu;
    float r = rsqrtf(var + EPS_LN);
    float4 g0 = *reinterpret_cast<const float4*>(gam + lane * 4);
    float4 e0 = *reinterpret_cast<const float4*>(bet + lane * 4);
    float4 o0 = make_float4((acc[0] - mu) * r * g0.x + e0.x,
                            (acc[1] - mu) * r * g0.y + e0.y,
                            (acc[2] - mu) * r * g0.z + e0.z,
                            (acc[3] - mu) * r * g0.w + e0.w);
    *reinterpret_cast<float4*>(out + (size_t)warp * 128 + lane * 4) = o0;
}

// ---------------- host orchestration ----------------
static inline int ceil_div(int a, int b) { return (a + b - 1) / b; }

extern "C" void kernel_launch(void* const* d_in, const int* in_sizes, int n_in,
                              void* d_out, int out_size) {
    const float* x   = (const float*)d_in[0];
    const int*   ei  = (const int*)d_in[1];
    const float* ew  = (const float*)d_in[2];
    const float* W1  = (const float*)d_in[3];
    const float* as1 = (const float*)d_in[4];
    const float* ad1 = (const float*)d_in[5];
    const float* b1  = (const float*)d_in[6];
    const float* g1  = (const float*)d_in[7];
    const float* be1 = (const float*)d_in[8];
    const float* W2  = (const float*)d_in[9];
    const float* as2 = (const float*)d_in[10];
    const float* ad2 = (const float*)d_in[11];
    const float* b2  = (const float*)d_in[12];
    const float* g2  = (const float*)d_in[13];
    const float* be2 = (const float*)d_in[14];
    const float* W3  = (const float*)d_in[15];
    const float* as3 = (const float*)d_in[16];
    const float* ad3 = (const float*)d_in[17];
    const float* b3  = (const float*)d_in[18];
    const float* g3  = (const float*)d_in[19];
    const float* be3 = (const float*)d_in[20];
    float* out = (float*)d_out;

    const int* row = ei;
    const int* col = ei + NEDGE;

    float *alpha, *denomA, *denomB, *score;
    int *cnt, *rptr, *fill, *epos, *rcol;
    __half *h16, *ahi, *alo, *wt;
    cudaGetSymbolAddress((void**)&h16, g_h16);
    cudaGetSymbolAddress((void**)&alpha, g_alpha);
    cudaGetSymbolAddress((void**)&denomA, g_denomA);
    cudaGetSymbolAddress((void**)&denomB, g_denomB);
    cudaGetSymbolAddress((void**)&score, g_score);
    cudaGetSymbolAddress((void**)&cnt, g_cnt);
    cudaGetSymbolAddress((void**)&rptr, g_rptr);
    cudaGetSymbolAddress((void**)&fill, g_fill);
    cudaGetSymbolAddress((void**)&epos, g_epos);
    cudaGetSymbolAddress((void**)&rcol, g_rcol);
    cudaGetSymbolAddress((void**)&ahi, g_ahi);
    cudaGetSymbolAddress((void**)&alo, g_alo);
    cudaGetSymbolAddress((void**)&wt, g_wt);

    float* ssrc = score;
    float* sdst = score + NNODE * 4;

    const int TB = 256;
    const int eb = ceil_div(NEDGE, TB);
    const int mtiles = ceil_div(NNODE, 128);
    const int SMEM = 3 * 24576;   // 73728

    cudaFuncSetAttribute(gemm_mma<256, 384>, cudaFuncAttributeMaxDynamicSharedMemorySize, SMEM);
    cudaFuncSetAttribute(gemm_mma<256, 256>, cudaFuncAttributeMaxDynamicSharedMemorySize, SMEM);
    cudaFuncSetAttribute(gemm_mma<128, 256>, cudaFuncAttributeMaxDynamicSharedMemorySize, SMEM);

    // 0: x split + wprep1 + zero score/denomA
    asplit_fused_kernel<<<ceil_div(NNODE * 384, TB), TB>>>(
        x, ahi, alo, NNODE * 384, W1, wt, 384, 256,
        score, NNODE * 8, denomA, NNODE * 4);
    zero_i<<<ceil_div(NNODE, TB), TB>>>(cnt, NNODE);                 // 1
    hist_kernel<<<eb, TB>>>(row, cnt, NEDGE);                        // 2
    gemm_mma<256, 384><<<dim3(2, mtiles), 256, SMEM>>>(              // 3 <- profiled
        ahi, alo, wt, h16, as1, ad1, ssrc, sdst, 4, 64, NNODE);
    scan_kernel<<<1, 1024>>>(cnt, rptr, fill, NNODE);                // 4
    scatter_kernel<<<eb, TB>>>(row, col, fill, epos, rcol, NEDGE);   // 5

    // =============== Layer 1 (rest) ===============
    edge_scores4_kernel<<<eb, TB>>>(row, col, ew, epos, ssrc, sdst, alpha, denomA, NEDGE);
    aggln256_kernel<<<ceil_div(NNODE * 32, TB), TB>>>(
        h16, alpha, denomA, rcol, rptr, b1, g1, be1, ahi, alo, NNODE,
        W2, wt, 256, 256, score, NNODE * 8, denomB, NNODE * 4);

    // =============== Layer 2 ===============
    gemm_mma<256, 256><<<dim3(2, mtiles), 256, SMEM>>>(
        ahi, alo, wt, h16, as2, ad2, ssrc, sdst, 4, 64, NNODE);
    edge_scores4_kernel<<<eb, TB>>>(row, col, ew, epos, ssrc, sdst, alpha, denomB, NEDGE);
    aggln256_kernel<<<ceil_div(NNODE * 32, TB), TB>>>(
        h16, alpha, denomB, rcol, rptr, b2, g2, be2, ahi, alo, NNODE,
        W3, wt, 256, 128, score, NNODE * 8, denomA, NNODE * 4);

    // =============== Layer 3 ===============
    gemm_mma<128, 256><<<dim3(1, mtiles), 256, SMEM>>>(
        ahi, alo, wt, h16, as3, ad3, ssrc, sdst, 1, 128, NNODE);
    edge_scores1_kernel<<<eb, TB>>>(row, col, ew, epos, ssrc, sdst, alpha, denomA, NEDGE);
    aggln128_kernel<<<ceil_div(NNODE * 32, TB), TB>>>(
        h16, alpha, denomA, rcol, rptr, b3, g3, be3, out, NNODE);
}

// round 11
// speedup vs baseline: 1.0719x; 1.0719x over previous
#include <cuda_runtime.h>
#include <cuda_fp16.h>
#include <math.h>
#include <stdint.h>

#define NNODE 50000
#define NEDGE 500000
#define DMAX  256
#define EPS_SM 1e-16f
#define EPS_LN 1e-5f
#define NEG_SLOPE 0.2f

// ---------------- scratch (device globals) ----------------
__device__ __half g_h16[NNODE * DMAX];          // GEMM output (fp16)
__device__ float g_alpha[NEDGE * 4];            // edge exp scores (edge order)
__device__ float g_denomA[NNODE * 4];
__device__ float g_denomB[NNODE * 4];
__device__ float g_score[NNODE * 8];            // ssrc | sdst
__device__ int   g_cnt[NNODE];
__device__ int   g_rptr[NNODE + 1];
__device__ int   g_fill[NNODE];
__device__ int   g_redges[NEDGE];
__device__ __half g_ahi[NNODE * 384];           // activation hi (fp16)
__device__ __half g_alo[NNODE * 384];           // activation lo (fp16)
__device__ __half g_wt[256 * 384];              // transposed weight fp16 [N][K]

// ================= PTX helpers =================
__device__ __forceinline__ uint32_t smem_u32(const void* p) {
    uint32_t a;
    asm("{ .reg .u64 t; cvta.to.shared.u64 t, %1; cvt.u32.u64 %0, t; }" : "=r"(a) : "l"(p));
    return a;
}

#define CPA16(dst, src, sz) \
    asm volatile("cp.async.cg.shared.global [%0], [%1], 16, %2;" \
                 :: "r"(dst), "l"(src), "r"(sz))
#define CPA_COMMIT() asm volatile("cp.async.commit_group;" ::: "memory")
#define CPA_WAIT(n)  asm volatile("cp.async.wait_group %0;" :: "n"(n) : "memory")

#define LDMX4(r0, r1, r2, r3, addr) \
    asm volatile("ldmatrix.sync.aligned.m8n8.x4.shared.b16 {%0,%1,%2,%3}, [%4];" \
                 : "=r"(r0), "=r"(r1), "=r"(r2), "=r"(r3) : "r"(addr))

__device__ __forceinline__ void mma16816h(float* c, const uint32_t* a, const uint32_t* b) {
    asm volatile(
        "mma.sync.aligned.m16n8k16.row.col.f32.f16.f16.f32 "
        "{%0,%1,%2,%3}, {%4,%5,%6,%7}, {%8,%9}, {%0,%1,%2,%3};"
        : "+f"(c[0]), "+f"(c[1]), "+f"(c[2]), "+f"(c[3])
        : "r"(a[0]), "r"(a[1]), "r"(a[2]), "r"(a[3]), "r"(b[0]), "r"(b[1]));
}

#define SWZ64(b) ((b) ^ (((b) >> 3) & 0x30))

// ---------------- small utility ----------------
__global__ void zero_i(int* p, int n) {
    int i = blockIdx.x * blockDim.x + threadIdx.x;
    if (i < n) p[i] = 0;
}

// ---------------- asplit + wprep1 + zero score/denomA ----------------
__global__ void asplit_fused_kernel(
    const float* __restrict__ A, __half* hi, __half* lo, int total,
    const float* __restrict__ W, __half* wt, int K, int Nn,
    float* score, int nscore, float* den, int nden)
{
    int i = blockIdx.x * blockDim.x + threadIdx.x;
    if (i < total) {
        float v = A[i];
        __half h = __float2half(v);
        hi[i] = h;
        lo[i] = __float2half(v - __half2float(h));
    }
    if (i < K * Nn) {
        int n = i / K, k = i - n * K;
        wt[i] = __float2half(W[(size_t)k * Nn + n]);
    }
    if (i < nscore) score[i] = 0.0f;
    if (i < nden) den[i] = 0.0f;
}

// ---------------- CSR build ----------------
__global__ void hist_kernel(const int* __restrict__ row, int* cnt, int e) {
    int i = blockIdx.x * blockDim.x + threadIdx.x;
    if (i < e) atomicAdd(&cnt[row[i]], 1);
}

__global__ void scan_kernel(const int* __restrict__ cnt, int* ptr, int* fill, int n) {
    __shared__ int sh[1024];
    __shared__ int carry;
    if (threadIdx.x == 0) carry = 0;
    __syncthreads();
    for (int base = 0; base < n; base += 1024) {
        int i = base + threadIdx.x;
        int v = (i < n) ? cnt[i] : 0;
        sh[threadIdx.x] = v;
        __syncthreads();
        for (int off = 1; off < 1024; off <<= 1) {
            int t = (threadIdx.x >= off) ? sh[threadIdx.x - off] : 0;
            __syncthreads();
            sh[threadIdx.x] += t;
            __syncthreads();
        }
        int excl = sh[threadIdx.x] - v;
        if (i < n) { ptr[i] = carry + excl; fill[i] = carry + excl; }
        __syncthreads();
        if (threadIdx.x == 1023) carry += sh[1023];
        __syncthreads();
    }
    if (threadIdx.x == 0) ptr[n] = carry;
}

__global__ void scatter_kernel(const int* __restrict__ row, int* fill, int* redges, int e) {
    int i = blockIdx.x * blockDim.x + threadIdx.x;
    if (i < e) {
        int pos = atomicAdd(&fill[row[i]], 1);
        redges[pos] = i;
    }
}

// ===== HMMA fp16 2-term GEMM 128x128 tile + fused attention scores =====
template <int NN, int KK>
__global__ __launch_bounds__(256, 2) void gemm_mma(
    const __half* __restrict__ Ahi, const __half* __restrict__ Alo,
    const __half* __restrict__ Bw,
    __half* __restrict__ C,
    const float* __restrict__ Av, const float* __restrict__ Dv,
    float* __restrict__ Ssrc, float* __restrict__ Sdst,
    int H, int Cc, int M)
{
    constexpr int BK = 32;
    constexpr int NCH = KK / BK;
    constexpr int STG = 24576;   // A hi 8K | A lo 8K | B 8K
    extern __shared__ char smem[];
    uint32_t sb = smem_u32(smem);

    int tid = threadIdx.x;
    int lane = tid & 31, wid = tid >> 5;
    int wm = wid & 3, wn = wid >> 2;
    int m0 = blockIdx.y * 128;
    int n0 = blockIdx.x * 128;

    int g = lane >> 3, lr = lane & 7;
    uint32_t aoff[2][2];
#pragma unroll
    for (int mt = 0; mt < 2; mt++)
#pragma unroll
        for (int ks = 0; ks < 2; ks++) {
            int row = wm * 32 + mt * 16 + (g & 1) * 8 + lr;
            int unit = ks * 2 + (g >> 1);
            aoff[mt][ks] = SWZ64(row * 64 + unit * 16);
        }
    uint32_t boff[4][2];
#pragma unroll
    for (int np = 0; np < 4; np++)
#pragma unroll
        for (int ks = 0; ks < 2; ks++) {
            int row = wn * 64 + np * 16 + (g >> 1) * 8 + lr;
            int unit = ks * 2 + (g & 1);
            boff[np][ks] = 16384u + SWZ64(row * 64 + unit * 16);
        }

    int r0 = tid >> 2, u0 = tid & 3;
    uint32_t sw0 = SWZ64(r0 * 64 + u0 * 16);
    uint32_t sw1 = SWZ64((r0 + 64) * 64 + u0 * 16);
    long bofs0 = (long)(n0 + r0) * KK + u0 * 8;
    long bofs1 = (long)(n0 + r0 + 64) * KK + u0 * 8;

    float acc[2][8][4];
#pragma unroll
    for (int mt = 0; mt < 2; mt++)
#pragma unroll
        for (int nt = 0; nt < 8; nt++)
#pragma unroll
            for (int j = 0; j < 4; j++) acc[mt][nt][j] = 0.f;

    auto load_stage = [&](int ch, uint32_t so) {
        int k0 = ch * BK;
        {
            int grow = m0 + r0;
            int sz = (grow < M) ? 16 : 0;
            long go = (long)((grow < M) ? grow : 0) * KK + k0 + u0 * 8;
            CPA16(sb + so + sw0, Ahi + go, sz);
            CPA16(sb + so + 8192 + sw0, Alo + go, sz);
        }
        {
            int grow = m0 + r0 + 64;
            int sz = (grow < M) ? 16 : 0;
            long go = (long)((grow < M) ? grow : 0) * KK + k0 + u0 * 8;
            CPA16(sb + so + sw1, Ahi + go, sz);
            CPA16(sb + so + 8192 + sw1, Alo + go, sz);
        }
        CPA16(sb + so + 16384 + sw0, Bw + bofs0 + k0, 16);
        CPA16(sb + so + 16384 + sw1, Bw + bofs1 + k0, 16);
    };

    auto compute_stage = [&](uint32_t so) {
#pragma unroll
        for (int ks = 0; ks < 2; ks++) {
            uint32_t ah[2][4], al[2][4], b[8][2];
#pragma unroll
            for (int mt = 0; mt < 2; mt++) {
                LDMX4(ah[mt][0], ah[mt][1], ah[mt][2], ah[mt][3], sb + so + aoff[mt][ks]);
                LDMX4(al[mt][0], al[mt][1], al[mt][2], al[mt][3], sb + so + 8192 + aoff[mt][ks]);
            }
#pragma unroll
            for (int np = 0; np < 4; np++)
                LDMX4(b[2 * np][0], b[2 * np][1], b[2 * np + 1][0], b[2 * np + 1][1],
                      sb + so + boff[np][ks]);
#pragma unroll
            for (int mt = 0; mt < 2; mt++)
#pragma unroll
                for (int nt = 0; nt < 8; nt++) {
                    mma16816h(acc[mt][nt], ah[mt], b[nt]);
                    mma16816h(acc[mt][nt], al[mt], b[nt]);
                }
        }
    };

    load_stage(0, 0);
    CPA_COMMIT();
    load_stage(1, STG);
    CPA_COMMIT();
#pragma unroll 1
    for (int ch = 0; ch < NCH; ch++) {
        uint32_t so = (uint32_t)(ch % 3) * STG;
        if (ch + 1 < NCH) { CPA_WAIT(1); } else { CPA_WAIT(0); }
        __syncthreads();
        if (ch + 2 < NCH) {
            load_stage(ch + 2, (uint32_t)((ch + 2) % 3) * STG);
            CPA_COMMIT();
        }
        compute_stage(so);
    }

    // ---- epilogue 1: fp16 h store ----
#pragma unroll
    for (int mt = 0; mt < 2; mt++) {
        int m = m0 + wm * 32 + mt * 16 + (lane >> 2);
#pragma unroll
        for (int nt = 0; nt < 8; nt++) {
            int n = n0 + wn * 64 + nt * 8 + (lane & 3) * 2;
            if (m < M)
                *reinterpret_cast<__half2*>(C + (size_t)m * NN + n) =
                    __floats2half2_rn(acc[mt][nt][0], acc[mt][nt][1]);
            if (m + 8 < M)
                *reinterpret_cast<__half2*>(C + (size_t)(m + 8) * NN + n) =
                    __floats2half2_rn(acc[mt][nt][2], acc[mt][nt][3]);
        }
    }

    // ---- epilogue 2: fused attention scores ----
    {
        int head = (n0 + wn * 64) / Cc;
        float av[16], dv[16];
#pragma unroll
        for (int nt = 0; nt < 8; nt++) {
            int c0 = (n0 + wn * 64 + nt * 8 + (lane & 3) * 2) - head * Cc;
            av[2 * nt] = Av[head * Cc + c0];
            av[2 * nt + 1] = Av[head * Cc + c0 + 1];
            dv[2 * nt] = Dv[head * Cc + c0];
            dv[2 * nt + 1] = Dv[head * Cc + c0 + 1];
        }
#pragma unroll
        for (int mt = 0; mt < 2; mt++) {
            float ps0 = 0.f, pd0 = 0.f, ps1 = 0.f, pd1 = 0.f;
#pragma unroll
            for (int nt = 0; nt < 8; nt++) {
                ps0 += acc[mt][nt][0] * av[2 * nt] + acc[mt][nt][1] * av[2 * nt + 1];
                pd0 += acc[mt][nt][0] * dv[2 * nt] + acc[mt][nt][1] * dv[2 * nt + 1];
                ps1 += acc[mt][nt][2] * av[2 * nt] + acc[mt][nt][3] * av[2 * nt + 1];
                pd1 += acc[mt][nt][2] * dv[2 * nt] + acc[mt][nt][3] * dv[2 * nt + 1];
            }
#pragma unroll
            for (int o = 1; o <= 2; o <<= 1) {
                ps0 += __shfl_xor_sync(0xffffffffu, ps0, o);
                pd0 += __shfl_xor_sync(0xffffffffu, pd0, o);
                ps1 += __shfl_xor_sync(0xffffffffu, ps1, o);
                pd1 += __shfl_xor_sync(0xffffffffu, pd1, o);
            }
            if ((lane & 3) == 0) {
                int m = m0 + wm * 32 + mt * 16 + (lane >> 2);
                if (m < M) {
                    atomicAdd(&Ssrc[m * H + head], ps0);
                    atomicAdd(&Sdst[m * H + head], pd0);
                }
                if (m + 8 < M) {
                    atomicAdd(&Ssrc[(m + 8) * H + head], ps1);
                    atomicAdd(&Sdst[(m + 8) * H + head], pd1);
                }
            }
        }
    }
}

// ---------------- edge scores H=4 (coalesced alpha writes) ----------------
__global__ void edge_scores4_kernel(
    const int* __restrict__ row, const int* __restrict__ col, const float* __restrict__ ew,
    const float* __restrict__ ssrc, const float* __restrict__ sdst,
    float* __restrict__ aexp, float* __restrict__ denom, int e)
{
    int i = blockIdx.x * blockDim.x + threadIdx.x;
    if (i >= e) return;
    int r = row[i], c = col[i];
    float w = ew[i];
    float4 s4 = *reinterpret_cast<const float4*>(ssrc + (size_t)r * 4);
    float4 d4 = *reinterpret_cast<const float4*>(sdst + (size_t)c * 4);
    float4 o;
    float v;
    v = s4.x + d4.x; v = (v >= 0.f) ? v : NEG_SLOPE * v; o.x = expf(v * w);
    v = s4.y + d4.y; v = (v >= 0.f) ? v : NEG_SLOPE * v; o.y = expf(v * w);
    v = s4.z + d4.z; v = (v >= 0.f) ? v : NEG_SLOPE * v; o.z = expf(v * w);
    v = s4.w + d4.w; v = (v >= 0.f) ? v : NEG_SLOPE * v; o.w = expf(v * w);
    *reinterpret_cast<float4*>(aexp + (size_t)i * 4) = o;
    atomicAdd(&denom[c * 4 + 0], o.x);
    atomicAdd(&denom[c * 4 + 1], o.y);
    atomicAdd(&denom[c * 4 + 2], o.z);
    atomicAdd(&denom[c * 4 + 3], o.w);
}

// ---------------- edge scores H=1 ----------------
__global__ void edge_scores1_kernel(
    const int* __restrict__ row, const int* __restrict__ col, const float* __restrict__ ew,
    const float* __restrict__ ssrc, const float* __restrict__ sdst,
    float* __restrict__ aexp, float* __restrict__ denom, int e)
{
    int i = blockIdx.x * blockDim.x + threadIdx.x;
    if (i >= e) return;
    int r = row[i], c = col[i];
    float v = ssrc[r] + sdst[c];
    v = (v >= 0.f) ? v : NEG_SLOPE * v;
    v = expf(v * ew[i]);
    aexp[i] = v;
    atomicAdd(&denom[c], v);
}

// ---------------- reciprocal of denominators ----------------
__global__ void rdenom_kernel(float* d, int n) {
    int i = blockIdx.x * blockDim.x + threadIdx.x;
    if (i < n) d[i] = 1.0f / (d[i] + EPS_SM);
}

// ===== fused aggregation(D=256,H=4) + bias + LN + ELU + fp16 split
//       + next-layer wprep + zero score/denom (predicated prefix work) =====
__global__ __launch_bounds__(256) void aggln256_kernel(
    const __half* __restrict__ h, const float* __restrict__ aexp, const float* __restrict__ rden,
    const int* __restrict__ col, const int* __restrict__ rptr, const int* __restrict__ redges,
    const float* __restrict__ bias, const float* __restrict__ gam, const float* __restrict__ bet,
    __half* __restrict__ hi, __half* __restrict__ lo, int n,
    const float* __restrict__ Wnext, __half* wt, int K, int Nn,
    float* score_z, int nscore, float* den_z, int nden)
{
    int gt = blockIdx.x * blockDim.x + threadIdx.x;
    // folded side-work (consumed only by later launches)
    if (gt < nscore) score_z[gt] = 0.0f;
    if (gt < nden) den_z[gt] = 0.0f;
    if (gt < K * Nn) {
        int nn = gt / K, k = gt - nn * K;
        wt[gt] = __float2half(Wnext[(size_t)k * Nn + nn]);
    }

    int warp = gt >> 5;
    int lane = threadIdx.x & 31;
    if (warp >= n) return;
    int hh = lane >> 3;
    float acc[8];
#pragma unroll
    for (int j = 0; j < 8; j++) acc[j] = 0.f;
    int s = rptr[warp], e1 = rptr[warp + 1];
    int i = s;
    for (; i + 1 < e1; i += 2) {
        int ea = redges[i], eb = redges[i + 1];
        int ca = col[ea], cb = col[eb];
        float wa = aexp[(size_t)ea * 4 + hh] * rden[(size_t)ca * 4 + hh];
        float wb = aexp[(size_t)eb * 4 + hh] * rden[(size_t)cb * 4 + hh];
        uint4 ra = *reinterpret_cast<const uint4*>(h + (size_t)ca * 256 + lane * 8);
        uint4 rb = *reinterpret_cast<const uint4*>(h + (size_t)cb * 256 + lane * 8);
        const __half2* pa = reinterpret_cast<const __half2*>(&ra);
        const __half2* pb = reinterpret_cast<const __half2*>(&rb);
#pragma unroll
        for (int j = 0; j < 4; j++) {
            float2 fa = __half22float2(pa[j]);
            float2 fb = __half22float2(pb[j]);
            acc[2 * j]     += wa * fa.x + wb * fb.x;
            acc[2 * j + 1] += wa * fa.y + wb * fb.y;
        }
    }
    if (i < e1) {
        int e = redges[i];
        int c = col[e];
        float w = aexp[(size_t)e * 4 + hh] * rden[(size_t)c * 4 + hh];
        uint4 r = *reinterpret_cast<const uint4*>(h + (size_t)c * 256 + lane * 8);
        const __half2* p = reinterpret_cast<const __half2*>(&r);
#pragma unroll
        for (int j = 0; j < 4; j++) {
            float2 f = __half22float2(p[j]);
            acc[2 * j]     += w * f.x;
            acc[2 * j + 1] += w * f.y;
        }
    }
    const float4* bp = reinterpret_cast<const float4*>(bias + lane * 8);
    float4 b0 = bp[0], b1 = bp[1];
    acc[0] += b0.x; acc[1] += b0.y; acc[2] += b0.z; acc[3] += b0.w;
    acc[4] += b1.x; acc[5] += b1.y; acc[6] += b1.z; acc[7] += b1.w;
    float sum = 0.f, sumsq = 0.f;
#pragma unroll
    for (int j = 0; j < 8; j++) { sum += acc[j]; sumsq += acc[j] * acc[j]; }
#pragma unroll
    for (int o = 16; o; o >>= 1) {
        sum += __shfl_xor_sync(0xffffffffu, sum, o);
        sumsq += __shfl_xor_sync(0xffffffffu, sumsq, o);
    }
    float mu = sum * (1.0f / 256.0f);
    float var = sumsq * (1.0f / 256.0f) - mu * mu;
    float r = rsqrtf(var + EPS_LN);
    const float4* gp = reinterpret_cast<const float4*>(gam + lane * 8);
    const float4* ep = reinterpret_cast<const float4*>(bet + lane * 8);
    float4 g0 = gp[0], g1 = gp[1], e0 = ep[0], e1v = ep[1];
    float gg[8] = {g0.x, g0.y, g0.z, g0.w, g1.x, g1.y, g1.z, g1.w};
    float ee[8] = {e0.x, e0.y, e0.z, e0.w, e1v.x, e1v.y, e1v.z, e1v.w};
    union { __half2 h2[4]; uint4 u; } uh, ul;
#pragma unroll
    for (int j = 0; j < 4; j++) {
        float y0 = (acc[2 * j] - mu) * r * gg[2 * j] + ee[2 * j];
        float y1 = (acc[2 * j + 1] - mu) * r * gg[2 * j + 1] + ee[2 * j + 1];
        y0 = (y0 > 0.f) ? y0 : expm1f(y0);
        y1 = (y1 > 0.f) ? y1 : expm1f(y1);
        __half h0 = __float2half(y0), h1 = __float2half(y1);
        uh.h2[j] = __halves2half2(h0, h1);
        ul.h2[j] = __halves2half2(__float2half(y0 - __half2float(h0)),
                                  __float2half(y1 - __half2float(h1)));
    }
    *reinterpret_cast<uint4*>(hi + (size_t)warp * 256 + lane * 8) = uh.u;
    *reinterpret_cast<uint4*>(lo + (size_t)warp * 256 + lane * 8) = ul.u;
}

// ===== fused aggregation(D=128,H=1) + bias + final LN -> fp32 out =====
__global__ __launch_bounds__(256) void aggln128_kernel(
    const __half* __restrict__ h, const float* __restrict__ aexp, const float* __restrict__ rden,
    const int* __restrict__ col, const int* __restrict__ rptr, const int* __restrict__ redges,
    const float* __restrict__ bias, const float* __restrict__ gam, const float* __restrict__ bet,
    float* __restrict__ out, int n)
{
    int warp = (blockIdx.x * blockDim.x + threadIdx.x) >> 5;
    int lane = threadIdx.x & 31;
    if (warp >= n) return;
    float acc[4];
#pragma unroll
    for (int j = 0; j < 4; j++) acc[j] = 0.f;
    int s = rptr[warp], e1 = rptr[warp + 1];
    int i = s;
    for (; i + 1 < e1; i += 2) {
        int ea = redges[i], eb = redges[i + 1];
        int ca = col[ea], cb = col[eb];
        float wa = aexp[ea] * rden[ca];
        float wb = aexp[eb] * rden[cb];
        uint2 ra = *reinterpret_cast<const uint2*>(h + (size_t)ca * 128 + lane * 4);
        uint2 rb = *reinterpret_cast<const uint2*>(h + (size_t)cb * 128 + lane * 4);
        const __half2* pa = reinterpret_cast<const __half2*>(&ra);
        const __half2* pb = reinterpret_cast<const __half2*>(&rb);
#pragma unroll
        for (int j = 0; j < 2; j++) {
            float2 fa = __half22float2(pa[j]);
            float2 fb = __half22float2(pb[j]);
            acc[2 * j]     += wa * fa.x + wb * fb.x;
            acc[2 * j + 1] += wa * fa.y + wb * fb.y;
        }
    }
    if (i < e1) {
        int e = redges[i];
        int c = col[e];
        float w = aexp[e] * rden[c];
        uint2 r = *reinterpret_cast<const uint2*>(h + (size_t)c * 128 + lane * 4);
        const __half2* p = reinterpret_cast<const __half2*>(&r);
#pragma unroll
        for (int j = 0; j < 2; j++) {
            float2 f = __half22float2(p[j]);
            acc[2 * j]     += w * f.x;
            acc[2 * j + 1] += w * f.y;
        }
    }
    float4 b0 = *reinterpret_cast<const float4*>(bias + lane * 4);
    acc[0] += b0.x; acc[1] += b0.y; acc[2] += b0.z; acc[3] += b0.w;
    float sum = 0.f, sumsq = 0.f;
#pragma unroll
    for (int j = 0; j < 4; j++) { sum += acc[j]; sumsq += acc[j] * acc[j]; }
#pragma unroll
    for (int o = 16; o; o >>= 1) {
        sum += __shfl_xor_sync(0xffffffffu, sum, o);
        sumsq += __shfl_xor_sync(0xffffffffu, sumsq, o);
    }
    float mu = sum * (1.0f / 128.0f);
    float var = sumsq * (1.0f / 128.0f) - mu * mu;
    float r = rsqrtf(var + EPS_LN);
    float4 g0 = *reinterpret_cast<const float4*>(gam + lane * 4);
    float4 e0 = *reinterpret_cast<const float4*>(bet + lane * 4);
    float4 o0 = make_float4((acc[0] - mu) * r * g0.x + e0.x,
                            (acc[1] - mu) * r * g0.y + e0.y,
                            (acc[2] - mu) * r * g0.z + e0.z,
                            (acc[3] - mu) * r * g0.w + e0.w);
    *reinterpret_cast<float4*>(out + (size_t)warp * 128 + lane * 4) = o0;
}

// ---------------- host orchestration ----------------
static inline int ceil_div(int a, int b) { return (a + b - 1) / b; }

extern "C" void kernel_launch(void* const* d_in, const int* in_sizes, int n_in,
                              void* d_out, int out_size) {
    const float* x   = (const float*)d_in[0];
    const int*   ei  = (const int*)d_in[1];
    const float* ew  = (const float*)d_in[2];
    const float* W1  = (const float*)d_in[3];
    const float* as1 = (const float*)d_in[4];
    const float* ad1 = (const float*)d_in[5];
    const float* b1  = (const float*)d_in[6];
    const float* g1  = (const float*)d_in[7];
    const float* be1 = (const float*)d_in[8];
    const float* W2  = (const float*)d_in[9];
    const float* as2 = (const float*)d_in[10];
    const float* ad2 = (const float*)d_in[11];
    const float* b2  = (const float*)d_in[12];
    const float* g2  = (const float*)d_in[13];
    const float* be2 = (const float*)d_in[14];
    const float* W3  = (const float*)d_in[15];
    const float* as3 = (const float*)d_in[16];
    const float* ad3 = (const float*)d_in[17];
    const float* b3  = (const float*)d_in[18];
    const float* g3  = (const float*)d_in[19];
    const float* be3 = (const float*)d_in[20];
    float* out = (float*)d_out;

    const int* row = ei;
    const int* col = ei + NEDGE;

    float *alpha, *denomA, *denomB, *score;
    int *cnt, *rptr, *fill, *redges;
    __half *h16, *ahi, *alo, *wt;
    cudaGetSymbolAddress((void**)&h16, g_h16);
    cudaGetSymbolAddress((void**)&alpha, g_alpha);
    cudaGetSymbolAddress((void**)&denomA, g_denomA);
    cudaGetSymbolAddress((void**)&denomB, g_denomB);
    cudaGetSymbolAddress((void**)&score, g_score);
    cudaGetSymbolAddress((void**)&cnt, g_cnt);
    cudaGetSymbolAddress((void**)&rptr, g_rptr);
    cudaGetSymbolAddress((void**)&fill, g_fill);
    cudaGetSymbolAddress((void**)&redges, g_redges);
    cudaGetSymbolAddress((void**)&ahi, g_ahi);
    cudaGetSymbolAddress((void**)&alo, g_alo);
    cudaGetSymbolAddress((void**)&wt, g_wt);

    float* ssrc = score;
    float* sdst = score + NNODE * 4;

    const int TB = 256;
    const int eb = ceil_div(NEDGE, TB);
    const int mtiles = ceil_div(NNODE, 128);
    const int SMEM = 3 * 24576;   // 73728

    cudaFuncSetAttribute(gemm_mma<256, 384>, cudaFuncAttributeMaxDynamicSharedMemorySize, SMEM);
    cudaFuncSetAttribute(gemm_mma<256, 256>, cudaFuncAttributeMaxDynamicSharedMemorySize, SMEM);
    cudaFuncSetAttribute(gemm_mma<128, 256>, cudaFuncAttributeMaxDynamicSharedMemorySize, SMEM);

    // 0: x split + wprep1 + zero score/denomA
    asplit_fused_kernel<<<ceil_div(NNODE * 384, TB), TB>>>(
        x, ahi, alo, NNODE * 384, W1, wt, 384, 256,
        score, NNODE * 8, denomA, NNODE * 4);
    zero_i<<<ceil_div(NNODE, TB), TB>>>(cnt, NNODE);                 // 1
    hist_kernel<<<eb, TB>>>(row, cnt, NEDGE);                        // 2
    gemm_mma<256, 384><<<dim3(2, mtiles), 256, SMEM>>>(              // 3 <- profiled
        ahi, alo, wt, h16, as1, ad1, ssrc, sdst, 4, 64, NNODE);
    scan_kernel<<<1, 1024>>>(cnt, rptr, fill, NNODE);                // 4
    scatter_kernel<<<eb, TB>>>(row, fill, redges, NEDGE);            // 5

    // =============== Layer 1 (rest) ===============
    edge_scores4_kernel<<<eb, TB>>>(row, col, ew, ssrc, sdst, alpha, denomA, NEDGE);
    rdenom_kernel<<<ceil_div(NNODE * 4, TB), TB>>>(denomA, NNODE * 4);
    aggln256_kernel<<<ceil_div(NNODE * 32, TB), TB>>>(
        h16, alpha, denomA, col, rptr, redges, b1, g1, be1, ahi, alo, NNODE,
        W2, wt, 256, 256, score, NNODE * 8, denomB, NNODE * 4);

    // =============== Layer 2 ===============
    gemm_mma<256, 256><<<dim3(2, mtiles), 256, SMEM>>>(
        ahi, alo, wt, h16, as2, ad2, ssrc, sdst, 4, 64, NNODE);
    edge_scores4_kernel<<<eb, TB>>>(row, col, ew, ssrc, sdst, alpha, denomB, NEDGE);
    rdenom_kernel<<<ceil_div(NNODE * 4, TB), TB>>>(denomB, NNODE * 4);
    aggln256_kernel<<<ceil_div(NNODE * 32, TB), TB>>>(
        h16, alpha, denomB, col, rptr, redges, b2, g2, be2, ahi, alo, NNODE,
        W3, wt, 256, 128, score, NNODE * 8, denomA, NNODE * 4);

    // =============== Layer 3 ===============
    gemm_mma<128, 256><<<dim3(1, mtiles), 256, SMEM>>>(
        ahi, alo, wt, h16, as3, ad3, ssrc, sdst, 1, 128, NNODE);
    edge_scores1_kernel<<<eb, TB>>>(row, col, ew, ssrc, sdst, alpha, denomA, NEDGE);
    rdenom_kernel<<<ceil_div(NNODE, TB), TB>>>(denomA, NNODE);
    aggln128_kernel<<<ceil_div(NNODE * 32, TB), TB>>>(
        h16, alpha, denomA, col, rptr, redges, b3, g3, be3, out, NNODE);
}

// round 12
// speedup vs baseline: 1.1435x; 1.0668x over previous
#include <cuda_runtime.h>
#include <cuda_fp16.h>
#include <math.h>
#include <stdint.h>

#define NNODE 50000
#define NEDGE 500000
#define DMAX  256
#define EPS_SM 1e-16f
#define EPS_LN 1e-5f
#define NEG_SLOPE 0.2f

// ---------------- scratch (device globals) ----------------
__device__ __half g_h16[NNODE * DMAX];
__device__ float g_alpha[NEDGE * 4];
__device__ float g_denomA[NNODE * 4];
__device__ float g_denomB[NNODE * 4];
__device__ float g_denomC[NNODE * 4];
__device__ float g_score1[NNODE * 8];
__device__ float g_score2[NNODE * 8];
__device__ float g_score3[NNODE * 8];
__device__ int   g_cnt[NNODE];
__device__ int   g_rptr[NNODE + 1];
__device__ int   g_fill[NNODE];
__device__ int   g_redges[NEDGE];
__device__ __half g_ahi[NNODE * 384];
__device__ __half g_alo[NNODE * 384];
__device__ __half g_wt1[256 * 384];
__device__ __half g_wt2[256 * 256];
__device__ __half g_wt3[128 * 256];

// ================= PTX helpers =================
__device__ __forceinline__ uint32_t smem_u32(const void* p) {
    uint32_t a;
    asm("{ .reg .u64 t; cvta.to.shared.u64 t, %1; cvt.u32.u64 %0, t; }" : "=r"(a) : "l"(p));
    return a;
}

#define CPA16(dst, src, sz) \
    asm volatile("cp.async.cg.shared.global [%0], [%1], 16, %2;" \
                 :: "r"(dst), "l"(src), "r"(sz))
#define CPA_COMMIT() asm volatile("cp.async.commit_group;" ::: "memory")
#define CPA_WAIT(n)  asm volatile("cp.async.wait_group %0;" :: "n"(n) : "memory")

#define LDMX4(r0, r1, r2, r3, addr) \
    asm volatile("ldmatrix.sync.aligned.m8n8.x4.shared.b16 {%0,%1,%2,%3}, [%4];" \
                 : "=r"(r0), "=r"(r1), "=r"(r2), "=r"(r3) : "r"(addr))

__device__ __forceinline__ void mma16816h(float* c, const uint32_t* a, const uint32_t* b) {
    asm volatile(
        "mma.sync.aligned.m16n8k16.row.col.f32.f16.f16.f32 "
        "{%0,%1,%2,%3}, {%4,%5,%6,%7}, {%8,%9}, {%0,%1,%2,%3};"
        : "+f"(c[0]), "+f"(c[1]), "+f"(c[2]), "+f"(c[3])
        : "r"(a[0]), "r"(a[1]), "r"(a[2]), "r"(a[3]), "r"(b[0]), "r"(b[1]));
}

#define SWZ64(b) ((b) ^ (((b) >> 3) & 0x30))

// ---------------- small utility ----------------
__global__ void zero_i(int* p, int n) {
    int i = blockIdx.x * blockDim.x + threadIdx.x;
    if (i < n) p[i] = 0;
}

// ---------------- asplit + wprep1 + zero score1/denomA ----------------
__global__ void asplit_fused_kernel(
    const float* __restrict__ A, __half* hi, __half* lo, int total,
    const float* __restrict__ W, __half* wt, int K, int Nn,
    float* score, int nscore, float* den, int nden)
{
    int i = blockIdx.x * blockDim.x + threadIdx.x;
    if (i < total) {
        float v = A[i];
        __half h = __float2half(v);
        hi[i] = h;
        lo[i] = __float2half(v - __half2float(h));
    }
    if (i < K * Nn) {
        int n = i / K, k = i - n * K;
        wt[i] = __float2half(W[(size_t)k * Nn + n]);
    }
    if (i < nscore) score[i] = 0.0f;
    if (i < nden) den[i] = 0.0f;
}

// ---------------- side prep: wprep2 + wprep3 + zero score2/3, denomB/C ----------------
__global__ void prep_side_kernel(
    const float* __restrict__ W2, __half* wt2,
    const float* __restrict__ W3, __half* wt3,
    float* sc2, float* sc3, int nscore,
    float* dB, float* dC, int nden)
{
    int i = blockIdx.x * blockDim.x + threadIdx.x;
    if (i < 256 * 256) {
        int n = i / 256, k = i - n * 256;
        wt2[i] = __float2half(W2[(size_t)k * 256 + n]);
    }
    if (i < 128 * 256) {
        int n = i / 256, k = i - n * 256;
        wt3[i] = __float2half(W3[(size_t)k * 128 + n]);
    }
    if (i < nscore) { sc2[i] = 0.0f; sc3[i] = 0.0f; }
    if (i < nden) { dB[i] = 0.0f; dC[i] = 0.0f; }
}

// ---------------- CSR build ----------------
__global__ void hist_kernel(const int* __restrict__ row, int* cnt, int e) {
    int i = blockIdx.x * blockDim.x + threadIdx.x;
    if (i < e) atomicAdd(&cnt[row[i]], 1);
}

__global__ void scan_kernel(const int* __restrict__ cnt, int* ptr, int* fill, int n) {
    __shared__ int sh[1024];
    __shared__ int carry;
    if (threadIdx.x == 0) carry = 0;
    __syncthreads();
    for (int base = 0; base < n; base += 1024) {
        int i = base + threadIdx.x;
        int v = (i < n) ? cnt[i] : 0;
        sh[threadIdx.x] = v;
        __syncthreads();
        for (int off = 1; off < 1024; off <<= 1) {
            int t = (threadIdx.x >= off) ? sh[threadIdx.x - off] : 0;
            __syncthreads();
            sh[threadIdx.x] += t;
            __syncthreads();
        }
        int excl = sh[threadIdx.x] - v;
        if (i < n) { ptr[i] = carry + excl; fill[i] = carry + excl; }
        __syncthreads();
        if (threadIdx.x == 1023) carry += sh[1023];
        __syncthreads();
    }
    if (threadIdx.x == 0) ptr[n] = carry;
}

__global__ void scatter_kernel(const int* __restrict__ row, int* fill, int* redges, int e) {
    int i = blockIdx.x * blockDim.x + threadIdx.x;
    if (i < e) {
        int pos = atomicAdd(&fill[row[i]], 1);
        redges[pos] = i;
    }
}

// ===== HMMA fp16 2-term GEMM 128x128 tile + fused attention scores =====
template <int NN, int KK>
__global__ __launch_bounds__(256, 2) void gemm_mma(
    const __half* __restrict__ Ahi, const __half* __restrict__ Alo,
    const __half* __restrict__ Bw,
    __half* __restrict__ C,
    const float* __restrict__ Av, const float* __restrict__ Dv,
    float* __restrict__ Ssrc, float* __restrict__ Sdst,
    int H, int Cc, int M)
{
    constexpr int BK = 32;
    constexpr int NCH = KK / BK;
    constexpr int STG = 24576;
    extern __shared__ char smem[];
    uint32_t sb = smem_u32(smem);

    int tid = threadIdx.x;
    int lane = tid & 31, wid = tid >> 5;
    int wm = wid & 3, wn = wid >> 2;
    int m0 = blockIdx.y * 128;
    int n0 = blockIdx.x * 128;

    int g = lane >> 3, lr = lane & 7;
    uint32_t aoff[2][2];
#pragma unroll
    for (int mt = 0; mt < 2; mt++)
#pragma unroll
        for (int ks = 0; ks < 2; ks++) {
            int row = wm * 32 + mt * 16 + (g & 1) * 8 + lr;
            int unit = ks * 2 + (g >> 1);
            aoff[mt][ks] = SWZ64(row * 64 + unit * 16);
        }
    uint32_t boff[4][2];
#pragma unroll
    for (int np = 0; np < 4; np++)
#pragma unroll
        for (int ks = 0; ks < 2; ks++) {
            int row = wn * 64 + np * 16 + (g >> 1) * 8 + lr;
            int unit = ks * 2 + (g & 1);
            boff[np][ks] = 16384u + SWZ64(row * 64 + unit * 16);
        }

    int r0 = tid >> 2, u0 = tid & 3;
    uint32_t sw0 = SWZ64(r0 * 64 + u0 * 16);
    uint32_t sw1 = SWZ64((r0 + 64) * 64 + u0 * 16);
    long bofs0 = (long)(n0 + r0) * KK + u0 * 8;
    long bofs1 = (long)(n0 + r0 + 64) * KK + u0 * 8;

    float acc[2][8][4];
#pragma unroll
    for (int mt = 0; mt < 2; mt++)
#pragma unroll
        for (int nt = 0; nt < 8; nt++)
#pragma unroll
            for (int j = 0; j < 4; j++) acc[mt][nt][j] = 0.f;

    auto load_stage = [&](int ch, uint32_t so) {
        int k0 = ch * BK;
        {
            int grow = m0 + r0;
            int sz = (grow < M) ? 16 : 0;
            long go = (long)((grow < M) ? grow : 0) * KK + k0 + u0 * 8;
            CPA16(sb + so + sw0, Ahi + go, sz);
            CPA16(sb + so + 8192 + sw0, Alo + go, sz);
        }
        {
            int grow = m0 + r0 + 64;
            int sz = (grow < M) ? 16 : 0;
            long go = (long)((grow < M) ? grow : 0) * KK + k0 + u0 * 8;
            CPA16(sb + so + sw1, Ahi + go, sz);
            CPA16(sb + so + 8192 + sw1, Alo + go, sz);
        }
        CPA16(sb + so + 16384 + sw0, Bw + bofs0 + k0, 16);
        CPA16(sb + so + 16384 + sw1, Bw + bofs1 + k0, 16);
    };

    auto compute_stage = [&](uint32_t so) {
#pragma unroll
        for (int ks = 0; ks < 2; ks++) {
            uint32_t ah[2][4], al[2][4], b[8][2];
#pragma unroll
            for (int mt = 0; mt < 2; mt++) {
                LDMX4(ah[mt][0], ah[mt][1], ah[mt][2], ah[mt][3], sb + so + aoff[mt][ks]);
                LDMX4(al[mt][0], al[mt][1], al[mt][2], al[mt][3], sb + so + 8192 + aoff[mt][ks]);
            }
#pragma unroll
            for (int np = 0; np < 4; np++)
                LDMX4(b[2 * np][0], b[2 * np][1], b[2 * np + 1][0], b[2 * np + 1][1],
                      sb + so + boff[np][ks]);
#pragma unroll
            for (int mt = 0; mt < 2; mt++)
#pragma unroll
                for (int nt = 0; nt < 8; nt++) {
                    mma16816h(acc[mt][nt], ah[mt], b[nt]);
                    mma16816h(acc[mt][nt], al[mt], b[nt]);
                }
        }
    };

    load_stage(0, 0);
    CPA_COMMIT();
    load_stage(1, STG);
    CPA_COMMIT();
#pragma unroll 1
    for (int ch = 0; ch < NCH; ch++) {
        uint32_t so = (uint32_t)(ch % 3) * STG;
        if (ch + 1 < NCH) { CPA_WAIT(1); } else { CPA_WAIT(0); }
        __syncthreads();
        if (ch + 2 < NCH) {
            load_stage(ch + 2, (uint32_t)((ch + 2) % 3) * STG);
            CPA_COMMIT();
        }
        compute_stage(so);
    }

    // epilogue 1: fp16 h store
#pragma unroll
    for (int mt = 0; mt < 2; mt++) {
        int m = m0 + wm * 32 + mt * 16 + (lane >> 2);
#pragma unroll
        for (int nt = 0; nt < 8; nt++) {
            int n = n0 + wn * 64 + nt * 8 + (lane & 3) * 2;
            if (m < M)
                *reinterpret_cast<__half2*>(C + (size_t)m * NN + n) =
                    __floats2half2_rn(acc[mt][nt][0], acc[mt][nt][1]);
            if (m + 8 < M)
                *reinterpret_cast<__half2*>(C + (size_t)(m + 8) * NN + n) =
                    __floats2half2_rn(acc[mt][nt][2], acc[mt][nt][3]);
        }
    }

    // epilogue 2: fused attention scores
    {
        int head = (n0 + wn * 64) / Cc;
        float av[16], dv[16];
#pragma unroll
        for (int nt = 0; nt < 8; nt++) {
            int c0 = (n0 + wn * 64 + nt * 8 + (lane & 3) * 2) - head * Cc;
            av[2 * nt] = Av[head * Cc + c0];
            av[2 * nt + 1] = Av[head * Cc + c0 + 1];
            dv[2 * nt] = Dv[head * Cc + c0];
            dv[2 * nt + 1] = Dv[head * Cc + c0 + 1];
        }
#pragma unroll
        for (int mt = 0; mt < 2; mt++) {
            float ps0 = 0.f, pd0 = 0.f, ps1 = 0.f, pd1 = 0.f;
#pragma unroll
            for (int nt = 0; nt < 8; nt++) {
                ps0 += acc[mt][nt][0] * av[2 * nt] + acc[mt][nt][1] * av[2 * nt + 1];
                pd0 += acc[mt][nt][0] * dv[2 * nt] + acc[mt][nt][1] * dv[2 * nt + 1];
                ps1 += acc[mt][nt][2] * av[2 * nt] + acc[mt][nt][3] * av[2 * nt + 1];
                pd1 += acc[mt][nt][2] * dv[2 * nt] + acc[mt][nt][3] * dv[2 * nt + 1];
            }
#pragma unroll
            for (int o = 1; o <= 2; o <<= 1) {
                ps0 += __shfl_xor_sync(0xffffffffu, ps0, o);
                pd0 += __shfl_xor_sync(0xffffffffu, pd0, o);
                ps1 += __shfl_xor_sync(0xffffffffu, ps1, o);
                pd1 += __shfl_xor_sync(0xffffffffu, pd1, o);
            }
            if ((lane & 3) == 0) {
                int m = m0 + wm * 32 + mt * 16 + (lane >> 2);
                if (m < M) {
                    atomicAdd(&Ssrc[m * H + head], ps0);
                    atomicAdd(&Sdst[m * H + head], pd0);
                }
                if (m + 8 < M) {
                    atomicAdd(&Ssrc[(m + 8) * H + head], ps1);
                    atomicAdd(&Sdst[(m + 8) * H + head], pd1);
                }
            }
        }
    }
}

// ---------------- edge scores H=4 ----------------
__global__ void edge_scores4_kernel(
    const int* __restrict__ row, const int* __restrict__ col, const float* __restrict__ ew,
    const float* __restrict__ ssrc, const float* __restrict__ sdst,
    float* __restrict__ aexp, float* __restrict__ denom, int e)
{
    int i = blockIdx.x * blockDim.x + threadIdx.x;
    if (i >= e) return;
    int r = row[i], c = col[i];
    float w = ew[i];
    float4 s4 = *reinterpret_cast<const float4*>(ssrc + (size_t)r * 4);
    float4 d4 = *reinterpret_cast<const float4*>(sdst + (size_t)c * 4);
    float4 o;
    float v;
    v = s4.x + d4.x; v = (v >= 0.f) ? v : NEG_SLOPE * v; o.x = expf(v * w);
    v = s4.y + d4.y; v = (v >= 0.f) ? v : NEG_SLOPE * v; o.y = expf(v * w);
    v = s4.z + d4.z; v = (v >= 0.f) ? v : NEG_SLOPE * v; o.z = expf(v * w);
    v = s4.w + d4.w; v = (v >= 0.f) ? v : NEG_SLOPE * v; o.w = expf(v * w);
    *reinterpret_cast<float4*>(aexp + (size_t)i * 4) = o;
    atomicAdd(&denom[c * 4 + 0], o.x);
    atomicAdd(&denom[c * 4 + 1], o.y);
    atomicAdd(&denom[c * 4 + 2], o.z);
    atomicAdd(&denom[c * 4 + 3], o.w);
}

// ---------------- edge scores H=1 ----------------
__global__ void edge_scores1_kernel(
    const int* __restrict__ row, const int* __restrict__ col, const float* __restrict__ ew,
    const float* __restrict__ ssrc, const float* __restrict__ sdst,
    float* __restrict__ aexp, float* __restrict__ denom, int e)
{
    int i = blockIdx.x * blockDim.x + threadIdx.x;
    if (i >= e) return;
    int r = row[i], c = col[i];
    float v = ssrc[r] + sdst[c];
    v = (v >= 0.f) ? v : NEG_SLOPE * v;
    v = expf(v * ew[i]);
    aexp[i] = v;
    atomicAdd(&denom[c], v);
}

// ---------------- reciprocal of denominators ----------------
__global__ void rdenom_kernel(float* d, int n) {
    int i = blockIdx.x * blockDim.x + threadIdx.x;
    if (i < n) d[i] = 1.0f / (d[i] + EPS_SM);
}

// ===== fused aggregation(D=256,H=4) + bias + LN + ELU + fp16 split =====
__global__ __launch_bounds__(256) void aggln256_kernel(
    const __half* __restrict__ h, const float* __restrict__ aexp, const float* __restrict__ rden,
    const int* __restrict__ col, const int* __restrict__ rptr, const int* __restrict__ redges,
    const float* __restrict__ bias, const float* __restrict__ gam, const float* __restrict__ bet,
    __half* __restrict__ hi, __half* __restrict__ lo, int n)
{
    int warp = (blockIdx.x * blockDim.x + threadIdx.x) >> 5;
    int lane = threadIdx.x & 31;
    if (warp >= n) return;
    int hh = lane >> 3;
    float acc[8];
#pragma unroll
    for (int j = 0; j < 8; j++) acc[j] = 0.f;
    int s = rptr[warp], e1 = rptr[warp + 1];
    int i = s;
    for (; i + 1 < e1; i += 2) {
        int ea = redges[i], eb = redges[i + 1];
        int ca = col[ea], cb = col[eb];
        float wa = aexp[(size_t)ea * 4 + hh] * rden[(size_t)ca * 4 + hh];
        float wb = aexp[(size_t)eb * 4 + hh] * rden[(size_t)cb * 4 + hh];
        uint4 ra = *reinterpret_cast<const uint4*>(h + (size_t)ca * 256 + lane * 8);
        uint4 rb = *reinterpret_cast<const uint4*>(h + (size_t)cb * 256 + lane * 8);
        const __half2* pa = reinterpret_cast<const __half2*>(&ra);
        const __half2* pb = reinterpret_cast<const __half2*>(&rb);
#pragma unroll
        for (int j = 0; j < 4; j++) {
            float2 fa = __half22float2(pa[j]);
            float2 fb = __half22float2(pb[j]);
            acc[2 * j]     += wa * fa.x + wb * fb.x;
            acc[2 * j + 1] += wa * fa.y + wb * fb.y;
        }
    }
    if (i < e1) {
        int e = redges[i];
        int c = col[e];
        float w = aexp[(size_t)e * 4 + hh] * rden[(size_t)c * 4 + hh];
        uint4 r = *reinterpret_cast<const uint4*>(h + (size_t)c * 256 + lane * 8);
        const __half2* p = reinterpret_cast<const __half2*>(&r);
#pragma unroll
        for (int j = 0; j < 4; j++) {
            float2 f = __half22float2(p[j]);
            acc[2 * j]     += w * f.x;
            acc[2 * j + 1] += w * f.y;
        }
    }
    const float4* bp = reinterpret_cast<const float4*>(bias + lane * 8);
    float4 b0 = bp[0], b1 = bp[1];
    acc[0] += b0.x; acc[1] += b0.y; acc[2] += b0.z; acc[3] += b0.w;
    acc[4] += b1.x; acc[5] += b1.y; acc[6] += b1.z; acc[7] += b1.w;
    float sum = 0.f, sumsq = 0.f;
#pragma unroll
    for (int j = 0; j < 8; j++) { sum += acc[j]; sumsq += acc[j] * acc[j]; }
#pragma unroll
    for (int o = 16; o; o >>= 1) {
        sum += __shfl_xor_sync(0xffffffffu, sum, o);
        sumsq += __shfl_xor_sync(0xffffffffu, sumsq, o);
    }
    float mu = sum * (1.0f / 256.0f);
    float var = sumsq * (1.0f / 256.0f) - mu * mu;
    float r = rsqrtf(var + EPS_LN);
    const float4* gp = reinterpret_cast<const float4*>(gam + lane * 8);
    const float4* ep = reinterpret_cast<const float4*>(bet + lane * 8);
    float4 g0 = gp[0], g1 = gp[1], e0 = ep[0], e1v = ep[1];
    float gg[8] = {g0.x, g0.y, g0.z, g0.w, g1.x, g1.y, g1.z, g1.w};
    float ee[8] = {e0.x, e0.y, e0.z, e0.w, e1v.x, e1v.y, e1v.z, e1v.w};
    union { __half2 h2[4]; uint4 u; } uh, ul;
#pragma unroll
    for (int j = 0; j < 4; j++) {
        float y0 = (acc[2 * j] - mu) * r * gg[2 * j] + ee[2 * j];
        float y1 = (acc[2 * j + 1] - mu) * r * gg[2 * j + 1] + ee[2 * j + 1];
        y0 = (y0 > 0.f) ? y0 : expm1f(y0);
        y1 = (y1 > 0.f) ? y1 : expm1f(y1);
        __half h0 = __float2half(y0), h1 = __float2half(y1);
        uh.h2[j] = __halves2half2(h0, h1);
        ul.h2[j] = __halves2half2(__float2half(y0 - __half2float(h0)),
                                  __float2half(y1 - __half2float(h1)));
    }
    *reinterpret_cast<uint4*>(hi + (size_t)warp * 256 + lane * 8) = uh.u;
    *reinterpret_cast<uint4*>(lo + (size_t)warp * 256 + lane * 8) = ul.u;
}

// ===== fused aggregation(D=128,H=1) + bias + final LN -> fp32 out =====
__global__ __launch_bounds__(256) void aggln128_kernel(
    const __half* __restrict__ h, const float* __restrict__ aexp, const float* __restrict__ rden,
    const int* __restrict__ col, const int* __restrict__ rptr, const int* __restrict__ redges,
    const float* __restrict__ bias, const float* __restrict__ gam, const float* __restrict__ bet,
    float* __restrict__ out, int n)
{
    int warp = (blockIdx.x * blockDim.x + threadIdx.x) >> 5;
    int lane = threadIdx.x & 31;
    if (warp >= n) return;
    float acc[4];
#pragma unroll
    for (int j = 0; j < 4; j++) acc[j] = 0.f;
    int s = rptr[warp], e1 = rptr[warp + 1];
    int i = s;
    for (; i + 1 < e1; i += 2) {
        int ea = redges[i], eb = redges[i + 1];
        int ca = col[ea], cb = col[eb];
        float wa = aexp[ea] * rden[ca];
        float wb = aexp[eb] * rden[cb];
        uint2 ra = *reinterpret_cast<const uint2*>(h + (size_t)ca * 128 + lane * 4);
        uint2 rb = *reinterpret_cast<const uint2*>(h + (size_t)cb * 128 + lane * 4);
        const __half2* pa = reinterpret_cast<const __half2*>(&ra);
        const __half2* pb = reinterpret_cast<const __half2*>(&rb);
#pragma unroll
        for (int j = 0; j < 2; j++) {
            float2 fa = __half22float2(pa[j]);
            float2 fb = __half22float2(pb[j]);
            acc[2 * j]     += wa * fa.x + wb * fb.x;
            acc[2 * j + 1] += wa * fa.y + wb * fb.y;
        }
    }
    if (i < e1) {
        int e = redges[i];
        int c = col[e];
        float w = aexp[e] * rden[c];
        uint2 r = *reinterpret_cast<const uint2*>(h + (size_t)c * 128 + lane * 4);
        const __half2* p = reinterpret_cast<const __half2*>(&r);
#pragma unroll
        for (int j = 0; j < 2; j++) {
            float2 f = __half22float2(p[j]);
            acc[2 * j]     += w * f.x;
            acc[2 * j + 1] += w * f.y;
        }
    }
    float4 b0 = *reinterpret_cast<const float4*>(bias + lane * 4);
    acc[0] += b0.x; acc[1] += b0.y; acc[2] += b0.z; acc[3] += b0.w;
    float sum = 0.f, sumsq = 0.f;
#pragma unroll
    for (int j = 0; j < 4; j++) { sum += acc[j]; sumsq += acc[j] * acc[j]; }
#pragma unroll
    for (int o = 16; o; o >>= 1) {
        sum += __shfl_xor_sync(0xffffffffu, sum, o);
        sumsq += __shfl_xor_sync(0xffffffffu, sumsq, o);
    }
    float mu = sum * (1.0f / 128.0f);
    float var = sumsq * (1.0f / 128.0f) - mu * mu;
    float r = rsqrtf(var + EPS_LN);
    float4 g0 = *reinterpret_cast<const float4*>(gam + lane * 4);
    float4 e0 = *reinterpret_cast<const float4*>(bet + lane * 4);
    float4 o0 = make_float4((acc[0] - mu) * r * g0.x + e0.x,
                            (acc[1] - mu) * r * g0.y + e0.y,
                            (acc[2] - mu) * r * g0.z + e0.z,
                            (acc[3] - mu) * r * g0.w + e0.w);
    *reinterpret_cast<float4*>(out + (size_t)warp * 128 + lane * 4) = o0;
}

// ---------------- host orchestration ----------------
static inline int ceil_div(int a, int b) { return (a + b - 1) / b; }

extern "C" void kernel_launch(void* const* d_in, const int* in_sizes, int n_in,
                              void* d_out, int out_size) {
    const float* x   = (const float*)d_in[0];
    const int*   ei  = (const int*)d_in[1];
    const float* ew  = (const float*)d_in[2];
    const float* W1  = (const float*)d_in[3];
    const float* as1 = (const float*)d_in[4];
    const float* ad1 = (const float*)d_in[5];
    const float* b1  = (const float*)d_in[6];
    const float* g1  = (const float*)d_in[7];
    const float* be1 = (const float*)d_in[8];
    const float* W2  = (const float*)d_in[9];
    const float* as2 = (const float*)d_in[10];
    const float* ad2 = (const float*)d_in[11];
    const float* b2  = (const float*)d_in[12];
    const float* g2  = (const float*)d_in[13];
    const float* be2 = (const float*)d_in[14];
    const float* W3  = (const float*)d_in[15];
    const float* as3 = (const float*)d_in[16];
    const float* ad3 = (const float*)d_in[17];
    const float* b3  = (const float*)d_in[18];
    const float* g3  = (const float*)d_in[19];
    const float* be3 = (const float*)d_in[20];
    float* out = (float*)d_out;

    const int* row = ei;
    const int* col = ei + NEDGE;

    float *alpha, *denomA, *denomB, *denomC, *score1, *score2, *score3;
    int *cnt, *rptr, *fill, *redges;
    __half *h16, *ahi, *alo, *wt1, *wt2, *wt3;
    cudaGetSymbolAddress((void**)&h16, g_h16);
    cudaGetSymbolAddress((void**)&alpha, g_alpha);
    cudaGetSymbolAddress((void**)&denomA, g_denomA);
    cudaGetSymbolAddress((void**)&denomB, g_denomB);
    cudaGetSymbolAddress((void**)&denomC, g_denomC);
    cudaGetSymbolAddress((void**)&score1, g_score1);
    cudaGetSymbolAddress((void**)&score2, g_score2);
    cudaGetSymbolAddress((void**)&score3, g_score3);
    cudaGetSymbolAddress((void**)&cnt, g_cnt);
    cudaGetSymbolAddress((void**)&rptr, g_rptr);
    cudaGetSymbolAddress((void**)&fill, g_fill);
    cudaGetSymbolAddress((void**)&redges, g_redges);
    cudaGetSymbolAddress((void**)&ahi, g_ahi);
    cudaGetSymbolAddress((void**)&alo, g_alo);
    cudaGetSymbolAddress((void**)&wt1, g_wt1);
    cudaGetSymbolAddress((void**)&wt2, g_wt2);
    cudaGetSymbolAddress((void**)&wt3, g_wt3);

    const int TB = 256;
    const int eb = ceil_div(NEDGE, TB);
    const int mtiles = ceil_div(NNODE, 128);
    const int SMEM = 3 * 24576;

    cudaFuncSetAttribute(gemm_mma<256, 384>, cudaFuncAttributeMaxDynamicSharedMemorySize, SMEM);
    cudaFuncSetAttribute(gemm_mma<256, 256>, cudaFuncAttributeMaxDynamicSharedMemorySize, SMEM);
    cudaFuncSetAttribute(gemm_mma<128, 256>, cudaFuncAttributeMaxDynamicSharedMemorySize, SMEM);

    // lazily created side streams/events (resource setup, reused across calls)
    static cudaStream_t s1 = nullptr, s2 = nullptr;
    static cudaEvent_t evF = nullptr, evJ1 = nullptr, evJ2 = nullptr;
    if (!s1) {
        cudaStreamCreateWithFlags(&s1, cudaStreamNonBlocking);
        cudaStreamCreateWithFlags(&s2, cudaStreamNonBlocking);
        cudaEventCreateWithFlags(&evF, cudaEventDisableTiming);
        cudaEventCreateWithFlags(&evJ1, cudaEventDisableTiming);
        cudaEventCreateWithFlags(&evJ2, cudaEventDisableTiming);
    }

    // ---- fork ----
    cudaEventRecord(evF, 0);
    cudaStreamWaitEvent(s1, evF, 0);
    cudaStreamWaitEvent(s2, evF, 0);

    // s1: CSR build
    zero_i<<<ceil_div(NNODE, TB), TB, 0, s1>>>(cnt, NNODE);
    hist_kernel<<<eb, TB, 0, s1>>>(row, cnt, NEDGE);
    scan_kernel<<<1, 1024, 0, s1>>>(cnt, rptr, fill, NNODE);
    scatter_kernel<<<eb, TB, 0, s1>>>(row, fill, redges, NEDGE);
    cudaEventRecord(evJ1, s1);

    // s2: next-layer weights + zero score2/3, denomB/C
    prep_side_kernel<<<ceil_div(NNODE * 8, TB), TB, 0, s2>>>(
        W2, wt2, W3, wt3, score2, score3, NNODE * 8, denomB, denomC, NNODE * 4);
    cudaEventRecord(evJ2, s2);

    // main: layer-1 front
    asplit_fused_kernel<<<ceil_div(NNODE * 384, TB), TB>>>(
        x, ahi, alo, NNODE * 384, W1, wt1, 384, 256,
        score1, NNODE * 8, denomA, NNODE * 4);
    gemm_mma<256, 384><<<dim3(2, mtiles), 256, SMEM>>>(
        ahi, alo, wt1, h16, as1, ad1, score1, score1 + NNODE * 4, 4, 64, NNODE);
    edge_scores4_kernel<<<eb, TB>>>(row, col, ew, score1, score1 + NNODE * 4, alpha, denomA, NEDGE);
    rdenom_kernel<<<ceil_div(NNODE * 4, TB), TB>>>(denomA, NNODE * 4);

    // ---- join ----
    cudaStreamWaitEvent(0, evJ1, 0);
    cudaStreamWaitEvent(0, evJ2, 0);

    aggln256_kernel<<<ceil_div(NNODE * 32, TB), TB>>>(
        h16, alpha, denomA, col, rptr, redges, b1, g1, be1, ahi, alo, NNODE);

    // =============== Layer 2 ===============
    gemm_mma<256, 256><<<dim3(2, mtiles), 256, SMEM>>>(
        ahi, alo, wt2, h16, as2, ad2, score2, score2 + NNODE * 4, 4, 64, NNODE);
    edge_scores4_kernel<<<eb, TB>>>(row, col, ew, score2, score2 + NNODE * 4, alpha, denomB, NEDGE);
    rdenom_kernel<<<ceil_div(NNODE * 4, TB), TB>>>(denomB, NNODE * 4);
    aggln256_kernel<<<ceil_div(NNODE * 32, TB), TB>>>(
        h16, alpha, denomB, col, rptr, redges, b2, g2, be2, ahi, alo, NNODE);

    // =============== Layer 3 ===============
    gemm_mma<128, 256><<<dim3(1, mtiles), 256, SMEM>>>(
        ahi, alo, wt3, h16, as3, ad3, score3, score3 + NNODE * 4, 1, 128, NNODE);
    edge_scores1_kernel<<<eb, TB>>>(row, col, ew, score3, score3 + NNODE * 4, alpha, denomC, NEDGE);
    rdenom_kernel<<<ceil_div(NNODE, TB), TB>>>(denomC, NNODE);
    aggln128_kernel<<<ceil_div(NNODE * 32, TB), TB>>>(
        h16, alpha, denomC, col, rptr, redges, b3, g3, be3, out, NNODE);
}

// round 13
// speedup vs baseline: 1.1489x; 1.0047x over previous
#include <cuda_runtime.h>
#include <cuda_fp16.h>
#include <math.h>
#include <stdint.h>

#define NNODE 50000
#define NEDGE 500000
#define DMAX  256
#define EPS_SM 1e-16f
#define EPS_LN 1e-5f
#define NEG_SLOPE 0.2f
#define NSPLIT 25088            // 196 * 128, node split for pipelining

// ---------------- scratch (device globals) ----------------
__device__ __half g_h16[NNODE * DMAX];
__device__ float g_alpha[NEDGE * 4];
__device__ float g_denomA[NNODE * 4];
__device__ float g_denomB[NNODE * 4];
__device__ float g_denomC[NNODE * 4];
__device__ float g_score1[NNODE * 8];
__device__ float g_score2[NNODE * 8];
__device__ float g_score3[NNODE * 8];
__device__ int   g_cnt[NNODE];
__device__ int   g_rptr[NNODE + 1];
__device__ int   g_fill[NNODE];
__device__ int   g_redges[NEDGE];
__device__ __half g_ahi[NNODE * 384];
__device__ __half g_alo[NNODE * 384];
__device__ __half g_wt1[256 * 384];
__device__ __half g_wt2[256 * 256];
__device__ __half g_wt3[128 * 256];

// ================= PTX helpers =================
__device__ __forceinline__ uint32_t smem_u32(const void* p) {
    uint32_t a;
    asm("{ .reg .u64 t; cvta.to.shared.u64 t, %1; cvt.u32.u64 %0, t; }" : "=r"(a) : "l"(p));
    return a;
}

#define CPA16(dst, src, sz) \
    asm volatile("cp.async.cg.shared.global [%0], [%1], 16, %2;" \
                 :: "r"(dst), "l"(src), "r"(sz))
#define CPA_COMMIT() asm volatile("cp.async.commit_group;" ::: "memory")
#define CPA_WAIT(n)  asm volatile("cp.async.wait_group %0;" :: "n"(n) : "memory")

#define LDMX4(r0, r1, r2, r3, addr) \
    asm volatile("ldmatrix.sync.aligned.m8n8.x4.shared.b16 {%0,%1,%2,%3}, [%4];" \
                 : "=r"(r0), "=r"(r1), "=r"(r2), "=r"(r3) : "r"(addr))

__device__ __forceinline__ void mma16816h(float* c, const uint32_t* a, const uint32_t* b) {
    asm volatile(
        "mma.sync.aligned.m16n8k16.row.col.f32.f16.f16.f32 "
        "{%0,%1,%2,%3}, {%4,%5,%6,%7}, {%8,%9}, {%0,%1,%2,%3};"
        : "+f"(c[0]), "+f"(c[1]), "+f"(c[2]), "+f"(c[3])
        : "r"(a[0]), "r"(a[1]), "r"(a[2]), "r"(a[3]), "r"(b[0]), "r"(b[1]));
}

#define SWZ64(b) ((b) ^ (((b) >> 3) & 0x30))

// ---------------- small utility ----------------
__global__ void zero_i(int* p, int n) {
    int i = blockIdx.x * blockDim.x + threadIdx.x;
    if (i < n) p[i] = 0;
}

// ---------------- activation split over element range + optional prep ----------------
__global__ void asplit_fused_kernel(
    const float* __restrict__ A, __half* hi, __half* lo, int off, int cnt,
    const float* __restrict__ W, __half* wt, int K, int Nn,
    float* score, int nscore, float* den, int nden)
{
    int i = blockIdx.x * blockDim.x + threadIdx.x;
    if (i < cnt) {
        int j = off + i;
        float v = A[j];
        __half h = __float2half(v);
        hi[j] = h;
        lo[j] = __float2half(v - __half2float(h));
    }
    if (i < K * Nn) {
        int n = i / K, k = i - n * K;
        wt[i] = __float2half(W[(size_t)k * Nn + n]);
    }
    if (i < nscore) score[i] = 0.0f;
    if (i < nden) den[i] = 0.0f;
}

// ---------------- side prep: wprep2 + wprep3 + zero score2/3, denomB/C ----------------
__global__ void prep_side_kernel(
    const float* __restrict__ W2, __half* wt2,
    const float* __restrict__ W3, __half* wt3,
    float* sc2, float* sc3, int nscore,
    float* dB, float* dC, int nden)
{
    int i = blockIdx.x * blockDim.x + threadIdx.x;
    if (i < 256 * 256) {
        int n = i / 256, k = i - n * 256;
        wt2[i] = __float2half(W2[(size_t)k * 256 + n]);
    }
    if (i < 128 * 256) {
        int n = i / 256, k = i - n * 256;
        wt3[i] = __float2half(W3[(size_t)k * 128 + n]);
    }
    if (i < nscore) { sc2[i] = 0.0f; sc3[i] = 0.0f; }
    if (i < nden) { dB[i] = 0.0f; dC[i] = 0.0f; }
}

// ---------------- CSR build ----------------
__global__ void hist_kernel(const int* __restrict__ row, int* cnt, int e) {
    int i = blockIdx.x * blockDim.x + threadIdx.x;
    if (i < e) atomicAdd(&cnt[row[i]], 1);
}

__global__ void scan_kernel(const int* __restrict__ cnt, int* ptr, int* fill, int n) {
    __shared__ int sh[1024];
    __shared__ int carry;
    if (threadIdx.x == 0) carry = 0;
    __syncthreads();
    for (int base = 0; base < n; base += 1024) {
        int i = base + threadIdx.x;
        int v = (i < n) ? cnt[i] : 0;
        sh[threadIdx.x] = v;
        __syncthreads();
        for (int off = 1; off < 1024; off <<= 1) {
            int t = (threadIdx.x >= off) ? sh[threadIdx.x - off] : 0;
            __syncthreads();
            sh[threadIdx.x] += t;
            __syncthreads();
        }
        int excl = sh[threadIdx.x] - v;
        if (i < n) { ptr[i] = carry + excl; fill[i] = carry + excl; }
        __syncthreads();
        if (threadIdx.x == 1023) carry += sh[1023];
        __syncthreads();
    }
    if (threadIdx.x == 0) ptr[n] = carry;
}

__global__ void scatter_kernel(const int* __restrict__ row, int* fill, int* redges, int e) {
    int i = blockIdx.x * blockDim.x + threadIdx.x;
    if (i < e) {
        int pos = atomicAdd(&fill[row[i]], 1);
        redges[pos] = i;
    }
}

// ===== HMMA fp16 2-term GEMM 128x128 tile + fused attention scores =====
// moff: m-tile offset (for half-grid pipelining)
template <int NN, int KK>
__global__ __launch_bounds__(256, 2) void gemm_mma(
    const __half* __restrict__ Ahi, const __half* __restrict__ Alo,
    const __half* __restrict__ Bw,
    __half* __restrict__ C,
    const float* __restrict__ Av, const float* __restrict__ Dv,
    float* __restrict__ Ssrc, float* __restrict__ Sdst,
    int H, int Cc, int M, int moff)
{
    constexpr int BK = 32;
    constexpr int NCH = KK / BK;
    constexpr int STG = 24576;
    extern __shared__ char smem[];
    uint32_t sb = smem_u32(smem);

    int tid = threadIdx.x;
    int lane = tid & 31, wid = tid >> 5;
    int wm = wid & 3, wn = wid >> 2;
    int m0 = (blockIdx.y + moff) * 128;
    int n0 = blockIdx.x * 128;

    int g = lane >> 3, lr = lane & 7;
    uint32_t aoff[2][2];
#pragma unroll
    for (int mt = 0; mt < 2; mt++)
#pragma unroll
        for (int ks = 0; ks < 2; ks++) {
            int row = wm * 32 + mt * 16 + (g & 1) * 8 + lr;
            int unit = ks * 2 + (g >> 1);
            aoff[mt][ks] = SWZ64(row * 64 + unit * 16);
        }
    uint32_t boff[4][2];
#pragma unroll
    for (int np = 0; np < 4; np++)
#pragma unroll
        for (int ks = 0; ks < 2; ks++) {
            int row = wn * 64 + np * 16 + (g >> 1) * 8 + lr;
            int unit = ks * 2 + (g & 1);
            boff[np][ks] = 16384u + SWZ64(row * 64 + unit * 16);
        }

    int r0 = tid >> 2, u0 = tid & 3;
    uint32_t sw0 = SWZ64(r0 * 64 + u0 * 16);
    uint32_t sw1 = SWZ64((r0 + 64) * 64 + u0 * 16);
    long bofs0 = (long)(n0 + r0) * KK + u0 * 8;
    long bofs1 = (long)(n0 + r0 + 64) * KK + u0 * 8;

    float acc[2][8][4];
#pragma unroll
    for (int mt = 0; mt < 2; mt++)
#pragma unroll
        for (int nt = 0; nt < 8; nt++)
#pragma unroll
            for (int j = 0; j < 4; j++) acc[mt][nt][j] = 0.f;

    auto load_stage = [&](int ch, uint32_t so) {
        int k0 = ch * BK;
        {
            int grow = m0 + r0;
            int sz = (grow < M) ? 16 : 0;
            long go = (long)((grow < M) ? grow : 0) * KK + k0 + u0 * 8;
            CPA16(sb + so + sw0, Ahi + go, sz);
            CPA16(sb + so + 8192 + sw0, Alo + go, sz);
        }
        {
            int grow = m0 + r0 + 64;
            int sz = (grow < M) ? 16 : 0;
            long go = (long)((grow < M) ? grow : 0) * KK + k0 + u0 * 8;
            CPA16(sb + so + sw1, Ahi + go, sz);
            CPA16(sb + so + 8192 + sw1, Alo + go, sz);
        }
        CPA16(sb + so + 16384 + sw0, Bw + bofs0 + k0, 16);
        CPA16(sb + so + 16384 + sw1, Bw + bofs1 + k0, 16);
    };

    auto compute_stage = [&](uint32_t so) {
#pragma unroll
        for (int ks = 0; ks < 2; ks++) {
            uint32_t ah[2][4], al[2][4], b[8][2];
#pragma unroll
            for (int mt = 0; mt < 2; mt++) {
                LDMX4(ah[mt][0], ah[mt][1], ah[mt][2], ah[mt][3], sb + so + aoff[mt][ks]);
                LDMX4(al[mt][0], al[mt][1], al[mt][2], al[mt][3], sb + so + 8192 + aoff[mt][ks]);
            }
#pragma unroll
            for (int np = 0; np < 4; np++)
                LDMX4(b[2 * np][0], b[2 * np][1], b[2 * np + 1][0], b[2 * np + 1][1],
                      sb + so + boff[np][ks]);
#pragma unroll
            for (int mt = 0; mt < 2; mt++)
#pragma unroll
                for (int nt = 0; nt < 8; nt++) {
                    mma16816h(acc[mt][nt], ah[mt], b[nt]);
                    mma16816h(acc[mt][nt], al[mt], b[nt]);
                }
        }
    };

    load_stage(0, 0);
    CPA_COMMIT();
    load_stage(1, STG);
    CPA_COMMIT();
#pragma unroll 1
    for (int ch = 0; ch < NCH; ch++) {
        uint32_t so = (uint32_t)(ch % 3) * STG;
        if (ch + 1 < NCH) { CPA_WAIT(1); } else { CPA_WAIT(0); }
        __syncthreads();
        if (ch + 2 < NCH) {
            load_stage(ch + 2, (uint32_t)((ch + 2) % 3) * STG);
            CPA_COMMIT();
        }
        compute_stage(so);
    }

    // epilogue 1: fp16 h store
#pragma unroll
    for (int mt = 0; mt < 2; mt++) {
        int m = m0 + wm * 32 + mt * 16 + (lane >> 2);
#pragma unroll
        for (int nt = 0; nt < 8; nt++) {
            int n = n0 + wn * 64 + nt * 8 + (lane & 3) * 2;
            if (m < M)
                *reinterpret_cast<__half2*>(C + (size_t)m * NN + n) =
                    __floats2half2_rn(acc[mt][nt][0], acc[mt][nt][1]);
            if (m + 8 < M)
                *reinterpret_cast<__half2*>(C + (size_t)(m + 8) * NN + n) =
                    __floats2half2_rn(acc[mt][nt][2], acc[mt][nt][3]);
        }
    }

    // epilogue 2: fused attention scores
    {
        int head = (n0 + wn * 64) / Cc;
        float av[16], dv[16];
#pragma unroll
        for (int nt = 0; nt < 8; nt++) {
            int c0 = (n0 + wn * 64 + nt * 8 + (lane & 3) * 2) - head * Cc;
            av[2 * nt] = Av[head * Cc + c0];
            av[2 * nt + 1] = Av[head * Cc + c0 + 1];
            dv[2 * nt] = Dv[head * Cc + c0];
            dv[2 * nt + 1] = Dv[head * Cc + c0 + 1];
        }
#pragma unroll
        for (int mt = 0; mt < 2; mt++) {
            float ps0 = 0.f, pd0 = 0.f, ps1 = 0.f, pd1 = 0.f;
#pragma unroll
            for (int nt = 0; nt < 8; nt++) {
                ps0 += acc[mt][nt][0] * av[2 * nt] + acc[mt][nt][1] * av[2 * nt + 1];
                pd0 += acc[mt][nt][0] * dv[2 * nt] + acc[mt][nt][1] * dv[2 * nt + 1];
                ps1 += acc[mt][nt][2] * av[2 * nt] + acc[mt][nt][3] * av[2 * nt + 1];
                pd1 += acc[mt][nt][2] * dv[2 * nt] + acc[mt][nt][3] * dv[2 * nt + 1];
            }
#pragma unroll
            for (int o = 1; o <= 2; o <<= 1) {
                ps0 += __shfl_xor_sync(0xffffffffu, ps0, o);
                pd0 += __shfl_xor_sync(0xffffffffu, pd0, o);
                ps1 += __shfl_xor_sync(0xffffffffu, ps1, o);
                pd1 += __shfl_xor_sync(0xffffffffu, pd1, o);
            }
            if ((lane & 3) == 0) {
                int m = m0 + wm * 32 + mt * 16 + (lane >> 2);
                if (m < M) {
                    atomicAdd(&Ssrc[m * H + head], ps0);
                    atomicAdd(&Sdst[m * H + head], pd0);
                }
                if (m + 8 < M) {
                    atomicAdd(&Ssrc[(m + 8) * H + head], ps1);
                    atomicAdd(&Sdst[(m + 8) * H + head], pd1);
                }
            }
        }
    }
}

// ---------------- edge scores H=4 ----------------
__global__ void edge_scores4_kernel(
    const int* __restrict__ row, const int* __restrict__ col, const float* __restrict__ ew,
    const float* __restrict__ ssrc, const float* __restrict__ sdst,
    float* __restrict__ aexp, float* __restrict__ denom, int e)
{
    int i = blockIdx.x * blockDim.x + threadIdx.x;
    if (i >= e) return;
    int r = row[i], c = col[i];
    float w = ew[i];
    float4 s4 = *reinterpret_cast<const float4*>(ssrc + (size_t)r * 4);
    float4 d4 = *reinterpret_cast<const float4*>(sdst + (size_t)c * 4);
    float4 o;
    float v;
    v = s4.x + d4.x; v = (v >= 0.f) ? v : NEG_SLOPE * v; o.x = expf(v * w);
    v = s4.y + d4.y; v = (v >= 0.f) ? v : NEG_SLOPE * v; o.y = expf(v * w);
    v = s4.z + d4.z; v = (v >= 0.f) ? v : NEG_SLOPE * v; o.z = expf(v * w);
    v = s4.w + d4.w; v = (v >= 0.f) ? v : NEG_SLOPE * v; o.w = expf(v * w);
    *reinterpret_cast<float4*>(aexp + (size_t)i * 4) = o;
    atomicAdd(&denom[c * 4 + 0], o.x);
    atomicAdd(&denom[c * 4 + 1], o.y);
    atomicAdd(&denom[c * 4 + 2], o.z);
    atomicAdd(&denom[c * 4 + 3], o.w);
}

// ---------------- edge scores H=1 ----------------
__global__ void edge_scores1_kernel(
    const int* __restrict__ row, const int* __restrict__ col, const float* __restrict__ ew,
    const float* __restrict__ ssrc, const float* __restrict__ sdst,
    float* __restrict__ aexp, float* __restrict__ denom, int e)
{
    int i = blockIdx.x * blockDim.x + threadIdx.x;
    if (i >= e) return;
    int r = row[i], c = col[i];
    float v = ssrc[r] + sdst[c];
    v = (v >= 0.f) ? v : NEG_SLOPE * v;
    v = expf(v * ew[i]);
    aexp[i] = v;
    atomicAdd(&denom[c], v);
}

// ---------------- reciprocal of denominators ----------------
__global__ void rdenom_kernel(float* d, int n) {
    int i = blockIdx.x * blockDim.x + threadIdx.x;
    if (i < n) d[i] = 1.0f / (d[i] + EPS_SM);
}

// ===== fused aggregation(D=256,H=4) + bias + LN + ELU + fp16 split, node range =====
__global__ __launch_bounds__(256) void aggln256_kernel(
    const __half* __restrict__ h, const float* __restrict__ aexp, const float* __restrict__ rden,
    const int* __restrict__ col, const int* __restrict__ rptr, const int* __restrict__ redges,
    const float* __restrict__ bias, const float* __restrict__ gam, const float* __restrict__ bet,
    __half* __restrict__ hi, __half* __restrict__ lo, int noff, int nend)
{
    int warp = ((blockIdx.x * blockDim.x + threadIdx.x) >> 5) + noff;
    int lane = threadIdx.x & 31;
    if (warp >= nend) return;
    int hh = lane >> 3;
    float acc[8];
#pragma unroll
    for (int j = 0; j < 8; j++) acc[j] = 0.f;
    int s = rptr[warp], e1 = rptr[warp + 1];
    int i = s;
    for (; i + 1 < e1; i += 2) {
        int ea = redges[i], eb = redges[i + 1];
        int ca = col[ea], cb = col[eb];
        float wa = aexp[(size_t)ea * 4 + hh] * rden[(size_t)ca * 4 + hh];
        float wb = aexp[(size_t)eb * 4 + hh] * rden[(size_t)cb * 4 + hh];
        uint4 ra = *reinterpret_cast<const uint4*>(h + (size_t)ca * 256 + lane * 8);
        uint4 rb = *reinterpret_cast<const uint4*>(h + (size_t)cb * 256 + lane * 8);
        const __half2* pa = reinterpret_cast<const __half2*>(&ra);
        const __half2* pb = reinterpret_cast<const __half2*>(&rb);
#pragma unroll
        for (int j = 0; j < 4; j++) {
            float2 fa = __half22float2(pa[j]);
            float2 fb = __half22float2(pb[j]);
            acc[2 * j]     += wa * fa.x + wb * fb.x;
            acc[2 * j + 1] += wa * fa.y + wb * fb.y;
        }
    }
    if (i < e1) {
        int e = redges[i];
        int c = col[e];
        float w = aexp[(size_t)e * 4 + hh] * rden[(size_t)c * 4 + hh];
        uint4 r = *reinterpret_cast<const uint4*>(h + (size_t)c * 256 + lane * 8);
        const __half2* p = reinterpret_cast<const __half2*>(&r);
#pragma unroll
        for (int j = 0; j < 4; j++) {
            float2 f = __half22float2(p[j]);
            acc[2 * j]     += w * f.x;
            acc[2 * j + 1] += w * f.y;
        }
    }
    const float4* bp = reinterpret_cast<const float4*>(bias + lane * 8);
    float4 b0 = bp[0], b1 = bp[1];
    acc[0] += b0.x; acc[1] += b0.y; acc[2] += b0.z; acc[3] += b0.w;
    acc[4] += b1.x; acc[5] += b1.y; acc[6] += b1.z; acc[7] += b1.w;
    float sum = 0.f, sumsq = 0.f;
#pragma unroll
    for (int j = 0; j < 8; j++) { sum += acc[j]; sumsq += acc[j] * acc[j]; }
#pragma unroll
    for (int o = 16; o; o >>= 1) {
        sum += __shfl_xor_sync(0xffffffffu, sum, o);
        sumsq += __shfl_xor_sync(0xffffffffu, sumsq, o);
    }
    float mu = sum * (1.0f / 256.0f);
    float var = sumsq * (1.0f / 256.0f) - mu * mu;
    float r = rsqrtf(var + EPS_LN);
    const float4* gp = reinterpret_cast<const float4*>(gam + lane * 8);
    const float4* ep = reinterpret_cast<const float4*>(bet + lane * 8);
    float4 g0 = gp[0], g1 = gp[1], e0 = ep[0], e1v = ep[1];
    float gg[8] = {g0.x, g0.y, g0.z, g0.w, g1.x, g1.y, g1.z, g1.w};
    float ee[8] = {e0.x, e0.y, e0.z, e0.w, e1v.x, e1v.y, e1v.z, e1v.w};
    union { __half2 h2[4]; uint4 u; } uh, ul;
#pragma unroll
    for (int j = 0; j < 4; j++) {
        float y0 = (acc[2 * j] - mu) * r * gg[2 * j] + ee[2 * j];
        float y1 = (acc[2 * j + 1] - mu) * r * gg[2 * j + 1] + ee[2 * j + 1];
        y0 = (y0 > 0.f) ? y0 : expm1f(y0);
        y1 = (y1 > 0.f) ? y1 : expm1f(y1);
        __half h0 = __float2half(y0), h1 = __float2half(y1);
        uh.h2[j] = __halves2half2(h0, h1);
        ul.h2[j] = __halves2half2(__float2half(y0 - __half2float(h0)),
                                  __float2half(y1 - __half2float(h1)));
    }
    *reinterpret_cast<uint4*>(hi + (size_t)warp * 256 + lane * 8) = uh.u;
    *reinterpret_cast<uint4*>(lo + (size_t)warp * 256 + lane * 8) = ul.u;
}

// ===== fused aggregation(D=128,H=1) + bias + final LN -> fp32 out =====
__global__ __launch_bounds__(256) void aggln128_kernel(
    const __half* __restrict__ h, const float* __restrict__ aexp, const float* __restrict__ rden,
    const int* __restrict__ col, const int* __restrict__ rptr, const int* __restrict__ redges,
    const float* __restrict__ bias, const float* __restrict__ gam, const float* __restrict__ bet,
    float* __restrict__ out, int n)
{
    int warp = (blockIdx.x * blockDim.x + threadIdx.x) >> 5;
    int lane = threadIdx.x & 31;
    if (warp >= n) return;
    float acc[4];
#pragma unroll
    for (int j = 0; j < 4; j++) acc[j] = 0.f;
    int s = rptr[warp], e1 = rptr[warp + 1];
    int i = s;
    for (; i + 1 < e1; i += 2) {
        int ea = redges[i], eb = redges[i + 1];
        int ca = col[ea], cb = col[eb];
        float wa = aexp[ea] * rden[ca];
        float wb = aexp[eb] * rden[cb];
        uint2 ra = *reinterpret_cast<const uint2*>(h + (size_t)ca * 128 + lane * 4);
        uint2 rb = *reinterpret_cast<const uint2*>(h + (size_t)cb * 128 + lane * 4);
        const __half2* pa = reinterpret_cast<const __half2*>(&ra);
        const __half2* pb = reinterpret_cast<const __half2*>(&rb);
#pragma unroll
        for (int j = 0; j < 2; j++) {
            float2 fa = __half22float2(pa[j]);
            float2 fb = __half22float2(pb[j]);
            acc[2 * j]     += wa * fa.x + wb * fb.x;
            acc[2 * j + 1] += wa * fa.y + wb * fb.y;
        }
    }
    if (i < e1) {
        int e = redges[i];
        int c = col[e];
        float w = aexp[e] * rden[c];
        uint2 r = *reinterpret_cast<const uint2*>(h + (size_t)c * 128 + lane * 4);
        const __half2* p = reinterpret_cast<const __half2*>(&r);
#pragma unroll
        for (int j = 0; j < 2; j++) {
            float2 f = __half22float2(p[j]);
            acc[2 * j]     += w * f.x;
            acc[2 * j + 1] += w * f.y;
        }
    }
    float4 b0 = *reinterpret_cast<const float4*>(bias + lane * 4);
    acc[0] += b0.x; acc[1] += b0.y; acc[2] += b0.z; acc[3] += b0.w;
    float sum = 0.f, sumsq = 0.f;
#pragma unroll
    for (int j = 0; j < 4; j++) { sum += acc[j]; sumsq += acc[j] * acc[j]; }
#pragma unroll
    for (int o = 16; o; o >>= 1) {
        sum += __shfl_xor_sync(0xffffffffu, sum, o);
        sumsq += __shfl_xor_sync(0xffffffffu, sumsq, o);
    }
    float mu = sum * (1.0f / 128.0f);
    float var = sumsq * (1.0f / 128.0f) - mu * mu;
    float r = rsqrtf(var + EPS_LN);
    float4 g0 = *reinterpret_cast<const float4*>(gam + lane * 4);
    float4 e0 = *reinterpret_cast<const float4*>(bet + lane * 4);
    float4 o0 = make_float4((acc[0] - mu) * r * g0.x + e0.x,
                            (acc[1] - mu) * r * g0.y + e0.y,
                            (acc[2] - mu) * r * g0.z + e0.z,
                            (acc[3] - mu) * r * g0.w + e0.w);
    *reinterpret_cast<float4*>(out + (size_t)warp * 128 + lane * 4) = o0;
}

// ---------------- host orchestration ----------------
static inline int ceil_div(int a, int b) { return (a + b - 1) / b; }

extern "C" void kernel_launch(void* const* d_in, const int* in_sizes, int n_in,
                              void* d_out, int out_size) {
    const float* x   = (const float*)d_in[0];
    const int*   ei  = (const int*)d_in[1];
    const float* ew  = (const float*)d_in[2];
    const float* W1  = (const float*)d_in[3];
    const float* as1 = (const float*)d_in[4];
    const float* ad1 = (const float*)d_in[5];
    const float* b1  = (const float*)d_in[6];
    const float* g1  = (const float*)d_in[7];
    const float* be1 = (const float*)d_in[8];
    const float* W2  = (const float*)d_in[9];
    const float* as2 = (const float*)d_in[10];
    const float* ad2 = (const float*)d_in[11];
    const float* b2  = (const float*)d_in[12];
    const float* g2  = (const float*)d_in[13];
    const float* be2 = (const float*)d_in[14];
    const float* W3  = (const float*)d_in[15];
    const float* as3 = (const float*)d_in[16];
    const float* ad3 = (const float*)d_in[17];
    const float* b3  = (const float*)d_in[18];
    const float* g3  = (const float*)d_in[19];
    const float* be3 = (const float*)d_in[20];
    float* out = (float*)d_out;

    const int* row = ei;
    const int* col = ei + NEDGE;

    float *alpha, *denomA, *denomB, *denomC, *score1, *score2, *score3;
    int *cnt, *rptr, *fill, *redges;
    __half *h16, *ahi, *alo, *wt1, *wt2, *wt3;
    cudaGetSymbolAddress((void**)&h16, g_h16);
    cudaGetSymbolAddress((void**)&alpha, g_alpha);
    cudaGetSymbolAddress((void**)&denomA, g_denomA);
    cudaGetSymbolAddress((void**)&denomB, g_denomB);
    cudaGetSymbolAddress((void**)&denomC, g_denomC);
    cudaGetSymbolAddress((void**)&score1, g_score1);
    cudaGetSymbolAddress((void**)&score2, g_score2);
    cudaGetSymbolAddress((void**)&score3, g_score3);
    cudaGetSymbolAddress((void**)&cnt, g_cnt);
    cudaGetSymbolAddress((void**)&rptr, g_rptr);
    cudaGetSymbolAddress((void**)&fill, g_fill);
    cudaGetSymbolAddress((void**)&redges, g_redges);
    cudaGetSymbolAddress((void**)&ahi, g_ahi);
    cudaGetSymbolAddress((void**)&alo, g_alo);
    cudaGetSymbolAddress((void**)&wt1, g_wt1);
    cudaGetSymbolAddress((void**)&wt2, g_wt2);
    cudaGetSymbolAddress((void**)&wt3, g_wt3);

    const int TB = 256;
    const int eb = ceil_div(NEDGE, TB);
    const int mtA = NSPLIT / 128;                       // 196
    const int mtB = ceil_div(NNODE, 128) - mtA;         // 195
    const int SMEM = 3 * 24576;

    cudaFuncSetAttribute(gemm_mma<256, 384>, cudaFuncAttributeMaxDynamicSharedMemorySize, SMEM);
    cudaFuncSetAttribute(gemm_mma<256, 256>, cudaFuncAttributeMaxDynamicSharedMemorySize, SMEM);
    cudaFuncSetAttribute(gemm_mma<128, 256>, cudaFuncAttributeMaxDynamicSharedMemorySize, SMEM);

    static cudaStream_t s1 = nullptr, s2 = nullptr;
    static cudaEvent_t ev0 = nullptr, evS2 = nullptr;
    static cudaEvent_t evR1 = nullptr, evR2 = nullptr;
    static cudaEvent_t evG1B = nullptr, evG2B = nullptr, evG3B = nullptr;
    if (!s1) {
        cudaStreamCreateWithFlags(&s1, cudaStreamNonBlocking);
        cudaStreamCreateWithFlags(&s2, cudaStreamNonBlocking);
        cudaEventCreateWithFlags(&ev0, cudaEventDisableTiming);
        cudaEventCreateWithFlags(&evS2, cudaEventDisableTiming);
        cudaEventCreateWithFlags(&evR1, cudaEventDisableTiming);
        cudaEventCreateWithFlags(&evR2, cudaEventDisableTiming);
        cudaEventCreateWithFlags(&evG1B, cudaEventDisableTiming);
        cudaEventCreateWithFlags(&evG2B, cudaEventDisableTiming);
        cudaEventCreateWithFlags(&evG3B, cudaEventDisableTiming);
    }

    // ---- fork ----
    cudaEventRecord(ev0, 0);
    cudaStreamWaitEvent(s1, ev0, 0);
    cudaStreamWaitEvent(s2, ev0, 0);

    // s2: CSR build + side prep (off critical path)
    zero_i<<<ceil_div(NNODE, TB), TB, 0, s2>>>(cnt, NNODE);
    hist_kernel<<<eb, TB, 0, s2>>>(row, cnt, NEDGE);
    scan_kernel<<<1, 1024, 0, s2>>>(cnt, rptr, fill, NNODE);
    scatter_kernel<<<eb, TB, 0, s2>>>(row, fill, redges, NEDGE);
    prep_side_kernel<<<ceil_div(NNODE * 8, TB), TB, 0, s2>>>(
        W2, wt2, W3, wt3, score2, score3, NNODE * 8, denomB, denomC, NNODE * 4);
    cudaEventRecord(evS2, s2);

    // ===== Layer 1 front, half-pipelined =====
    const int splitElems = NSPLIT * 384;
    // main: half A (also wprep1 + zero score1/denomA)
    asplit_fused_kernel<<<ceil_div(NNODE * 384, TB), TB>>>(
        x, ahi, alo, 0, splitElems, W1, wt1, 384, 256,
        score1, NNODE * 8, denomA, NNODE * 4);
    gemm_mma<256, 384><<<dim3(2, mtA), 256, SMEM>>>(
        ahi, alo, wt1, h16, as1, ad1, score1, score1 + NNODE * 4, 4, 64, NNODE, 0);
    // s1: half B
    asplit_fused_kernel<<<ceil_div(NNODE * 384 - splitElems, TB), TB, 0, s1>>>(
        x, ahi, alo, splitElems, NNODE * 384 - splitElems, W1, wt1, 0, 0,
        nullptr, 0, nullptr, 0);
    gemm_mma<256, 384><<<dim3(2, mtB), 256, SMEM, s1>>>(
        ahi, alo, wt1, h16, as1, ad1, score1, score1 + NNODE * 4, 4, 64, NNODE, mtA);
    cudaEventRecord(evG1B, s1);
    cudaStreamWaitEvent(0, evG1B, 0);

    edge_scores4_kernel<<<eb, TB>>>(row, col, ew, score1, score1 + NNODE * 4, alpha, denomA, NEDGE);
    rdenom_kernel<<<ceil_div(NNODE * 4, TB), TB>>>(denomA, NNODE * 4);
    cudaEventRecord(evR1, 0);
    cudaStreamWaitEvent(0, evS2, 0);      // CSR + wt2/score2 ready
    cudaStreamWaitEvent(s1, evS2, 0);
    cudaStreamWaitEvent(s1, evR1, 0);

    // ===== aggln1 / gemm2 half-pipelined =====
    aggln256_kernel<<<ceil_div(NSPLIT * 32, TB), TB>>>(
        h16, alpha, denomA, col, rptr, redges, b1, g1, be1, ahi, alo, 0, NSPLIT);
    gemm_mma<256, 256><<<dim3(2, mtA), 256, SMEM>>>(
        ahi, alo, wt2, h16, as2, ad2, score2, score2 + NNODE * 4, 4, 64, NNODE, 0);
    aggln256_kernel<<<ceil_div((NNODE - NSPLIT) * 32, TB), TB, 0, s1>>>(
        h16, alpha, denomA, col, rptr, redges, b1, g1, be1, ahi, alo, NSPLIT, NNODE);
    gemm_mma<256, 256><<<dim3(2, mtB), 256, SMEM, s1>>>(
        ahi, alo, wt2, h16, as2, ad2, score2, score2 + NNODE * 4, 4, 64, NNODE, mtA);
    cudaEventRecord(evG2B, s1);
    cudaStreamWaitEvent(0, evG2B, 0);

    edge_scores4_kernel<<<eb, TB>>>(row, col, ew, score2, score2 + NNODE * 4, alpha, denomB, NEDGE);
    rdenom_kernel<<<ceil_div(NNODE * 4, TB), TB>>>(denomB, NNODE * 4);
    cudaEventRecord(evR2, 0);
    cudaStreamWaitEvent(s1, evR2, 0);

    // ===== aggln2 / gemm3 half-pipelined =====
    aggln256_kernel<<<ceil_div(NSPLIT * 32, TB), TB>>>(
        h16, alpha, denomB, col, rptr, redges, b2, g2, be2, ahi, alo, 0, NSPLIT);
    gemm_mma<128, 256><<<dim3(1, mtA), 256, SMEM>>>(
        ahi, alo, wt3, h16, as3, ad3, score3, score3 + NNODE * 4, 1, 128, NNODE, 0);
    aggln256_kernel<<<ceil_div((NNODE - NSPLIT) * 32, TB), TB, 0, s1>>>(
        h16, alpha, denomB, col, rptr, redges, b2, g2, be2, ahi, alo, NSPLIT, NNODE);
    gemm_mma<128, 256><<<dim3(1, mtB), 256, SMEM, s1>>>(
        ahi, alo, wt3, h16, as3, ad3, score3, score3 + NNODE * 4, 1, 128, NNODE, mtA);
    cudaEventRecord(evG3B, s1);
    cudaStreamWaitEvent(0, evG3B, 0);

    // ===== Layer 3 tail =====
    edge_scores1_kernel<<<eb, TB>>>(row, col, ew, score3, score3 + NNODE * 4, alpha, denomC, NEDGE);
    rdenom_kernel<<<ceil_div(NNODE, TB), TB>>>(denomC, NNODE);
    aggln128_kernel<<<ceil_div(NNODE * 32, TB), TB>>>(
        h16, alpha, denomC, col, rptr, redges, b3, g3, be3, out, NNODE);
}

// round 14
// speedup vs baseline: 1.2137x; 1.0564x over previous
#include <cuda_runtime.h>
#include <cuda_fp16.h>
#include <math.h>
#include <stdint.h>

#define NNODE 50000
#define NEDGE 500000
#define DMAX  256
#define EPS_SM 1e-16f
#define EPS_LN 1e-5f
#define NEG_SLOPE 0.2f
#define NSPLIT 25088            // 196 * 128

// ---------------- scratch (device globals) ----------------
__device__ __half g_h16[NNODE * DMAX];
__device__ float g_alpha[NEDGE * 4];
__device__ float g_denomA[NNODE * 4];
__device__ float g_denomB[NNODE * 4];
__device__ float g_denomC[NNODE * 4];
__device__ float g_score1[NNODE * 8];
__device__ float g_score2[NNODE * 8];
__device__ float g_score3[NNODE * 8];
__device__ int   g_cnt[NNODE];
__device__ int   g_rptr[NNODE + 1];
__device__ int   g_fill[NNODE];
__device__ int   g_redges[NEDGE];
__device__ __half g_ahi[NNODE * 384];
__device__ __half g_alo[NNODE * 384];
__device__ __half g_wt1[256 * 384];
__device__ __half g_wt2[256 * 256];
__device__ __half g_wt3[128 * 256];

// ================= PTX helpers =================
__device__ __forceinline__ uint32_t smem_u32(const void* p) {
    uint32_t a;
    asm("{ .reg .u64 t; cvta.to.shared.u64 t, %1; cvt.u32.u64 %0, t; }" : "=r"(a) : "l"(p));
    return a;
}

#define CPA16(dst, src, sz) \
    asm volatile("cp.async.cg.shared.global [%0], [%1], 16, %2;" \
                 :: "r"(dst), "l"(src), "r"(sz))
#define CPA_COMMIT() asm volatile("cp.async.commit_group;" ::: "memory")
#define CPA_WAIT(n)  asm volatile("cp.async.wait_group %0;" :: "n"(n) : "memory")

#define LDMX4(r0, r1, r2, r3, addr) \
    asm volatile("ldmatrix.sync.aligned.m8n8.x4.shared.b16 {%0,%1,%2,%3}, [%4];" \
                 : "=r"(r0), "=r"(r1), "=r"(r2), "=r"(r3) : "r"(addr))

__device__ __forceinline__ void mma16816h(float* c, const uint32_t* a, const uint32_t* b) {
    asm volatile(
        "mma.sync.aligned.m16n8k16.row.col.f32.f16.f16.f32 "
        "{%0,%1,%2,%3}, {%4,%5,%6,%7}, {%8,%9}, {%0,%1,%2,%3};"
        : "+f"(c[0]), "+f"(c[1]), "+f"(c[2]), "+f"(c[3])
        : "r"(a[0]), "r"(a[1]), "r"(a[2]), "r"(a[3]), "r"(b[0]), "r"(b[1]));
}

#define SWZ64(b) ((b) ^ (((b) >> 3) & 0x30))

// ---------------- small utility ----------------
__global__ void zero_i(int* p, int n) {
    int i = blockIdx.x * blockDim.x + threadIdx.x;
    if (i < n) p[i] = 0;
}

// ---------------- activation convert (hi only or hi+lo) + optional prep ----------------
__global__ void asplit_fused_kernel(
    const float* __restrict__ A, __half* hi, __half* lo, int off, int cnt,
    const float* __restrict__ W, __half* wt, int K, int Nn,
    float* score, int nscore, float* den, int nden)
{
    int i = blockIdx.x * blockDim.x + threadIdx.x;
    if (i < cnt) {
        int j = off + i;
        float v = A[j];
        __half h = __float2half(v);
        hi[j] = h;
        if (lo) lo[j] = __float2half(v - __half2float(h));
    }
    if (i < K * Nn) {
        int n = i / K, k = i - n * K;
        wt[i] = __float2half(W[(size_t)k * Nn + n]);
    }
    if (i < nscore) score[i] = 0.0f;
    if (i < nden) den[i] = 0.0f;
}

// ---------------- side prep ----------------
__global__ void prep_side_kernel(
    const float* __restrict__ W2, __half* wt2,
    const float* __restrict__ W3, __half* wt3,
    float* sc2, float* sc3, int nscore,
    float* dB, float* dC, int nden)
{
    int i = blockIdx.x * blockDim.x + threadIdx.x;
    if (i < 256 * 256) {
        int n = i / 256, k = i - n * 256;
        wt2[i] = __float2half(W2[(size_t)k * 256 + n]);
    }
    if (i < 128 * 256) {
        int n = i / 256, k = i - n * 256;
        wt3[i] = __float2half(W3[(size_t)k * 128 + n]);
    }
    if (i < nscore) { sc2[i] = 0.0f; sc3[i] = 0.0f; }
    if (i < nden) { dB[i] = 0.0f; dC[i] = 0.0f; }
}

// ---------------- CSR build ----------------
__global__ void hist_kernel(const int* __restrict__ row, int* cnt, int e) {
    int i = blockIdx.x * blockDim.x + threadIdx.x;
    if (i < e) atomicAdd(&cnt[row[i]], 1);
}

__global__ void scan_kernel(const int* __restrict__ cnt, int* ptr, int* fill, int n) {
    __shared__ int sh[1024];
    __shared__ int carry;
    if (threadIdx.x == 0) carry = 0;
    __syncthreads();
    for (int base = 0; base < n; base += 1024) {
        int i = base + threadIdx.x;
        int v = (i < n) ? cnt[i] : 0;
        sh[threadIdx.x] = v;
        __syncthreads();
        for (int off = 1; off < 1024; off <<= 1) {
            int t = (threadIdx.x >= off) ? sh[threadIdx.x - off] : 0;
            __syncthreads();
            sh[threadIdx.x] += t;
            __syncthreads();
        }
        int excl = sh[threadIdx.x] - v;
        if (i < n) { ptr[i] = carry + excl; fill[i] = carry + excl; }
        __syncthreads();
        if (threadIdx.x == 1023) carry += sh[1023];
        __syncthreads();
    }
    if (threadIdx.x == 0) ptr[n] = carry;
}

__global__ void scatter_kernel(const int* __restrict__ row, int* fill, int* redges, int e) {
    int i = blockIdx.x * blockDim.x + threadIdx.x;
    if (i < e) {
        int pos = atomicAdd(&fill[row[i]], 1);
        redges[pos] = i;
    }
}

// ===== HMMA fp16 GEMM 128x128 tile + fused attention scores =====
// SPLIT: A = hi+lo 2-term; else single fp16 A.
template <int NN, int KK, bool SPLIT>
__global__ __launch_bounds__(256, 2) void gemm_mma(
    const __half* __restrict__ Ahi, const __half* __restrict__ Alo,
    const __half* __restrict__ Bw,
    __half* __restrict__ C,
    const float* __restrict__ Av, const float* __restrict__ Dv,
    float* __restrict__ Ssrc, float* __restrict__ Sdst,
    int H, int Cc, int M, int moff)
{
    constexpr int BK = 32;
    constexpr int NCH = KK / BK;
    constexpr int STG = SPLIT ? 24576 : 16384;
    constexpr uint32_t BOFF = SPLIT ? 16384u : 8192u;
    extern __shared__ char smem[];
    uint32_t sb = smem_u32(smem);

    int tid = threadIdx.x;
    int lane = tid & 31, wid = tid >> 5;
    int wm = wid & 3, wn = wid >> 2;
    int m0 = (blockIdx.y + moff) * 128;
    int n0 = blockIdx.x * 128;

    int g = lane >> 3, lr = lane & 7;
    uint32_t aoff[2][2];
#pragma unroll
    for (int mt = 0; mt < 2; mt++)
#pragma unroll
        for (int ks = 0; ks < 2; ks++) {
            int row = wm * 32 + mt * 16 + (g & 1) * 8 + lr;
            int unit = ks * 2 + (g >> 1);
            aoff[mt][ks] = SWZ64(row * 64 + unit * 16);
        }
    uint32_t boff[4][2];
#pragma unroll
    for (int np = 0; np < 4; np++)
#pragma unroll
        for (int ks = 0; ks < 2; ks++) {
            int row = wn * 64 + np * 16 + (g >> 1) * 8 + lr;
            int unit = ks * 2 + (g & 1);
            boff[np][ks] = BOFF + SWZ64(row * 64 + unit * 16);
        }

    int r0 = tid >> 2, u0 = tid & 3;
    uint32_t sw0 = SWZ64(r0 * 64 + u0 * 16);
    uint32_t sw1 = SWZ64((r0 + 64) * 64 + u0 * 16);
    long bofs0 = (long)(n0 + r0) * KK + u0 * 8;
    long bofs1 = (long)(n0 + r0 + 64) * KK + u0 * 8;

    float acc[2][8][4];
#pragma unroll
    for (int mt = 0; mt < 2; mt++)
#pragma unroll
        for (int nt = 0; nt < 8; nt++)
#pragma unroll
            for (int j = 0; j < 4; j++) acc[mt][nt][j] = 0.f;

    auto load_stage = [&](int ch, uint32_t so) {
        int k0 = ch * BK;
        {
            int grow = m0 + r0;
            int sz = (grow < M) ? 16 : 0;
            long go = (long)((grow < M) ? grow : 0) * KK + k0 + u0 * 8;
            CPA16(sb + so + sw0, Ahi + go, sz);
            if (SPLIT) CPA16(sb + so + 8192 + sw0, Alo + go, sz);
        }
        {
            int grow = m0 + r0 + 64;
            int sz = (grow < M) ? 16 : 0;
            long go = (long)((grow < M) ? grow : 0) * KK + k0 + u0 * 8;
            CPA16(sb + so + sw1, Ahi + go, sz);
            if (SPLIT) CPA16(sb + so + 8192 + sw1, Alo + go, sz);
        }
        CPA16(sb + so + BOFF + sw0, Bw + bofs0 + k0, 16);
        CPA16(sb + so + BOFF + sw1, Bw + bofs1 + k0, 16);
    };

    auto compute_stage = [&](uint32_t so) {
#pragma unroll
        for (int ks = 0; ks < 2; ks++) {
            uint32_t ah[2][4], al[2][4], b[8][2];
#pragma unroll
            for (int mt = 0; mt < 2; mt++) {
                LDMX4(ah[mt][0], ah[mt][1], ah[mt][2], ah[mt][3], sb + so + aoff[mt][ks]);
                if (SPLIT)
                    LDMX4(al[mt][0], al[mt][1], al[mt][2], al[mt][3], sb + so + 8192 + aoff[mt][ks]);
            }
#pragma unroll
            for (int np = 0; np < 4; np++)
                LDMX4(b[2 * np][0], b[2 * np][1], b[2 * np + 1][0], b[2 * np + 1][1],
                      sb + so + boff[np][ks]);
#pragma unroll
            for (int mt = 0; mt < 2; mt++)
#pragma unroll
                for (int nt = 0; nt < 8; nt++) {
                    mma16816h(acc[mt][nt], ah[mt], b[nt]);
                    if (SPLIT) mma16816h(acc[mt][nt], al[mt], b[nt]);
                }
        }
    };

    load_stage(0, 0);
    CPA_COMMIT();
    load_stage(1, STG);
    CPA_COMMIT();
#pragma unroll 1
    for (int ch = 0; ch < NCH; ch++) {
        uint32_t so = (uint32_t)(ch % 3) * STG;
        if (ch + 1 < NCH) { CPA_WAIT(1); } else { CPA_WAIT(0); }
        __syncthreads();
        if (ch + 2 < NCH) {
            load_stage(ch + 2, (uint32_t)((ch + 2) % 3) * STG);
            CPA_COMMIT();
        }
        compute_stage(so);
    }

    // epilogue 1: fp16 h store
#pragma unroll
    for (int mt = 0; mt < 2; mt++) {
        int m = m0 + wm * 32 + mt * 16 + (lane >> 2);
#pragma unroll
        for (int nt = 0; nt < 8; nt++) {
            int n = n0 + wn * 64 + nt * 8 + (lane & 3) * 2;
            if (m < M)
                *reinterpret_cast<__half2*>(C + (size_t)m * NN + n) =
                    __floats2half2_rn(acc[mt][nt][0], acc[mt][nt][1]);
            if (m + 8 < M)
                *reinterpret_cast<__half2*>(C + (size_t)(m + 8) * NN + n) =
                    __floats2half2_rn(acc[mt][nt][2], acc[mt][nt][3]);
        }
    }

    // epilogue 2: fused attention scores
    {
        int head = (n0 + wn * 64) / Cc;
        float av[16], dv[16];
#pragma unroll
        for (int nt = 0; nt < 8; nt++) {
            int c0 = (n0 + wn * 64 + nt * 8 + (lane & 3) * 2) - head * Cc;
            av[2 * nt] = Av[head * Cc + c0];
            av[2 * nt + 1] = Av[head * Cc + c0 + 1];
            dv[2 * nt] = Dv[head * Cc + c0];
            dv[2 * nt + 1] = Dv[head * Cc + c0 + 1];
        }
#pragma unroll
        for (int mt = 0; mt < 2; mt++) {
            float ps0 = 0.f, pd0 = 0.f, ps1 = 0.f, pd1 = 0.f;
#pragma unroll
            for (int nt = 0; nt < 8; nt++) {
                ps0 += acc[mt][nt][0] * av[2 * nt] + acc[mt][nt][1] * av[2 * nt + 1];
                pd0 += acc[mt][nt][0] * dv[2 * nt] + acc[mt][nt][1] * dv[2 * nt + 1];
                ps1 += acc[mt][nt][2] * av[2 * nt] + acc[mt][nt][3] * av[2 * nt + 1];
                pd1 += acc[mt][nt][2] * dv[2 * nt] + acc[mt][nt][3] * dv[2 * nt + 1];
            }
#pragma unroll
            for (int o = 1; o <= 2; o <<= 1) {
                ps0 += __shfl_xor_sync(0xffffffffu, ps0, o);
                pd0 += __shfl_xor_sync(0xffffffffu, pd0, o);
                ps1 += __shfl_xor_sync(0xffffffffu, ps1, o);
                pd1 += __shfl_xor_sync(0xffffffffu, pd1, o);
            }
            if ((lane & 3) == 0) {
                int m = m0 + wm * 32 + mt * 16 + (lane >> 2);
                if (m < M) {
                    atomicAdd(&Ssrc[m * H + head], ps0);
                    atomicAdd(&Sdst[m * H + head], pd0);
                }
                if (m + 8 < M) {
                    atomicAdd(&Ssrc[(m + 8) * H + head], ps1);
                    atomicAdd(&Sdst[(m + 8) * H + head], pd1);
                }
            }
        }
    }
}

// ---------------- edge scores H=4 ----------------
__global__ void edge_scores4_kernel(
    const int* __restrict__ row, const int* __restrict__ col, const float* __restrict__ ew,
    const float* __restrict__ ssrc, const float* __restrict__ sdst,
    float* __restrict__ aexp, float* __restrict__ denom, int e)
{
    int i = blockIdx.x * blockDim.x + threadIdx.x;
    if (i >= e) return;
    int r = row[i], c = col[i];
    float w = ew[i];
    float4 s4 = *reinterpret_cast<const float4*>(ssrc + (size_t)r * 4);
    float4 d4 = *reinterpret_cast<const float4*>(sdst + (size_t)c * 4);
    float4 o;
    float v;
    v = s4.x + d4.x; v = (v >= 0.f) ? v : NEG_SLOPE * v; o.x = expf(v * w);
    v = s4.y + d4.y; v = (v >= 0.f) ? v : NEG_SLOPE * v; o.y = expf(v * w);
    v = s4.z + d4.z; v = (v >= 0.f) ? v : NEG_SLOPE * v; o.z = expf(v * w);
    v = s4.w + d4.w; v = (v >= 0.f) ? v : NEG_SLOPE * v; o.w = expf(v * w);
    *reinterpret_cast<float4*>(aexp + (size_t)i * 4) = o;
    atomicAdd(&denom[c * 4 + 0], o.x);
    atomicAdd(&denom[c * 4 + 1], o.y);
    atomicAdd(&denom[c * 4 + 2], o.z);
    atomicAdd(&denom[c * 4 + 3], o.w);
}

// ---------------- edge scores H=1 ----------------
__global__ void edge_scores1_kernel(
    const int* __restrict__ row, const int* __restrict__ col, const float* __restrict__ ew,
    const float* __restrict__ ssrc, const float* __restrict__ sdst,
    float* __restrict__ aexp, float* __restrict__ denom, int e)
{
    int i = blockIdx.x * blockDim.x + threadIdx.x;
    if (i >= e) return;
    int r = row[i], c = col[i];
    float v = ssrc[r] + sdst[c];
    v = (v >= 0.f) ? v : NEG_SLOPE * v;
    v = expf(v * ew[i]);
    aexp[i] = v;
    atomicAdd(&denom[c], v);
}

// ---------------- reciprocal of denominators ----------------
__global__ void rdenom_kernel(float* d, int n) {
    int i = blockIdx.x * blockDim.x + threadIdx.x;
    if (i < n) d[i] = 1.0f / (d[i] + EPS_SM);
}

// ===== fused aggregation(D=256,H=4) + bias + LN + ELU + fp16 split, node range =====
__global__ __launch_bounds__(256) void aggln256_kernel(
    const __half* __restrict__ h, const float* __restrict__ aexp, const float* __restrict__ rden,
    const int* __restrict__ col, const int* __restrict__ rptr, const int* __restrict__ redges,
    const float* __restrict__ bias, const float* __restrict__ gam, const float* __restrict__ bet,
    __half* __restrict__ hi, __half* __restrict__ lo, int noff, int nend)
{
    int warp = ((blockIdx.x * blockDim.x + threadIdx.x) >> 5) + noff;
    int lane = threadIdx.x & 31;
    if (warp >= nend) return;
    int hh = lane >> 3;
    float acc[8];
#pragma unroll
    for (int j = 0; j < 8; j++) acc[j] = 0.f;
    int s = rptr[warp], e1 = rptr[warp + 1];
    int i = s;
    for (; i + 1 < e1; i += 2) {
        int ea = redges[i], eb = redges[i + 1];
        int ca = col[ea], cb = col[eb];
        float wa = aexp[(size_t)ea * 4 + hh] * rden[(size_t)ca * 4 + hh];
        float wb = aexp[(size_t)eb * 4 + hh] * rden[(size_t)cb * 4 + hh];
        uint4 ra = *reinterpret_cast<const uint4*>(h + (size_t)ca * 256 + lane * 8);
        uint4 rb = *reinterpret_cast<const uint4*>(h + (size_t)cb * 256 + lane * 8);
        const __half2* pa = reinterpret_cast<const __half2*>(&ra);
        const __half2* pb = reinterpret_cast<const __half2*>(&rb);
#pragma unroll
        for (int j = 0; j < 4; j++) {
            float2 fa = __half22float2(pa[j]);
            float2 fb = __half22float2(pb[j]);
            acc[2 * j]     += wa * fa.x + wb * fb.x;
            acc[2 * j + 1] += wa * fa.y + wb * fb.y;
        }
    }
    if (i < e1) {
        int e = redges[i];
        int c = col[e];
        float w = aexp[(size_t)e * 4 + hh] * rden[(size_t)c * 4 + hh];
        uint4 r = *reinterpret_cast<const uint4*>(h + (size_t)c * 256 + lane * 8);
        const __half2* p = reinterpret_cast<const __half2*>(&r);
#pragma unroll
        for (int j = 0; j < 4; j++) {
            float2 f = __half22float2(p[j]);
            acc[2 * j]     += w * f.x;
            acc[2 * j + 1] += w * f.y;
        }
    }
    const float4* bp = reinterpret_cast<const float4*>(bias + lane * 8);
    float4 b0 = bp[0], b1 = bp[1];
    acc[0] += b0.x; acc[1] += b0.y; acc[2] += b0.z; acc[3] += b0.w;
    acc[4] += b1.x; acc[5] += b1.y; acc[6] += b1.z; acc[7] += b1.w;
    float sum = 0.f, sumsq = 0.f;
#pragma unroll
    for (int j = 0; j < 8; j++) { sum += acc[j]; sumsq += acc[j] * acc[j]; }
#pragma unroll
    for (int o = 16; o; o >>= 1) {
        sum += __shfl_xor_sync(0xffffffffu, sum, o);
        sumsq += __shfl_xor_sync(0xffffffffu, sumsq, o);
    }
    float mu = sum * (1.0f / 256.0f);
    float var = sumsq * (1.0f / 256.0f) - mu * mu;
    float r = rsqrtf(var + EPS_LN);
    const float4* gp = reinterpret_cast<const float4*>(gam + lane * 8);
    const float4* ep = reinterpret_cast<const float4*>(bet + lane * 8);
    float4 g0 = gp[0], g1 = gp[1], e0 = ep[0], e1v = ep[1];
    float gg[8] = {g0.x, g0.y, g0.z, g0.w, g1.x, g1.y, g1.z, g1.w};
    float ee[8] = {e0.x, e0.y, e0.z, e0.w, e1v.x, e1v.y, e1v.z, e1v.w};
    union { __half2 h2[4]; uint4 u; } uh, ul;
#pragma unroll
    for (int j = 0; j < 4; j++) {
        float y0 = (acc[2 * j] - mu) * r * gg[2 * j] + ee[2 * j];
        float y1 = (acc[2 * j + 1] - mu) * r * gg[2 * j + 1] + ee[2 * j + 1];
        y0 = (y0 > 0.f) ? y0 : expm1f(y0);
        y1 = (y1 > 0.f) ? y1 : expm1f(y1);
        __half h0 = __float2half(y0), h1 = __float2half(y1);
        uh.h2[j] = __halves2half2(h0, h1);
        ul.h2[j] = __halves2half2(__float2half(y0 - __half2float(h0)),
                                  __float2half(y1 - __half2float(h1)));
    }
    *reinterpret_cast<uint4*>(hi + (size_t)warp * 256 + lane * 8) = uh.u;
    *reinterpret_cast<uint4*>(lo + (size_t)warp * 256 + lane * 8) = ul.u;
}

// ===== fused aggregation(D=128,H=1) + bias + final LN -> fp32 out =====
__global__ __launch_bounds__(256) void aggln128_kernel(
    const __half* __restrict__ h, const float* __restrict__ aexp, const float* __restrict__ rden,
    const int* __restrict__ col, const int* __restrict__ rptr, const int* __restrict__ redges,
    const float* __restrict__ bias, const float* __restrict__ gam, const float* __restrict__ bet,
    float* __restrict__ out, int n)
{
    int warp = (blockIdx.x * blockDim.x + threadIdx.x) >> 5;
    int lane = threadIdx.x & 31;
    if (warp >= n) return;
    float acc[4];
#pragma unroll
    for (int j = 0; j < 4; j++) acc[j] = 0.f;
    int s = rptr[warp], e1 = rptr[warp + 1];
    int i = s;
    for (; i + 1 < e1; i += 2) {
        int ea = redges[i], eb = redges[i + 1];
        int ca = col[ea], cb = col[eb];
        float wa = aexp[ea] * rden[ca];
        float wb = aexp[eb] * rden[cb];
        uint2 ra = *reinterpret_cast<const uint2*>(h + (size_t)ca * 128 + lane * 4);
        uint2 rb = *reinterpret_cast<const uint2*>(h + (size_t)cb * 128 + lane * 4);
        const __half2* pa = reinterpret_cast<const __half2*>(&ra);
        const __half2* pb = reinterpret_cast<const __half2*>(&rb);
#pragma unroll
        for (int j = 0; j < 2; j++) {
            float2 fa = __half22float2(pa[j]);
            float2 fb = __half22float2(pb[j]);
            acc[2 * j]     += wa * fa.x + wb * fb.x;
            acc[2 * j + 1] += wa * fa.y + wb * fb.y;
        }
    }
    if (i < e1) {
        int e = redges[i];
        int c = col[e];
        float w = aexp[e] * rden[c];
        uint2 r = *reinterpret_cast<const uint2*>(h + (size_t)c * 128 + lane * 4);
        const __half2* p = reinterpret_cast<const __half2*>(&r);
#pragma unroll
        for (int j = 0; j < 2; j++) {
            float2 f = __half22float2(p[j]);
            acc[2 * j]     += w * f.x;
            acc[2 * j + 1] += w * f.y;
        }
    }
    float4 b0 = *reinterpret_cast<const float4*>(bias + lane * 4);
    acc[0] += b0.x; acc[1] += b0.y; acc[2] += b0.z; acc[3] += b0.w;
    float sum = 0.f, sumsq = 0.f;
#pragma unroll
    for (int j = 0; j < 4; j++) { sum += acc[j]; sumsq += acc[j] * acc[j]; }
#pragma unroll
    for (int o = 16; o; o >>= 1) {
        sum += __shfl_xor_sync(0xffffffffu, sum, o);
        sumsq += __shfl_xor_sync(0xffffffffu, sumsq, o);
    }
    float mu = sum * (1.0f / 128.0f);
    float var = sumsq * (1.0f / 128.0f) - mu * mu;
    float r = rsqrtf(var + EPS_LN);
    float4 g0 = *reinterpret_cast<const float4*>(gam + lane * 4);
    float4 e0 = *reinterpret_cast<const float4*>(bet + lane * 4);
    float4 o0 = make_float4((acc[0] - mu) * r * g0.x + e0.x,
                            (acc[1] - mu) * r * g0.y + e0.y,
                            (acc[2] - mu) * r * g0.z + e0.z,
                            (acc[3] - mu) * r * g0.w + e0.w);
    *reinterpret_cast<float4*>(out + (size_t)warp * 128 + lane * 4) = o0;
}

// ---------------- host orchestration ----------------
static inline int ceil_div(int a, int b) { return (a + b - 1) / b; }

extern "C" void kernel_launch(void* const* d_in, const int* in_sizes, int n_in,
                              void* d_out, int out_size) {
    const float* x   = (const float*)d_in[0];
    const int*   ei  = (const int*)d_in[1];
    const float* ew  = (const float*)d_in[2];
    const float* W1  = (const float*)d_in[3];
    const float* as1 = (const float*)d_in[4];
    const float* ad1 = (const float*)d_in[5];
    const float* b1  = (const float*)d_in[6];
    const float* g1  = (const float*)d_in[7];
    const float* be1 = (const float*)d_in[8];
    const float* W2  = (const float*)d_in[9];
    const float* as2 = (const float*)d_in[10];
    const float* ad2 = (const float*)d_in[11];
    const float* b2  = (const float*)d_in[12];
    const float* g2  = (const float*)d_in[13];
    const float* be2 = (const float*)d_in[14];
    const float* W3  = (const float*)d_in[15];
    const float* as3 = (const float*)d_in[16];
    const float* ad3 = (const float*)d_in[17];
    const float* b3  = (const float*)d_in[18];
    const float* g3  = (const float*)d_in[19];
    const float* be3 = (const float*)d_in[20];
    float* out = (float*)d_out;

    const int* row = ei;
    const int* col = ei + NEDGE;

    float *alpha, *denomA, *denomB, *denomC, *score1, *score2, *score3;
    int *cnt, *rptr, *fill, *redges;
    __half *h16, *ahi, *alo, *wt1, *wt2, *wt3;
    cudaGetSymbolAddress((void**)&h16, g_h16);
    cudaGetSymbolAddress((void**)&alpha, g_alpha);
    cudaGetSymbolAddress((void**)&denomA, g_denomA);
    cudaGetSymbolAddress((void**)&denomB, g_denomB);
    cudaGetSymbolAddress((void**)&denomC, g_denomC);
    cudaGetSymbolAddress((void**)&score1, g_score1);
    cudaGetSymbolAddress((void**)&score2, g_score2);
    cudaGetSymbolAddress((void**)&score3, g_score3);
    cudaGetSymbolAddress((void**)&cnt, g_cnt);
    cudaGetSymbolAddress((void**)&rptr, g_rptr);
    cudaGetSymbolAddress((void**)&fill, g_fill);
    cudaGetSymbolAddress((void**)&redges, g_redges);
    cudaGetSymbolAddress((void**)&ahi, g_ahi);
    cudaGetSymbolAddress((void**)&alo, g_alo);
    cudaGetSymbolAddress((void**)&wt1, g_wt1);
    cudaGetSymbolAddress((void**)&wt2, g_wt2);
    cudaGetSymbolAddress((void**)&wt3, g_wt3);

    const int TB = 256;
    const int eb = ceil_div(NEDGE, TB);
    const int mtA = NSPLIT / 128;
    const int mtB = ceil_div(NNODE, 128) - mtA;
    const int SMEM1 = 3 * 16384;   // layer1: no A-lo
    const int SMEM2 = 3 * 24576;

    cudaFuncSetAttribute(gemm_mma<256, 384, false>, cudaFuncAttributeMaxDynamicSharedMemorySize, SMEM1);
    cudaFuncSetAttribute(gemm_mma<256, 256, true>, cudaFuncAttributeMaxDynamicSharedMemorySize, SMEM2);
    cudaFuncSetAttribute(gemm_mma<128, 256, true>, cudaFuncAttributeMaxDynamicSharedMemorySize, SMEM2);

    static cudaStream_t s1 = nullptr, s2 = nullptr;
    static cudaEvent_t ev0 = nullptr, evS2 = nullptr;
    static cudaEvent_t evR1 = nullptr, evR2 = nullptr;
    static cudaEvent_t evG1B = nullptr, evG2B = nullptr, evG3B = nullptr;
    if (!s1) {
        cudaStreamCreateWithFlags(&s1, cudaStreamNonBlocking);
        cudaStreamCreateWithFlags(&s2, cudaStreamNonBlocking);
        cudaEventCreateWithFlags(&ev0, cudaEventDisableTiming);
        cudaEventCreateWithFlags(&evS2, cudaEventDisableTiming);
        cudaEventCreateWithFlags(&evR1, cudaEventDisableTiming);
        cudaEventCreateWithFlags(&evR2, cudaEventDisableTiming);
        cudaEventCreateWithFlags(&evG1B, cudaEventDisableTiming);
        cudaEventCreateWithFlags(&evG2B, cudaEventDisableTiming);
        cudaEventCreateWithFlags(&evG3B, cudaEventDisableTiming);
    }

    // ---- fork ----
    cudaEventRecord(ev0, 0);
    cudaStreamWaitEvent(s1, ev0, 0);
    cudaStreamWaitEvent(s2, ev0, 0);

    // s2: CSR build + side prep
    zero_i<<<ceil_div(NNODE, TB), TB, 0, s2>>>(cnt, NNODE);
    hist_kernel<<<eb, TB, 0, s2>>>(row, cnt, NEDGE);
    scan_kernel<<<1, 1024, 0, s2>>>(cnt, rptr, fill, NNODE);
    scatter_kernel<<<eb, TB, 0, s2>>>(row, fill, redges, NEDGE);
    prep_side_kernel<<<ceil_div(NNODE * 8, TB), TB, 0, s2>>>(
        W2, wt2, W3, wt3, score2, score3, NNODE * 8, denomB, denomC, NNODE * 4);
    cudaEventRecord(evS2, s2);

    // ===== Layer 1 front, half-pipelined (A single fp16) =====
    const int splitElems = NSPLIT * 384;
    asplit_fused_kernel<<<ceil_div(NNODE * 384, TB), TB>>>(
        x, ahi, nullptr, 0, splitElems, W1, wt1, 384, 256,
        score1, NNODE * 8, denomA, NNODE * 4);
    gemm_mma<256, 384, false><<<dim3(2, mtA), 256, SMEM1>>>(
        ahi, nullptr, wt1, h16, as1, ad1, score1, score1 + NNODE * 4, 4, 64, NNODE, 0);
    asplit_fused_kernel<<<ceil_div(NNODE * 384 - splitElems, TB), TB, 0, s1>>>(
        x, ahi, nullptr, splitElems, NNODE * 384 - splitElems, W1, wt1, 0, 0,
        nullptr, 0, nullptr, 0);
    gemm_mma<256, 384, false><<<dim3(2, mtB), 256, SMEM1, s1>>>(
        ahi, nullptr, wt1, h16, as1, ad1, score1, score1 + NNODE * 4, 4, 64, NNODE, mtA);
    cudaEventRecord(evG1B, s1);
    cudaStreamWaitEvent(0, evG1B, 0);

    edge_scores4_kernel<<<eb, TB>>>(row, col, ew, score1, score1 + NNODE * 4, alpha, denomA, NEDGE);
    rdenom_kernel<<<ceil_div(NNODE * 4, TB), TB>>>(denomA, NNODE * 4);
    cudaEventRecord(evR1, 0);
    cudaStreamWaitEvent(0, evS2, 0);
    cudaStreamWaitEvent(s1, evS2, 0);
    cudaStreamWaitEvent(s1, evR1, 0);

    // ===== aggln1 / gemm2 half-pipelined =====
    aggln256_kernel<<<ceil_div(NSPLIT * 32, TB), TB>>>(
        h16, alpha, denomA, col, rptr, redges, b1, g1, be1, ahi, alo, 0, NSPLIT);
    gemm_mma<256, 256, true><<<dim3(2, mtA), 256, SMEM2>>>(
        ahi, alo, wt2, h16, as2, ad2, score2, score2 + NNODE * 4, 4, 64, NNODE, 0);
    aggln256_kernel<<<ceil_div((NNODE - NSPLIT) * 32, TB), TB, 0, s1>>>(
        h16, alpha, denomA, col, rptr, redges, b1, g1, be1, ahi, alo, NSPLIT, NNODE);
    gemm_mma<256, 256, true><<<dim3(2, mtB), 256, SMEM2, s1>>>(
        ahi, alo, wt2, h16, as2, ad2, score2, score2 + NNODE * 4, 4, 64, NNODE, mtA);
    cudaEventRecord(evG2B, s1);
    cudaStreamWaitEvent(0, evG2B, 0);

    edge_scores4_kernel<<<eb, TB>>>(row, col, ew, score2, score2 + NNODE * 4, alpha, denomB, NEDGE);
    rdenom_kernel<<<ceil_div(NNODE * 4, TB), TB>>>(denomB, NNODE * 4);
    cudaEventRecord(evR2, 0);
    cudaStreamWaitEvent(s1, evR2, 0);

    // ===== aggln2 / gemm3 half-pipelined =====
    aggln256_kernel<<<ceil_div(NSPLIT * 32, TB), TB>>>(
        h16, alpha, denomB, col, rptr, redges, b2, g2, be2, ahi, alo, 0, NSPLIT);
    gemm_mma<128, 256, true><<<dim3(1, mtA), 256, SMEM2>>>(
        ahi, alo, wt3, h16, as3, ad3, score3, score3 + NNODE * 4, 1, 128, NNODE, 0);
    aggln256_kernel<<<ceil_div((NNODE - NSPLIT) * 32, TB), TB, 0, s1>>>(
        h16, alpha, denomB, col, rptr, redges, b2, g2, be2, ahi, alo, NSPLIT, NNODE);
    gemm_mma<128, 256, true><<<dim3(1, mtB), 256, SMEM2, s1>>>(
        ahi, alo, wt3, h16, as3, ad3, score3, score3 + NNODE * 4, 1, 128, NNODE, mtA);
    cudaEventRecord(evG3B, s1);
    cudaStreamWaitEvent(0, evG3B, 0);

    // ===== Layer 3 tail =====
    edge_scores1_kernel<<<eb, TB>>>(row, col, ew, score3, score3 + NNODE * 4, alpha, denomC, NEDGE);
    rdenom_kernel<<<ceil_div(NNODE, TB), TB>>>(denomC, NNODE);
    aggln128_kernel<<<ceil_div(NNODE * 32, TB), TB>>>(
        h16, alpha, denomC, col, rptr, redges, b3, g3, be3, out, NNODE);
}

// round 15
// speedup vs baseline: 1.2842x; 1.0581x over previous
#include <cuda_runtime.h>
#include <cuda_fp16.h>
#include <math.h>
#include <stdint.h>

#define NNODE 50000
#define NEDGE 500000
#define DMAX  256
#define EPS_SM 1e-16f
#define EPS_LN 1e-5f
#define NEG_SLOPE 0.2f
#define NSPLIT 25088            // 196 * 128

// ---------------- scratch (device globals) ----------------
__device__ __half g_h16[NNODE * DMAX];
__device__ float g_alpha[NEDGE * 4];
__device__ float g_denomA[NNODE * 4];
__device__ float g_denomB[NNODE * 4];
__device__ float g_denomC[NNODE * 4];
__device__ float g_score1[NNODE * 8];
__device__ float g_score2[NNODE * 8];
__device__ float g_score3[NNODE * 8];
__device__ int   g_cnt[NNODE];
__device__ int   g_rptr[NNODE + 1];
__device__ int   g_fill[NNODE];
__device__ int   g_redges[NEDGE];
__device__ __half g_ahi[NNODE * 384];
__device__ __half g_wt1[256 * 384];
__device__ __half g_wt2[256 * 256];
__device__ __half g_wt3[128 * 256];

// ================= PTX helpers =================
__device__ __forceinline__ uint32_t smem_u32(const void* p) {
    uint32_t a;
    asm("{ .reg .u64 t; cvta.to.shared.u64 t, %1; cvt.u32.u64 %0, t; }" : "=r"(a) : "l"(p));
    return a;
}

#define CPA16(dst, src, sz) \
    asm volatile("cp.async.cg.shared.global [%0], [%1], 16, %2;" \
                 :: "r"(dst), "l"(src), "r"(sz))
#define CPA_COMMIT() asm volatile("cp.async.commit_group;" ::: "memory")
#define CPA_WAIT(n)  asm volatile("cp.async.wait_group %0;" :: "n"(n) : "memory")

#define LDMX4(r0, r1, r2, r3, addr) \
    asm volatile("ldmatrix.sync.aligned.m8n8.x4.shared.b16 {%0,%1,%2,%3}, [%4];" \
                 : "=r"(r0), "=r"(r1), "=r"(r2), "=r"(r3) : "r"(addr))

__device__ __forceinline__ void mma16816h(float* c, const uint32_t* a, const uint32_t* b) {
    asm volatile(
        "mma.sync.aligned.m16n8k16.row.col.f32.f16.f16.f32 "
        "{%0,%1,%2,%3}, {%4,%5,%6,%7}, {%8,%9}, {%0,%1,%2,%3};"
        : "+f"(c[0]), "+f"(c[1]), "+f"(c[2]), "+f"(c[3])
        : "r"(a[0]), "r"(a[1]), "r"(a[2]), "r"(a[3]), "r"(b[0]), "r"(b[1]));
}

#define SWZ64(b) ((b) ^ (((b) >> 3) & 0x30))

// ---------------- small utility ----------------
__global__ void zero_i(int* p, int n) {
    int i = blockIdx.x * blockDim.x + threadIdx.x;
    if (i < n) p[i] = 0;
}

// ---------------- activation convert fp16 + optional prep ----------------
__global__ void asplit_fused_kernel(
    const float* __restrict__ A, __half* hi, int off, int cnt,
    const float* __restrict__ W, __half* wt, int K, int Nn,
    float* score, int nscore, float* den, int nden)
{
    int i = blockIdx.x * blockDim.x + threadIdx.x;
    if (i < cnt) {
        int j = off + i;
        hi[j] = __float2half(A[j]);
    }
    if (i < K * Nn) {
        int n = i / K, k = i - n * K;
        wt[i] = __float2half(W[(size_t)k * Nn + n]);
    }
    if (i < nscore) score[i] = 0.0f;
    if (i < nden) den[i] = 0.0f;
}

// ---------------- side prep ----------------
__global__ void prep_side_kernel(
    const float* __restrict__ W2, __half* wt2,
    const float* __restrict__ W3, __half* wt3,
    float* sc2, float* sc3, int nscore,
    float* dB, float* dC, int nden)
{
    int i = blockIdx.x * blockDim.x + threadIdx.x;
    if (i < 256 * 256) {
        int n = i / 256, k = i - n * 256;
        wt2[i] = __float2half(W2[(size_t)k * 256 + n]);
    }
    if (i < 128 * 256) {
        int n = i / 256, k = i - n * 256;
        wt3[i] = __float2half(W3[(size_t)k * 128 + n]);
    }
    if (i < nscore) { sc2[i] = 0.0f; sc3[i] = 0.0f; }
    if (i < nden) { dB[i] = 0.0f; dC[i] = 0.0f; }
}

// ---------------- CSR build ----------------
__global__ void hist_kernel(const int* __restrict__ row, int* cnt, int e) {
    int i = blockIdx.x * blockDim.x + threadIdx.x;
    if (i < e) atomicAdd(&cnt[row[i]], 1);
}

__global__ void scan_kernel(const int* __restrict__ cnt, int* ptr, int* fill, int n) {
    __shared__ int sh[1024];
    __shared__ int carry;
    if (threadIdx.x == 0) carry = 0;
    __syncthreads();
    for (int base = 0; base < n; base += 1024) {
        int i = base + threadIdx.x;
        int v = (i < n) ? cnt[i] : 0;
        sh[threadIdx.x] = v;
        __syncthreads();
        for (int off = 1; off < 1024; off <<= 1) {
            int t = (threadIdx.x >= off) ? sh[threadIdx.x - off] : 0;
            __syncthreads();
            sh[threadIdx.x] += t;
            __syncthreads();
        }
        int excl = sh[threadIdx.x] - v;
        if (i < n) { ptr[i] = carry + excl; fill[i] = carry + excl; }
        __syncthreads();
        if (threadIdx.x == 1023) carry += sh[1023];
        __syncthreads();
    }
    if (threadIdx.x == 0) ptr[n] = carry;
}

__global__ void scatter_kernel(const int* __restrict__ row, int* fill, int* redges, int e) {
    int i = blockIdx.x * blockDim.x + threadIdx.x;
    if (i < e) {
        int pos = atomicAdd(&fill[row[i]], 1);
        redges[pos] = i;
    }
}

// ===== HMMA fp16 GEMM 128x128 tile + fused attention scores (single-term A) =====
template <int NN, int KK>
__global__ __launch_bounds__(256, 2) void gemm_mma(
    const __half* __restrict__ Ahi,
    const __half* __restrict__ Bw,
    __half* __restrict__ C,
    const float* __restrict__ Av, const float* __restrict__ Dv,
    float* __restrict__ Ssrc, float* __restrict__ Sdst,
    int H, int Cc, int M, int moff)
{
    constexpr int BK = 32;
    constexpr int NCH = KK / BK;
    constexpr int STG = 16384;   // A 8K | B 8K
    extern __shared__ char smem[];
    uint32_t sb = smem_u32(smem);

    int tid = threadIdx.x;
    int lane = tid & 31, wid = tid >> 5;
    int wm = wid & 3, wn = wid >> 2;
    int m0 = (blockIdx.y + moff) * 128;
    int n0 = blockIdx.x * 128;

    int g = lane >> 3, lr = lane & 7;
    uint32_t aoff[2][2];
#pragma unroll
    for (int mt = 0; mt < 2; mt++)
#pragma unroll
        for (int ks = 0; ks < 2; ks++) {
            int row = wm * 32 + mt * 16 + (g & 1) * 8 + lr;
            int unit = ks * 2 + (g >> 1);
            aoff[mt][ks] = SWZ64(row * 64 + unit * 16);
        }
    uint32_t boff[4][2];
#pragma unroll
    for (int np = 0; np < 4; np++)
#pragma unroll
        for (int ks = 0; ks < 2; ks++) {
            int row = wn * 64 + np * 16 + (g >> 1) * 8 + lr;
            int unit = ks * 2 + (g & 1);
            boff[np][ks] = 8192u + SWZ64(row * 64 + unit * 16);
        }

    int r0 = tid >> 2, u0 = tid & 3;
    uint32_t sw0 = SWZ64(r0 * 64 + u0 * 16);
    uint32_t sw1 = SWZ64((r0 + 64) * 64 + u0 * 16);
    long bofs0 = (long)(n0 + r0) * KK + u0 * 8;
    long bofs1 = (long)(n0 + r0 + 64) * KK + u0 * 8;

    float acc[2][8][4];
#pragma unroll
    for (int mt = 0; mt < 2; mt++)
#pragma unroll
        for (int nt = 0; nt < 8; nt++)
#pragma unroll
            for (int j = 0; j < 4; j++) acc[mt][nt][j] = 0.f;

    auto load_stage = [&](int ch, uint32_t so) {
        int k0 = ch * BK;
        {
            int grow = m0 + r0;
            int sz = (grow < M) ? 16 : 0;
            long go = (long)((grow < M) ? grow : 0) * KK + k0 + u0 * 8;
            CPA16(sb + so + sw0, Ahi + go, sz);
        }
        {
            int grow = m0 + r0 + 64;
            int sz = (grow < M) ? 16 : 0;
            long go = (long)((grow < M) ? grow : 0) * KK + k0 + u0 * 8;
            CPA16(sb + so + sw1, Ahi + go, sz);
        }
        CPA16(sb + so + 8192 + sw0, Bw + bofs0 + k0, 16);
        CPA16(sb + so + 8192 + sw1, Bw + bofs1 + k0, 16);
    };

    auto compute_stage = [&](uint32_t so) {
#pragma unroll
        for (int ks = 0; ks < 2; ks++) {
            uint32_t ah[2][4], b[8][2];
#pragma unroll
            for (int mt = 0; mt < 2; mt++)
                LDMX4(ah[mt][0], ah[mt][1], ah[mt][2], ah[mt][3], sb + so + aoff[mt][ks]);
#pragma unroll
            for (int np = 0; np < 4; np++)
                LDMX4(b[2 * np][0], b[2 * np][1], b[2 * np + 1][0], b[2 * np + 1][1],
                      sb + so + boff[np][ks]);
#pragma unroll
            for (int mt = 0; mt < 2; mt++)
#pragma unroll
                for (int nt = 0; nt < 8; nt++)
                    mma16816h(acc[mt][nt], ah[mt], b[nt]);
        }
    };

    load_stage(0, 0);
    CPA_COMMIT();
    load_stage(1, STG);
    CPA_COMMIT();
#pragma unroll 1
    for (int ch = 0; ch < NCH; ch++) {
        uint32_t so = (uint32_t)(ch % 3) * STG;
        if (ch + 1 < NCH) { CPA_WAIT(1); } else { CPA_WAIT(0); }
        __syncthreads();
        if (ch + 2 < NCH) {
            load_stage(ch + 2, (uint32_t)((ch + 2) % 3) * STG);
            CPA_COMMIT();
        }
        compute_stage(so);
    }

    // epilogue 1: fp16 h store
#pragma unroll
    for (int mt = 0; mt < 2; mt++) {
        int m = m0 + wm * 32 + mt * 16 + (lane >> 2);
#pragma unroll
        for (int nt = 0; nt < 8; nt++) {
            int n = n0 + wn * 64 + nt * 8 + (lane & 3) * 2;
            if (m < M)
                *reinterpret_cast<__half2*>(C + (size_t)m * NN + n) =
                    __floats2half2_rn(acc[mt][nt][0], acc[mt][nt][1]);
            if (m + 8 < M)
                *reinterpret_cast<__half2*>(C + (size_t)(m + 8) * NN + n) =
                    __floats2half2_rn(acc[mt][nt][2], acc[mt][nt][3]);
        }
    }

    // epilogue 2: fused attention scores
    {
        int head = (n0 + wn * 64) / Cc;
        float av[16], dv[16];
#pragma unroll
        for (int nt = 0; nt < 8; nt++) {
            int c0 = (n0 + wn * 64 + nt * 8 + (lane & 3) * 2) - head * Cc;
            av[2 * nt] = Av[head * Cc + c0];
            av[2 * nt + 1] = Av[head * Cc + c0 + 1];
            dv[2 * nt] = Dv[head * Cc + c0];
            dv[2 * nt + 1] = Dv[head * Cc + c0 + 1];
        }
#pragma unroll
        for (int mt = 0; mt < 2; mt++) {
            float ps0 = 0.f, pd0 = 0.f, ps1 = 0.f, pd1 = 0.f;
#pragma unroll
            for (int nt = 0; nt < 8; nt++) {
                ps0 += acc[mt][nt][0] * av[2 * nt] + acc[mt][nt][1] * av[2 * nt + 1];
                pd0 += acc[mt][nt][0] * dv[2 * nt] + acc[mt][nt][1] * dv[2 * nt + 1];
                ps1 += acc[mt][nt][2] * av[2 * nt] + acc[mt][nt][3] * av[2 * nt + 1];
                pd1 += acc[mt][nt][2] * dv[2 * nt] + acc[mt][nt][3] * dv[2 * nt + 1];
            }
#pragma unroll
            for (int o = 1; o <= 2; o <<= 1) {
                ps0 += __shfl_xor_sync(0xffffffffu, ps0, o);
                pd0 += __shfl_xor_sync(0xffffffffu, pd0, o);
                ps1 += __shfl_xor_sync(0xffffffffu, ps1, o);
                pd1 += __shfl_xor_sync(0xffffffffu, pd1, o);
            }
            if ((lane & 3) == 0) {
                int m = m0 + wm * 32 + mt * 16 + (lane >> 2);
                if (m < M) {
                    atomicAdd(&Ssrc[m * H + head], ps0);
                    atomicAdd(&Sdst[m * H + head], pd0);
                }
                if (m + 8 < M) {
                    atomicAdd(&Ssrc[(m + 8) * H + head], ps1);
                    atomicAdd(&Sdst[(m + 8) * H + head], pd1);
                }
            }
        }
    }
}

// ---------------- edge scores H=4 ----------------
__global__ void edge_scores4_kernel(
    const int* __restrict__ row, const int* __restrict__ col, const float* __restrict__ ew,
    const float* __restrict__ ssrc, const float* __restrict__ sdst,
    float* __restrict__ aexp, float* __restrict__ denom, int e)
{
    int i = blockIdx.x * blockDim.x + threadIdx.x;
    if (i >= e) return;
    int r = row[i], c = col[i];
    float w = ew[i];
    float4 s4 = *reinterpret_cast<const float4*>(ssrc + (size_t)r * 4);
    float4 d4 = *reinterpret_cast<const float4*>(sdst + (size_t)c * 4);
    float4 o;
    float v;
    v = s4.x + d4.x; v = (v >= 0.f) ? v : NEG_SLOPE * v; o.x = expf(v * w);
    v = s4.y + d4.y; v = (v >= 0.f) ? v : NEG_SLOPE * v; o.y = expf(v * w);
    v = s4.z + d4.z; v = (v >= 0.f) ? v : NEG_SLOPE * v; o.z = expf(v * w);
    v = s4.w + d4.w; v = (v >= 0.f) ? v : NEG_SLOPE * v; o.w = expf(v * w);
    *reinterpret_cast<float4*>(aexp + (size_t)i * 4) = o;
    atomicAdd(&denom[c * 4 + 0], o.x);
    atomicAdd(&denom[c * 4 + 1], o.y);
    atomicAdd(&denom[c * 4 + 2], o.z);
    atomicAdd(&denom[c * 4 + 3], o.w);
}

// ---------------- edge scores H=1 ----------------
__global__ void edge_scores1_kernel(
    const int* __restrict__ row, const int* __restrict__ col, const float* __restrict__ ew,
    const float* __restrict__ ssrc, const float* __restrict__ sdst,
    float* __restrict__ aexp, float* __restrict__ denom, int e)
{
    int i = blockIdx.x * blockDim.x + threadIdx.x;
    if (i >= e) return;
    int r = row[i], c = col[i];
    float v = ssrc[r] + sdst[c];
    v = (v >= 0.f) ? v : NEG_SLOPE * v;
    v = expf(v * ew[i]);
    aexp[i] = v;
    atomicAdd(&denom[c], v);
}

// ---------------- reciprocal of denominators ----------------
__global__ void rdenom_kernel(float* d, int n) {
    int i = blockIdx.x * blockDim.x + threadIdx.x;
    if (i < n) d[i] = 1.0f / (d[i] + EPS_SM);
}

// ===== fused aggregation(D=256,H=4) + bias + LN + ELU -> fp16, node range =====
__global__ __launch_bounds__(256) void aggln256_kernel(
    const __half* __restrict__ h, const float* __restrict__ aexp, const float* __restrict__ rden,
    const int* __restrict__ col, const int* __restrict__ rptr, const int* __restrict__ redges,
    const float* __restrict__ bias, const float* __restrict__ gam, const float* __restrict__ bet,
    __half* __restrict__ hi, int noff, int nend)
{
    int warp = ((blockIdx.x * blockDim.x + threadIdx.x) >> 5) + noff;
    int lane = threadIdx.x & 31;
    if (warp >= nend) return;
    int hh = lane >> 3;
    float acc[8];
#pragma unroll
    for (int j = 0; j < 8; j++) acc[j] = 0.f;
    int s = rptr[warp], e1 = rptr[warp + 1];
    int i = s;
    for (; i + 1 < e1; i += 2) {
        int ea = redges[i], eb = redges[i + 1];
        int ca = col[ea], cb = col[eb];
        float wa = aexp[(size_t)ea * 4 + hh] * rden[(size_t)ca * 4 + hh];
        float wb = aexp[(size_t)eb * 4 + hh] * rden[(size_t)cb * 4 + hh];
        uint4 ra = *reinterpret_cast<const uint4*>(h + (size_t)ca * 256 + lane * 8);
        uint4 rb = *reinterpret_cast<const uint4*>(h + (size_t)cb * 256 + lane * 8);
        const __half2* pa = reinterpret_cast<const __half2*>(&ra);
        const __half2* pb = reinterpret_cast<const __half2*>(&rb);
#pragma unroll
        for (int j = 0; j < 4; j++) {
            float2 fa = __half22float2(pa[j]);
            float2 fb = __half22float2(pb[j]);
            acc[2 * j]     += wa * fa.x + wb * fb.x;
            acc[2 * j + 1] += wa * fa.y + wb * fb.y;
        }
    }
    if (i < e1) {
        int e = redges[i];
        int c = col[e];
        float w = aexp[(size_t)e * 4 + hh] * rden[(size_t)c * 4 + hh];
        uint4 r = *reinterpret_cast<const uint4*>(h + (size_t)c * 256 + lane * 8);
        const __half2* p = reinterpret_cast<const __half2*>(&r);
#pragma unroll
        for (int j = 0; j < 4; j++) {
            float2 f = __half22float2(p[j]);
            acc[2 * j]     += w * f.x;
            acc[2 * j + 1] += w * f.y;
        }
    }
    const float4* bp = reinterpret_cast<const float4*>(bias + lane * 8);
    float4 b0 = bp[0], b1 = bp[1];
    acc[0] += b0.x; acc[1] += b0.y; acc[2] += b0.z; acc[3] += b0.w;
    acc[4] += b1.x; acc[5] += b1.y; acc[6] += b1.z; acc[7] += b1.w;
    float sum = 0.f, sumsq = 0.f;
#pragma unroll
    for (int j = 0; j < 8; j++) { sum += acc[j]; sumsq += acc[j] * acc[j]; }
#pragma unroll
    for (int o = 16; o; o >>= 1) {
        sum += __shfl_xor_sync(0xffffffffu, sum, o);
        sumsq += __shfl_xor_sync(0xffffffffu, sumsq, o);
    }
    float mu = sum * (1.0f / 256.0f);
    float var = sumsq * (1.0f / 256.0f) - mu * mu;
    float r = rsqrtf(var + EPS_LN);
    const float4* gp = reinterpret_cast<const float4*>(gam + lane * 8);
    const float4* ep = reinterpret_cast<const float4*>(bet + lane * 8);
    float4 g0 = gp[0], g1 = gp[1], e0 = ep[0], e1v = ep[1];
    float gg[8] = {g0.x, g0.y, g0.z, g0.w, g1.x, g1.y, g1.z, g1.w};
    float ee[8] = {e0.x, e0.y, e0.z, e0.w, e1v.x, e1v.y, e1v.z, e1v.w};
    union { __half2 h2[4]; uint4 u; } uh;
#pragma unroll
    for (int j = 0; j < 4; j++) {
        float y0 = (acc[2 * j] - mu) * r * gg[2 * j] + ee[2 * j];
        float y1 = (acc[2 * j + 1] - mu) * r * gg[2 * j + 1] + ee[2 * j + 1];
        y0 = (y0 > 0.f) ? y0 : expm1f(y0);
        y1 = (y1 > 0.f) ? y1 : expm1f(y1);
        uh.h2[j] = __halves2half2(__float2half(y0), __float2half(y1));
    }
    *reinterpret_cast<uint4*>(hi + (size_t)warp * 256 + lane * 8) = uh.u;
}

// ===== fused aggregation(D=128,H=1) + bias + final LN -> fp32 out =====
__global__ __launch_bounds__(256) void aggln128_kernel(
    const __half* __restrict__ h, const float* __restrict__ aexp, const float* __restrict__ rden,
    const int* __restrict__ col, const int* __restrict__ rptr, const int* __restrict__ redges,
    const float* __restrict__ bias, const float* __restrict__ gam, const float* __restrict__ bet,
    float* __restrict__ out, int n)
{
    int warp = (blockIdx.x * blockDim.x + threadIdx.x) >> 5;
    int lane = threadIdx.x & 31;
    if (warp >= n) return;
    float acc[4];
#pragma unroll
    for (int j = 0; j < 4; j++) acc[j] = 0.f;
    int s = rptr[warp], e1 = rptr[warp + 1];
    int i = s;
    for (; i + 1 < e1; i += 2) {
        int ea = redges[i], eb = redges[i + 1];
        int ca = col[ea], cb = col[eb];
        float wa = aexp[ea] * rden[ca];
        float wb = aexp[eb] * rden[cb];
        uint2 ra = *reinterpret_cast<const uint2*>(h + (size_t)ca * 128 + lane * 4);
        uint2 rb = *reinterpret_cast<const uint2*>(h + (size_t)cb * 128 + lane * 4);
        const __half2* pa = reinterpret_cast<const __half2*>(&ra);
        const __half2* pb = reinterpret_cast<const __half2*>(&rb);
#pragma unroll
        for (int j = 0; j < 2; j++) {
            float2 fa = __half22float2(pa[j]);
            float2 fb = __half22float2(pb[j]);
            acc[2 * j]     += wa * fa.x + wb * fb.x;
            acc[2 * j + 1] += wa * fa.y + wb * fb.y;
        }
    }
    if (i < e1) {
        int e = redges[i];
        int c = col[e];
        float w = aexp[e] * rden[c];
        uint2 r = *reinterpret_cast<const uint2*>(h + (size_t)c * 128 + lane * 4);
        const __half2* p = reinterpret_cast<const __half2*>(&r);
#pragma unroll
        for (int j = 0; j < 2; j++) {
            float2 f = __half22float2(p[j]);
            acc[2 * j]     += w * f.x;
            acc[2 * j + 1] += w * f.y;
        }
    }
    float4 b0 = *reinterpret_cast<const float4*>(bias + lane * 4);
    acc[0] += b0.x; acc[1] += b0.y; acc[2] += b0.z; acc[3] += b0.w;
    float sum = 0.f, sumsq = 0.f;
#pragma unroll
    for (int j = 0; j < 4; j++) { sum += acc[j]; sumsq += acc[j] * acc[j]; }
#pragma unroll
    for (int o = 16; o; o >>= 1) {
        sum += __shfl_xor_sync(0xffffffffu, sum, o);
        sumsq += __shfl_xor_sync(0xffffffffu, sumsq, o);
    }
    float mu = sum * (1.0f / 128.0f);
    float var = sumsq * (1.0f / 128.0f) - mu * mu;
    float r = rsqrtf(var + EPS_LN);
    float4 g0 = *reinterpret_cast<const float4*>(gam + lane * 4);
    float4 e0 = *reinterpret_cast<const float4*>(bet + lane * 4);
    float4 o0 = make_float4((acc[0] - mu) * r * g0.x + e0.x,
                            (acc[1] - mu) * r * g0.y + e0.y,
                            (acc[2] - mu) * r * g0.z + e0.z,
                            (acc[3] - mu) * r * g0.w + e0.w);
    *reinterpret_cast<float4*>(out + (size_t)warp * 128 + lane * 4) = o0;
}

// ---------------- host orchestration ----------------
static inline int ceil_div(int a, int b) { return (a + b - 1) / b; }

extern "C" void kernel_launch(void* const* d_in, const int* in_sizes, int n_in,
                              void* d_out, int out_size) {
    const float* x   = (const float*)d_in[0];
    const int*   ei  = (const int*)d_in[1];
    const float* ew  = (const float*)d_in[2];
    const float* W1  = (const float*)d_in[3];
    const float* as1 = (const float*)d_in[4];
    const float* ad1 = (const float*)d_in[5];
    const float* b1  = (const float*)d_in[6];
    const float* g1  = (const float*)d_in[7];
    const float* be1 = (const float*)d_in[8];
    const float* W2  = (const float*)d_in[9];
    const float* as2 = (const float*)d_in[10];
    const float* ad2 = (const float*)d_in[11];
    const float* b2  = (const float*)d_in[12];
    const float* g2  = (const float*)d_in[13];
    const float* be2 = (const float*)d_in[14];
    const float* W3  = (const float*)d_in[15];
    const float* as3 = (const float*)d_in[16];
    const float* ad3 = (const float*)d_in[17];
    const float* b3  = (const float*)d_in[18];
    const float* g3  = (const float*)d_in[19];
    const float* be3 = (const float*)d_in[20];
    float* out = (float*)d_out;

    const int* row = ei;
    const int* col = ei + NEDGE;

    float *alpha, *denomA, *denomB, *denomC, *score1, *score2, *score3;
    int *cnt, *rptr, *fill, *redges;
    __half *h16, *ahi, *wt1, *wt2, *wt3;
    cudaGetSymbolAddress((void**)&h16, g_h16);
    cudaGetSymbolAddress((void**)&alpha, g_alpha);
    cudaGetSymbolAddress((void**)&denomA, g_denomA);
    cudaGetSymbolAddress((void**)&denomB, g_denomB);
    cudaGetSymbolAddress((void**)&denomC, g_denomC);
    cudaGetSymbolAddress((void**)&score1, g_score1);
    cudaGetSymbolAddress((void**)&score2, g_score2);
    cudaGetSymbolAddress((void**)&score3, g_score3);
    cudaGetSymbolAddress((void**)&cnt, g_cnt);
    cudaGetSymbolAddress((void**)&rptr, g_rptr);
    cudaGetSymbolAddress((void**)&fill, g_fill);
    cudaGetSymbolAddress((void**)&redges, g_redges);
    cudaGetSymbolAddress((void**)&ahi, g_ahi);
    cudaGetSymbolAddress((void**)&wt1, g_wt1);
    cudaGetSymbolAddress((void**)&wt2, g_wt2);
    cudaGetSymbolAddress((void**)&wt3, g_wt3);

    const int TB = 256;
    const int eb = ceil_div(NEDGE, TB);
    const int mtA = NSPLIT / 128;
    const int mtB = ceil_div(NNODE, 128) - mtA;
    const int SMEM = 3 * 16384;

    cudaFuncSetAttribute(gemm_mma<256, 384>, cudaFuncAttributeMaxDynamicSharedMemorySize, SMEM);
    cudaFuncSetAttribute(gemm_mma<256, 256>, cudaFuncAttributeMaxDynamicSharedMemorySize, SMEM);
    cudaFuncSetAttribute(gemm_mma<128, 256>, cudaFuncAttributeMaxDynamicSharedMemorySize, SMEM);

    static cudaStream_t s1 = nullptr, s2 = nullptr;
    static cudaEvent_t ev0 = nullptr, evS2 = nullptr;
    static cudaEvent_t evR1 = nullptr, evR2 = nullptr;
    static cudaEvent_t evG1B = nullptr, evG2B = nullptr, evG3B = nullptr;
    if (!s1) {
        cudaStreamCreateWithFlags(&s1, cudaStreamNonBlocking);
        cudaStreamCreateWithFlags(&s2, cudaStreamNonBlocking);
        cudaEventCreateWithFlags(&ev0, cudaEventDisableTiming);
        cudaEventCreateWithFlags(&evS2, cudaEventDisableTiming);
        cudaEventCreateWithFlags(&evR1, cudaEventDisableTiming);
        cudaEventCreateWithFlags(&evR2, cudaEventDisableTiming);
        cudaEventCreateWithFlags(&evG1B, cudaEventDisableTiming);
        cudaEventCreateWithFlags(&evG2B, cudaEventDisableTiming);
        cudaEventCreateWithFlags(&evG3B, cudaEventDisableTiming);
    }

    // ---- fork ----
    cudaEventRecord(ev0, 0);
    cudaStreamWaitEvent(s1, ev0, 0);
    cudaStreamWaitEvent(s2, ev0, 0);

    // s2: CSR build + side prep
    zero_i<<<ceil_div(NNODE, TB), TB, 0, s2>>>(cnt, NNODE);
    hist_kernel<<<eb, TB, 0, s2>>>(row, cnt, NEDGE);
    scan_kernel<<<1, 1024, 0, s2>>>(cnt, rptr, fill, NNODE);
    scatter_kernel<<<eb, TB, 0, s2>>>(row, fill, redges, NEDGE);
    prep_side_kernel<<<ceil_div(NNODE * 8, TB), TB, 0, s2>>>(
        W2, wt2, W3, wt3, score2, score3, NNODE * 8, denomB, denomC, NNODE * 4);
    cudaEventRecord(evS2, s2);

    // ===== Layer 1 front, half-pipelined =====
    const int splitElems = NSPLIT * 384;
    asplit_fused_kernel<<<ceil_div(NNODE * 384, TB), TB>>>(
        x, ahi, 0, splitElems, W1, wt1, 384, 256,
        score1, NNODE * 8, denomA, NNODE * 4);
    gemm_mma<256, 384><<<dim3(2, mtA), 256, SMEM>>>(
        ahi, wt1, h16, as1, ad1, score1, score1 + NNODE * 4, 4, 64, NNODE, 0);
    asplit_fused_kernel<<<ceil_div(NNODE * 384 - splitElems, TB), TB, 0, s1>>>(
        x, ahi, splitElems, NNODE * 384 - splitElems, W1, wt1, 0, 0,
        nullptr, 0, nullptr, 0);
    gemm_mma<256, 384><<<dim3(2, mtB), 256, SMEM, s1>>>(
        ahi, wt1, h16, as1, ad1, score1, score1 + NNODE * 4, 4, 64, NNODE, mtA);
    cudaEventRecord(evG1B, s1);
    cudaStreamWaitEvent(0, evG1B, 0);

    edge_scores4_kernel<<<eb, TB>>>(row, col, ew, score1, score1 + NNODE * 4, alpha, denomA, NEDGE);
    rdenom_kernel<<<ceil_div(NNODE * 4, TB), TB>>>(denomA, NNODE * 4);
    cudaEventRecord(evR1, 0);
    cudaStreamWaitEvent(0, evS2, 0);
    cudaStreamWaitEvent(s1, evS2, 0);
    cudaStreamWaitEvent(s1, evR1, 0);

    // ===== aggln1 / gemm2 half-pipelined =====
    aggln256_kernel<<<ceil_div(NSPLIT * 32, TB), TB>>>(
        h16, alpha, denomA, col, rptr, redges, b1, g1, be1, ahi, 0, NSPLIT);
    gemm_mma<256, 256><<<dim3(2, mtA), 256, SMEM>>>(
        ahi, wt2, h16, as2, ad2, score2, score2 + NNODE * 4, 4, 64, NNODE, 0);
    aggln256_kernel<<<ceil_div((NNODE - NSPLIT) * 32, TB), TB, 0, s1>>>(
        h16, alpha, denomA, col, rptr, redges, b1, g1, be1, ahi, NSPLIT, NNODE);
    gemm_mma<256, 256><<<dim3(2, mtB), 256, SMEM, s1>>>(
        ahi, wt2, h16, as2, ad2, score2, score2 + NNODE * 4, 4, 64, NNODE, mtA);
    cudaEventRecord(evG2B, s1);
    cudaStreamWaitEvent(0, evG2B, 0);

    edge_scores4_kernel<<<eb, TB>>>(row, col, ew, score2, score2 + NNODE * 4, alpha, denomB, NEDGE);
    rdenom_kernel<<<ceil_div(NNODE * 4, TB), TB>>>(denomB, NNODE * 4);
    cudaEventRecord(evR2, 0);
    cudaStreamWaitEvent(s1, evR2, 0);

    // ===== aggln2 / gemm3 half-pipelined =====
    aggln256_kernel<<<ceil_div(NSPLIT * 32, TB), TB>>>(
        h16, alpha, denomB, col, rptr, redges, b2, g2, be2, ahi, 0, NSPLIT);
    gemm_mma<128, 256><<<dim3(1, mtA), 256, SMEM>>>(
        ahi, wt3, h16, as3, ad3, score3, score3 + NNODE * 4, 1, 128, NNODE, 0);
    aggln256_kernel<<<ceil_div((NNODE - NSPLIT) * 32, TB), TB, 0, s1>>>(
        h16, alpha, denomB, col, rptr, redges, b2, g2, be2, ahi, NSPLIT, NNODE);
    gemm_mma<128, 256><<<dim3(1, mtB), 256, SMEM, s1>>>(
        ahi, wt3, h16, as3, ad3, score3, score3 + NNODE * 4, 1, 128, NNODE, mtA);
    cudaEventRecord(evG3B, s1);
    cudaStreamWaitEvent(0, evG3B, 0);

    // ===== Layer 3 tail =====
    edge_scores1_kernel<<<eb, TB>>>(row, col, ew, score3, score3 + NNODE * 4, alpha, denomC, NEDGE);
    rdenom_kernel<<<ceil_div(NNODE, TB), TB>>>(denomC, NNODE);
    aggln128_kernel<<<ceil_div(NNODE * 32, TB), TB>>>(
        h16, alpha, denomC, col, rptr, redges, b3, g3, be3, out, NNODE);
}

// round 16
// speedup vs baseline: 1.3057x; 1.0167x over previous
#include <cuda_runtime.h>
#include <cuda_fp16.h>
#include <math.h>
#include <stdint.h>

#define NNODE 50000
#define NEDGE 500000
#define DMAX  256
#define EPS_SM 1e-16f
#define EPS_LN 1e-5f
#define NEG_SLOPE 0.2f
#define NSPLIT 25088            // 196 * 128

// ---------------- scratch (device globals) ----------------
__device__ __half g_h16[NNODE * DMAX];
__device__ float g_alpha[NEDGE * 4];
__device__ float g_denomA[NNODE * 4];
__device__ float g_denomB[NNODE * 4];
__device__ float g_denomC[NNODE * 4];
__device__ float g_score1[NNODE * 8];
__device__ float g_score2[NNODE * 8];
__device__ float g_score3[NNODE * 8];
__device__ int   g_cnt[NNODE];
__device__ int   g_rptr[NNODE + 1];
__device__ int   g_fill[NNODE];
__device__ int   g_redges[NEDGE];
__device__ __half g_ahi[NNODE * 384];
__device__ __half g_wt1[256 * 384];
__device__ __half g_wt2[256 * 256];
__device__ __half g_wt3[128 * 256];

// ================= PTX helpers =================
__device__ __forceinline__ uint32_t smem_u32(const void* p) {
    uint32_t a;
    asm("{ .reg .u64 t; cvta.to.shared.u64 t, %1; cvt.u32.u64 %0, t; }" : "=r"(a) : "l"(p));
    return a;
}

#define CPA16(dst, src, sz) \
    asm volatile("cp.async.cg.shared.global [%0], [%1], 16, %2;" \
                 :: "r"(dst), "l"(src), "r"(sz))
#define CPA_COMMIT() asm volatile("cp.async.commit_group;" ::: "memory")
#define CPA_WAIT(n)  asm volatile("cp.async.wait_group %0;" :: "n"(n) : "memory")

#define LDMX4(r0, r1, r2, r3, addr) \
    asm volatile("ldmatrix.sync.aligned.m8n8.x4.shared.b16 {%0,%1,%2,%3}, [%4];" \
                 : "=r"(r0), "=r"(r1), "=r"(r2), "=r"(r3) : "r"(addr))

__device__ __forceinline__ void mma16816h(float* c, const uint32_t* a, const uint32_t* b) {
    asm volatile(
        "mma.sync.aligned.m16n8k16.row.col.f32.f16.f16.f32 "
        "{%0,%1,%2,%3}, {%4,%5,%6,%7}, {%8,%9}, {%0,%1,%2,%3};"
        : "+f"(c[0]), "+f"(c[1]), "+f"(c[2]), "+f"(c[3])
        : "r"(a[0]), "r"(a[1]), "r"(a[2]), "r"(a[3]), "r"(b[0]), "r"(b[1]));
}

#define SWZ64(b) ((b) ^ (((b) >> 3) & 0x30))

// ---------------- small utility ----------------
__global__ void zero_i(int* p, int n) {
    int i = blockIdx.x * blockDim.x + threadIdx.x;
    if (i < n) p[i] = 0;
}

// ---------------- activation convert fp16 + optional prep ----------------
__global__ void asplit_fused_kernel(
    const float* __restrict__ A, __half* hi, int off, int cnt,
    const float* __restrict__ W, __half* wt, int K, int Nn,
    float* score, int nscore, float* den, int nden)
{
    int i = blockIdx.x * blockDim.x + threadIdx.x;
    if (i < cnt) {
        int j = off + i;
        hi[j] = __float2half(A[j]);
    }
    if (i < K * Nn) {
        int n = i / K, k = i - n * K;
        wt[i] = __float2half(W[(size_t)k * Nn + n]);
    }
    if (i < nscore) score[i] = 0.0f;
    if (i < nden) den[i] = 0.0f;
}

// ---------------- side prep ----------------
__global__ void prep_side_kernel(
    const float* __restrict__ W2, __half* wt2,
    const float* __restrict__ W3, __half* wt3,
    float* sc2, float* sc3, int nscore,
    float* dB, float* dC, int nden)
{
    int i = blockIdx.x * blockDim.x + threadIdx.x;
    if (i < 256 * 256) {
        int n = i / 256, k = i - n * 256;
        wt2[i] = __float2half(W2[(size_t)k * 256 + n]);
    }
    if (i < 128 * 256) {
        int n = i / 256, k = i - n * 256;
        wt3[i] = __float2half(W3[(size_t)k * 128 + n]);
    }
    if (i < nscore) { sc2[i] = 0.0f; sc3[i] = 0.0f; }
    if (i < nden) { dB[i] = 0.0f; dC[i] = 0.0f; }
}

// ---------------- CSR build ----------------
__global__ void hist_kernel(const int* __restrict__ row, int* cnt, int e) {
    int i = blockIdx.x * blockDim.x + threadIdx.x;
    if (i < e) atomicAdd(&cnt[row[i]], 1);
}

__global__ void scan_kernel(const int* __restrict__ cnt, int* ptr, int* fill, int n) {
    __shared__ int sh[1024];
    __shared__ int carry;
    if (threadIdx.x == 0) carry = 0;
    __syncthreads();
    for (int base = 0; base < n; base += 1024) {
        int i = base + threadIdx.x;
        int v = (i < n) ? cnt[i] : 0;
        sh[threadIdx.x] = v;
        __syncthreads();
        for (int off = 1; off < 1024; off <<= 1) {
            int t = (threadIdx.x >= off) ? sh[threadIdx.x - off] : 0;
            __syncthreads();
            sh[threadIdx.x] += t;
            __syncthreads();
        }
        int excl = sh[threadIdx.x] - v;
        if (i < n) { ptr[i] = carry + excl; fill[i] = carry + excl; }
        __syncthreads();
        if (threadIdx.x == 1023) carry += sh[1023];
        __syncthreads();
    }
    if (threadIdx.x == 0) ptr[n] = carry;
}

__global__ void scatter_kernel(const int* __restrict__ row, int* fill, int* redges, int e) {
    int i = blockIdx.x * blockDim.x + threadIdx.x;
    if (i < e) {
        int pos = atomicAdd(&fill[row[i]], 1);
        redges[pos] = i;
    }
}

// ===== HMMA fp16 GEMM 128x128 tile + fused attention scores =====
template <int NN, int KK>
__global__ __launch_bounds__(256, 2) void gemm_mma(
    const __half* __restrict__ Ahi,
    const __half* __restrict__ Bw,
    __half* __restrict__ C,
    const float* __restrict__ Av, const float* __restrict__ Dv,
    float* __restrict__ Ssrc, float* __restrict__ Sdst,
    int H, int Cc, int M, int moff)
{
    constexpr int BK = 32;
    constexpr int NCH = KK / BK;
    constexpr int STG = 16384;
    extern __shared__ char smem[];
    uint32_t sb = smem_u32(smem);

    int tid = threadIdx.x;
    int lane = tid & 31, wid = tid >> 5;
    int wm = wid & 3, wn = wid >> 2;
    int m0 = (blockIdx.y + moff) * 128;
    int n0 = blockIdx.x * 128;

    int g = lane >> 3, lr = lane & 7;
    uint32_t aoff[2][2];
#pragma unroll
    for (int mt = 0; mt < 2; mt++)
#pragma unroll
        for (int ks = 0; ks < 2; ks++) {
            int row = wm * 32 + mt * 16 + (g & 1) * 8 + lr;
            int unit = ks * 2 + (g >> 1);
            aoff[mt][ks] = SWZ64(row * 64 + unit * 16);
        }
    uint32_t boff[4][2];
#pragma unroll
    for (int np = 0; np < 4; np++)
#pragma unroll
        for (int ks = 0; ks < 2; ks++) {
            int row = wn * 64 + np * 16 + (g >> 1) * 8 + lr;
            int unit = ks * 2 + (g & 1);
            boff[np][ks] = 8192u + SWZ64(row * 64 + unit * 16);
        }

    int r0 = tid >> 2, u0 = tid & 3;
    uint32_t sw0 = SWZ64(r0 * 64 + u0 * 16);
    uint32_t sw1 = SWZ64((r0 + 64) * 64 + u0 * 16);
    long bofs0 = (long)(n0 + r0) * KK + u0 * 8;
    long bofs1 = (long)(n0 + r0 + 64) * KK + u0 * 8;

    float acc[2][8][4];
#pragma unroll
    for (int mt = 0; mt < 2; mt++)
#pragma unroll
        for (int nt = 0; nt < 8; nt++)
#pragma unroll
            for (int j = 0; j < 4; j++) acc[mt][nt][j] = 0.f;

    auto load_stage = [&](int ch, uint32_t so) {
        int k0 = ch * BK;
        {
            int grow = m0 + r0;
            int sz = (grow < M) ? 16 : 0;
            long go = (long)((grow < M) ? grow : 0) * KK + k0 + u0 * 8;
            CPA16(sb + so + sw0, Ahi + go, sz);
        }
        {
            int grow = m0 + r0 + 64;
            int sz = (grow < M) ? 16 : 0;
            long go = (long)((grow < M) ? grow : 0) * KK + k0 + u0 * 8;
            CPA16(sb + so + sw1, Ahi + go, sz);
        }
        CPA16(sb + so + 8192 + sw0, Bw + bofs0 + k0, 16);
        CPA16(sb + so + 8192 + sw1, Bw + bofs1 + k0, 16);
    };

    auto compute_stage = [&](uint32_t so) {
#pragma unroll
        for (int ks = 0; ks < 2; ks++) {
            uint32_t ah[2][4], b[8][2];
#pragma unroll
            for (int mt = 0; mt < 2; mt++)
                LDMX4(ah[mt][0], ah[mt][1], ah[mt][2], ah[mt][3], sb + so + aoff[mt][ks]);
#pragma unroll
            for (int np = 0; np < 4; np++)
                LDMX4(b[2 * np][0], b[2 * np][1], b[2 * np + 1][0], b[2 * np + 1][1],
                      sb + so + boff[np][ks]);
#pragma unroll
            for (int mt = 0; mt < 2; mt++)
#pragma unroll
                for (int nt = 0; nt < 8; nt++)
                    mma16816h(acc[mt][nt], ah[mt], b[nt]);
        }
    };

    load_stage(0, 0);
    CPA_COMMIT();
    load_stage(1, STG);
    CPA_COMMIT();
#pragma unroll 1
    for (int ch = 0; ch < NCH; ch++) {
        uint32_t so = (uint32_t)(ch % 3) * STG;
        if (ch + 1 < NCH) { CPA_WAIT(1); } else { CPA_WAIT(0); }
        __syncthreads();
        if (ch + 2 < NCH) {
            load_stage(ch + 2, (uint32_t)((ch + 2) % 3) * STG);
            CPA_COMMIT();
        }
        compute_stage(so);
    }

    // epilogue 1: fp16 h store
#pragma unroll
    for (int mt = 0; mt < 2; mt++) {
        int m = m0 + wm * 32 + mt * 16 + (lane >> 2);
#pragma unroll
        for (int nt = 0; nt < 8; nt++) {
            int n = n0 + wn * 64 + nt * 8 + (lane & 3) * 2;
            if (m < M)
                *reinterpret_cast<__half2*>(C + (size_t)m * NN + n) =
                    __floats2half2_rn(acc[mt][nt][0], acc[mt][nt][1]);
            if (m + 8 < M)
                *reinterpret_cast<__half2*>(C + (size_t)(m + 8) * NN + n) =
                    __floats2half2_rn(acc[mt][nt][2], acc[mt][nt][3]);
        }
    }

    // epilogue 2: fused attention scores
    {
        int head = (n0 + wn * 64) / Cc;
        float av[16], dv[16];
#pragma unroll
        for (int nt = 0; nt < 8; nt++) {
            int c0 = (n0 + wn * 64 + nt * 8 + (lane & 3) * 2) - head * Cc;
            av[2 * nt] = Av[head * Cc + c0];
            av[2 * nt + 1] = Av[head * Cc + c0 + 1];
            dv[2 * nt] = Dv[head * Cc + c0];
            dv[2 * nt + 1] = Dv[head * Cc + c0 + 1];
        }
#pragma unroll
        for (int mt = 0; mt < 2; mt++) {
            float ps0 = 0.f, pd0 = 0.f, ps1 = 0.f, pd1 = 0.f;
#pragma unroll
            for (int nt = 0; nt < 8; nt++) {
                ps0 += acc[mt][nt][0] * av[2 * nt] + acc[mt][nt][1] * av[2 * nt + 1];
                pd0 += acc[mt][nt][0] * dv[2 * nt] + acc[mt][nt][1] * dv[2 * nt + 1];
                ps1 += acc[mt][nt][2] * av[2 * nt] + acc[mt][nt][3] * av[2 * nt + 1];
                pd1 += acc[mt][nt][2] * dv[2 * nt] + acc[mt][nt][3] * dv[2 * nt + 1];
            }
#pragma unroll
            for (int o = 1; o <= 2; o <<= 1) {
                ps0 += __shfl_xor_sync(0xffffffffu, ps0, o);
                pd0 += __shfl_xor_sync(0xffffffffu, pd0, o);
                ps1 += __shfl_xor_sync(0xffffffffu, ps1, o);
                pd1 += __shfl_xor_sync(0xffffffffu, pd1, o);
            }
            if ((lane & 3) == 0) {
                int m = m0 + wm * 32 + mt * 16 + (lane >> 2);
                if (m < M) {
                    atomicAdd(&Ssrc[m * H + head], ps0);
                    atomicAdd(&Sdst[m * H + head], pd0);
                }
                if (m + 8 < M) {
                    atomicAdd(&Ssrc[(m + 8) * H + head], ps1);
                    atomicAdd(&Sdst[(m + 8) * H + head], pd1);
                }
            }
        }
    }
}

// ---------------- edge scores H=4 ----------------
__global__ void edge_scores4_kernel(
    const int* __restrict__ row, const int* __restrict__ col, const float* __restrict__ ew,
    const float* __restrict__ ssrc, const float* __restrict__ sdst,
    float* __restrict__ aexp, float* __restrict__ denom, int e)
{
    int i = blockIdx.x * blockDim.x + threadIdx.x;
    if (i >= e) return;
    int r = row[i], c = col[i];
    float w = ew[i];
    float4 s4 = *reinterpret_cast<const float4*>(ssrc + (size_t)r * 4);
    float4 d4 = *reinterpret_cast<const float4*>(sdst + (size_t)c * 4);
    float4 o;
    float v;
    v = s4.x + d4.x; v = (v >= 0.f) ? v : NEG_SLOPE * v; o.x = expf(v * w);
    v = s4.y + d4.y; v = (v >= 0.f) ? v : NEG_SLOPE * v; o.y = expf(v * w);
    v = s4.z + d4.z; v = (v >= 0.f) ? v : NEG_SLOPE * v; o.z = expf(v * w);
    v = s4.w + d4.w; v = (v >= 0.f) ? v : NEG_SLOPE * v; o.w = expf(v * w);
    *reinterpret_cast<float4*>(aexp + (size_t)i * 4) = o;
    atomicAdd(&denom[c * 4 + 0], o.x);
    atomicAdd(&denom[c * 4 + 1], o.y);
    atomicAdd(&denom[c * 4 + 2], o.z);
    atomicAdd(&denom[c * 4 + 3], o.w);
}

// ---------------- edge scores H=1 ----------------
__global__ void edge_scores1_kernel(
    const int* __restrict__ row, const int* __restrict__ col, const float* __restrict__ ew,
    const float* __restrict__ ssrc, const float* __restrict__ sdst,
    float* __restrict__ aexp, float* __restrict__ denom, int e)
{
    int i = blockIdx.x * blockDim.x + threadIdx.x;
    if (i >= e) return;
    int r = row[i], c = col[i];
    float v = ssrc[r] + sdst[c];
    v = (v >= 0.f) ? v : NEG_SLOPE * v;
    v = expf(v * ew[i]);
    aexp[i] = v;
    atomicAdd(&denom[c], v);
}

// ---------------- reciprocal of denominators ----------------
__global__ void rdenom_kernel(float* d, int n) {
    int i = blockIdx.x * blockDim.x + threadIdx.x;
    if (i < n) d[i] = 1.0f / (d[i] + EPS_SM);
}

// ===== fused aggregation(D=256,H=4) + bias + LN + ELU -> fp16, 4-edge unroll =====
__global__ __launch_bounds__(256) void aggln256_kernel(
    const __half* __restrict__ h, const float* __restrict__ aexp, const float* __restrict__ rden,
    const int* __restrict__ col, const int* __restrict__ rptr, const int* __restrict__ redges,
    const float* __restrict__ bias, const float* __restrict__ gam, const float* __restrict__ bet,
    __half* __restrict__ hi, int noff, int nend)
{
    int warp = ((blockIdx.x * blockDim.x + threadIdx.x) >> 5) + noff;
    int lane = threadIdx.x & 31;
    if (warp >= nend) return;
    int hh = lane >> 3;
    float acc[8];
#pragma unroll
    for (int j = 0; j < 8; j++) acc[j] = 0.f;
    int s = rptr[warp], e1 = rptr[warp + 1];
    int i = s;
    for (; i + 3 < e1; i += 4) {
        int e0 = redges[i], ee1 = redges[i + 1], e2 = redges[i + 2], e3 = redges[i + 3];
        int c0 = col[e0], c1 = col[ee1], c2 = col[e2], c3 = col[e3];
        float w0 = aexp[(size_t)e0 * 4 + hh] * rden[(size_t)c0 * 4 + hh];
        float w1 = aexp[(size_t)ee1 * 4 + hh] * rden[(size_t)c1 * 4 + hh];
        float w2 = aexp[(size_t)e2 * 4 + hh] * rden[(size_t)c2 * 4 + hh];
        float w3 = aexp[(size_t)e3 * 4 + hh] * rden[(size_t)c3 * 4 + hh];
        uint4 r0 = *reinterpret_cast<const uint4*>(h + (size_t)c0 * 256 + lane * 8);
        uint4 r1 = *reinterpret_cast<const uint4*>(h + (size_t)c1 * 256 + lane * 8);
        uint4 r2 = *reinterpret_cast<const uint4*>(h + (size_t)c2 * 256 + lane * 8);
        uint4 r3 = *reinterpret_cast<const uint4*>(h + (size_t)c3 * 256 + lane * 8);
        const __half2* p0 = reinterpret_cast<const __half2*>(&r0);
        const __half2* p1 = reinterpret_cast<const __half2*>(&r1);
        const __half2* p2 = reinterpret_cast<const __half2*>(&r2);
        const __half2* p3 = reinterpret_cast<const __half2*>(&r3);
#pragma unroll
        for (int j = 0; j < 4; j++) {
            float2 f0 = __half22float2(p0[j]);
            float2 f1 = __half22float2(p1[j]);
            float2 f2 = __half22float2(p2[j]);
            float2 f3 = __half22float2(p3[j]);
            acc[2 * j]     += (w0 * f0.x + w1 * f1.x) + (w2 * f2.x + w3 * f3.x);
            acc[2 * j + 1] += (w0 * f0.y + w1 * f1.y) + (w2 * f2.y + w3 * f3.y);
        }
    }
    for (; i < e1; i++) {
        int e = redges[i];
        int c = col[e];
        float w = aexp[(size_t)e * 4 + hh] * rden[(size_t)c * 4 + hh];
        uint4 r = *reinterpret_cast<const uint4*>(h + (size_t)c * 256 + lane * 8);
        const __half2* p = reinterpret_cast<const __half2*>(&r);
#pragma unroll
        for (int j = 0; j < 4; j++) {
            float2 f = __half22float2(p[j]);
            acc[2 * j]     += w * f.x;
            acc[2 * j + 1] += w * f.y;
        }
    }
    const float4* bp = reinterpret_cast<const float4*>(bias + lane * 8);
    float4 b0 = bp[0], b1 = bp[1];
    acc[0] += b0.x; acc[1] += b0.y; acc[2] += b0.z; acc[3] += b0.w;
    acc[4] += b1.x; acc[5] += b1.y; acc[6] += b1.z; acc[7] += b1.w;
    float sum = 0.f, sumsq = 0.f;
#pragma unroll
    for (int j = 0; j < 8; j++) { sum += acc[j]; sumsq += acc[j] * acc[j]; }
#pragma unroll
    for (int o = 16; o; o >>= 1) {
        sum += __shfl_xor_sync(0xffffffffu, sum, o);
        sumsq += __shfl_xor_sync(0xffffffffu, sumsq, o);
    }
    float mu = sum * (1.0f / 256.0f);
    float var = sumsq * (1.0f / 256.0f) - mu * mu;
    float r = rsqrtf(var + EPS_LN);
    const float4* gp = reinterpret_cast<const float4*>(gam + lane * 8);
    const float4* ep = reinterpret_cast<const float4*>(bet + lane * 8);
    float4 g0 = gp[0], g1 = gp[1], e0 = ep[0], e1v = ep[1];
    float gg[8] = {g0.x, g0.y, g0.z, g0.w, g1.x, g1.y, g1.z, g1.w};
    float ee[8] = {e0.x, e0.y, e0.z, e0.w, e1v.x, e1v.y, e1v.z, e1v.w};
    union { __half2 h2[4]; uint4 u; } uh;
#pragma unroll
    for (int j = 0; j < 4; j++) {
        float y0 = (acc[2 * j] - mu) * r * gg[2 * j] + ee[2 * j];
        float y1 = (acc[2 * j + 1] - mu) * r * gg[2 * j + 1] + ee[2 * j + 1];
        y0 = (y0 > 0.f) ? y0 : expm1f(y0);
        y1 = (y1 > 0.f) ? y1 : expm1f(y1);
        uh.h2[j] = __halves2half2(__float2half(y0), __float2half(y1));
    }
    *reinterpret_cast<uint4*>(hi + (size_t)warp * 256 + lane * 8) = uh.u;
}

// ===== fused aggregation(D=128,H=1) + bias + final LN -> fp32, 4-edge unroll =====
__global__ __launch_bounds__(256) void aggln128_kernel(
    const __half* __restrict__ h, const float* __restrict__ aexp, const float* __restrict__ rden,
    const int* __restrict__ col, const int* __restrict__ rptr, const int* __restrict__ redges,
    const float* __restrict__ bias, const float* __restrict__ gam, const float* __restrict__ bet,
    float* __restrict__ out, int n)
{
    int warp = (blockIdx.x * blockDim.x + threadIdx.x) >> 5;
    int lane = threadIdx.x & 31;
    if (warp >= n) return;
    float acc[4];
#pragma unroll
    for (int j = 0; j < 4; j++) acc[j] = 0.f;
    int s = rptr[warp], e1 = rptr[warp + 1];
    int i = s;
    for (; i + 3 < e1; i += 4) {
        int e0 = redges[i], ee1 = redges[i + 1], e2 = redges[i + 2], e3 = redges[i + 3];
        int c0 = col[e0], c1 = col[ee1], c2 = col[e2], c3 = col[e3];
        float w0 = aexp[e0] * rden[c0];
        float w1 = aexp[ee1] * rden[c1];
        float w2 = aexp[e2] * rden[c2];
        float w3 = aexp[e3] * rden[c3];
        uint2 r0 = *reinterpret_cast<const uint2*>(h + (size_t)c0 * 128 + lane * 4);
        uint2 r1 = *reinterpret_cast<const uint2*>(h + (size_t)c1 * 128 + lane * 4);
        uint2 r2 = *reinterpret_cast<const uint2*>(h + (size_t)c2 * 128 + lane * 4);
        uint2 r3 = *reinterpret_cast<const uint2*>(h + (size_t)c3 * 128 + lane * 4);
        const __half2* p0 = reinterpret_cast<const __half2*>(&r0);
        const __half2* p1 = reinterpret_cast<const __half2*>(&r1);
        const __half2* p2 = reinterpret_cast<const __half2*>(&r2);
        const __half2* p3 = reinterpret_cast<const __half2*>(&r3);
#pragma unroll
        for (int j = 0; j < 2; j++) {
            float2 f0 = __half22float2(p0[j]);
            float2 f1 = __half22float2(p1[j]);
            float2 f2 = __half22float2(p2[j]);
            float2 f3 = __half22float2(p3[j]);
            acc[2 * j]     += (w0 * f0.x + w1 * f1.x) + (w2 * f2.x + w3 * f3.x);
            acc[2 * j + 1] += (w0 * f0.y + w1 * f1.y) + (w2 * f2.y + w3 * f3.y);
        }
    }
    for (; i < e1; i++) {
        int e = redges[i];
        int c = col[e];
        float w = aexp[e] * rden[c];
        uint2 r = *reinterpret_cast<const uint2*>(h + (size_t)c * 128 + lane * 4);
        const __half2* p = reinterpret_cast<const __half2*>(&r);
#pragma unroll
        for (int j = 0; j < 2; j++) {
            float2 f = __half22float2(p[j]);
            acc[2 * j]     += w * f.x;
            acc[2 * j + 1] += w * f.y;
        }
    }
    float4 b0 = *reinterpret_cast<const float4*>(bias + lane * 4);
    acc[0] += b0.x; acc[1] += b0.y; acc[2] += b0.z; acc[3] += b0.w;
    float sum = 0.f, sumsq = 0.f;
#pragma unroll
    for (int j = 0; j < 4; j++) { sum += acc[j]; sumsq += acc[j] * acc[j]; }
#pragma unroll
    for (int o = 16; o; o >>= 1) {
        sum += __shfl_xor_sync(0xffffffffu, sum, o);
        sumsq += __shfl_xor_sync(0xffffffffu, sumsq, o);
    }
    float mu = sum * (1.0f / 128.0f);
    float var = sumsq * (1.0f / 128.0f) - mu * mu;
    float r = rsqrtf(var + EPS_LN);
    float4 g0 = *reinterpret_cast<const float4*>(gam + lane * 4);
    float4 e0 = *reinterpret_cast<const float4*>(bet + lane * 4);
    float4 o0 = make_float4((acc[0] - mu) * r * g0.x + e0.x,
                            (acc[1] - mu) * r * g0.y + e0.y,
                            (acc[2] - mu) * r * g0.z + e0.z,
                            (acc[3] - mu) * r * g0.w + e0.w);
    *reinterpret_cast<float4*>(out + (size_t)warp * 128 + lane * 4) = o0;
}

// ---------------- host orchestration ----------------
static inline int ceil_div(int a, int b) { return (a + b - 1) / b; }

extern "C" void kernel_launch(void* const* d_in, const int* in_sizes, int n_in,
                              void* d_out, int out_size) {
    const float* x   = (const float*)d_in[0];
    const int*   ei  = (const int*)d_in[1];
    const float* ew  = (const float*)d_in[2];
    const float* W1  = (const float*)d_in[3];
    const float* as1 = (const float*)d_in[4];
    const float* ad1 = (const float*)d_in[5];
    const float* b1  = (const float*)d_in[6];
    const float* g1  = (const float*)d_in[7];
    const float* be1 = (const float*)d_in[8];
    const float* W2  = (const float*)d_in[9];
    const float* as2 = (const float*)d_in[10];
    const float* ad2 = (const float*)d_in[11];
    const float* b2  = (const float*)d_in[12];
    const float* g2  = (const float*)d_in[13];
    const float* be2 = (const float*)d_in[14];
    const float* W3  = (const float*)d_in[15];
    const float* as3 = (const float*)d_in[16];
    const float* ad3 = (const float*)d_in[17];
    const float* b3  = (const float*)d_in[18];
    const float* g3  = (const float*)d_in[19];
    const float* be3 = (const float*)d_in[20];
    float* out = (float*)d_out;

    const int* row = ei;
    const int* col = ei + NEDGE;

    float *alpha, *denomA, *denomB, *denomC, *score1, *score2, *score3;
    int *cnt, *rptr, *fill, *redges;
    __half *h16, *ahi, *wt1, *wt2, *wt3;
    cudaGetSymbolAddress((void**)&h16, g_h16);
    cudaGetSymbolAddress((void**)&alpha, g_alpha);
    cudaGetSymbolAddress((void**)&denomA, g_denomA);
    cudaGetSymbolAddress((void**)&denomB, g_denomB);
    cudaGetSymbolAddress((void**)&denomC, g_denomC);
    cudaGetSymbolAddress((void**)&score1, g_score1);
    cudaGetSymbolAddress((void**)&score2, g_score2);
    cudaGetSymbolAddress((void**)&score3, g_score3);
    cudaGetSymbolAddress((void**)&cnt, g_cnt);
    cudaGetSymbolAddress((void**)&rptr, g_rptr);
    cudaGetSymbolAddress((void**)&fill, g_fill);
    cudaGetSymbolAddress((void**)&redges, g_redges);
    cudaGetSymbolAddress((void**)&ahi, g_ahi);
    cudaGetSymbolAddress((void**)&wt1, g_wt1);
    cudaGetSymbolAddress((void**)&wt2, g_wt2);
    cudaGetSymbolAddress((void**)&wt3, g_wt3);

    const int TB = 256;
    const int eb = ceil_div(NEDGE, TB);
    const int mtA = NSPLIT / 128;
    const int mtB = ceil_div(NNODE, 128) - mtA;
    const int SMEM = 3 * 16384;

    cudaFuncSetAttribute(gemm_mma<256, 384>, cudaFuncAttributeMaxDynamicSharedMemorySize, SMEM);
    cudaFuncSetAttribute(gemm_mma<256, 256>, cudaFuncAttributeMaxDynamicSharedMemorySize, SMEM);
    cudaFuncSetAttribute(gemm_mma<128, 256>, cudaFuncAttributeMaxDynamicSharedMemorySize, SMEM);

    static cudaStream_t s1 = nullptr, s2 = nullptr;
    static cudaEvent_t ev0 = nullptr, evS2 = nullptr;
    static cudaEvent_t evR1 = nullptr, evR2 = nullptr;
    static cudaEvent_t evG1B = nullptr, evG2B = nullptr, evG3B = nullptr;
    if (!s1) {
        cudaStreamCreateWithFlags(&s1, cudaStreamNonBlocking);
        cudaStreamCreateWithFlags(&s2, cudaStreamNonBlocking);
        cudaEventCreateWithFlags(&ev0, cudaEventDisableTiming);
        cudaEventCreateWithFlags(&evS2, cudaEventDisableTiming);
        cudaEventCreateWithFlags(&evR1, cudaEventDisableTiming);
        cudaEventCreateWithFlags(&evR2, cudaEventDisableTiming);
        cudaEventCreateWithFlags(&evG1B, cudaEventDisableTiming);
        cudaEventCreateWithFlags(&evG2B, cudaEventDisableTiming);
        cudaEventCreateWithFlags(&evG3B, cudaEventDisableTiming);
    }

    // ---- fork ----
    cudaEventRecord(ev0, 0);
    cudaStreamWaitEvent(s1, ev0, 0);
    cudaStreamWaitEvent(s2, ev0, 0);

    // s2: CSR build + side prep
    zero_i<<<ceil_div(NNODE, TB), TB, 0, s2>>>(cnt, NNODE);
    hist_kernel<<<eb, TB, 0, s2>>>(row, cnt, NEDGE);
    scan_kernel<<<1, 1024, 0, s2>>>(cnt, rptr, fill, NNODE);
    scatter_kernel<<<eb, TB, 0, s2>>>(row, fill, redges, NEDGE);
    prep_side_kernel<<<ceil_div(NNODE * 8, TB), TB, 0, s2>>>(
        W2, wt2, W3, wt3, score2, score3, NNODE * 8, denomB, denomC, NNODE * 4);
    cudaEventRecord(evS2, s2);

    // ===== Layer 1 front, half-pipelined =====
    const int splitElems = NSPLIT * 384;
    asplit_fused_kernel<<<ceil_div(NNODE * 384, TB), TB>>>(
        x, ahi, 0, splitElems, W1, wt1, 384, 256,
        score1, NNODE * 8, denomA, NNODE * 4);
    gemm_mma<256, 384><<<dim3(2, mtA), 256, SMEM>>>(
        ahi, wt1, h16, as1, ad1, score1, score1 + NNODE * 4, 4, 64, NNODE, 0);
    asplit_fused_kernel<<<ceil_div(NNODE * 384 - splitElems, TB), TB, 0, s1>>>(
        x, ahi, splitElems, NNODE * 384 - splitElems, W1, wt1, 0, 0,
        nullptr, 0, nullptr, 0);
    gemm_mma<256, 384><<<dim3(2, mtB), 256, SMEM, s1>>>(
        ahi, wt1, h16, as1, ad1, score1, score1 + NNODE * 4, 4, 64, NNODE, mtA);
    cudaEventRecord(evG1B, s1);
    cudaStreamWaitEvent(0, evG1B, 0);

    edge_scores4_kernel<<<eb, TB>>>(row, col, ew, score1, score1 + NNODE * 4, alpha, denomA, NEDGE);
    rdenom_kernel<<<ceil_div(NNODE * 4, TB), TB>>>(denomA, NNODE * 4);
    cudaEventRecord(evR1, 0);
    cudaStreamWaitEvent(0, evS2, 0);
    cudaStreamWaitEvent(s1, evS2, 0);
    cudaStreamWaitEvent(s1, evR1, 0);

    // ===== aggln1 / gemm2 half-pipelined =====
    aggln256_kernel<<<ceil_div(NSPLIT * 32, TB), TB>>>(
        h16, alpha, denomA, col, rptr, redges, b1, g1, be1, ahi, 0, NSPLIT);
    gemm_mma<256, 256><<<dim3(2, mtA), 256, SMEM>>>(
        ahi, wt2, h16, as2, ad2, score2, score2 + NNODE * 4, 4, 64, NNODE, 0);
    aggln256_kernel<<<ceil_div((NNODE - NSPLIT) * 32, TB), TB, 0, s1>>>(
        h16, alpha, denomA, col, rptr, redges, b1, g1, be1, ahi, NSPLIT, NNODE);
    gemm_mma<256, 256><<<dim3(2, mtB), 256, SMEM, s1>>>(
        ahi, wt2, h16, as2, ad2, score2, score2 + NNODE * 4, 4, 64, NNODE, mtA);
    cudaEventRecord(evG2B, s1);
    cudaStreamWaitEvent(0, evG2B, 0);

    edge_scores4_kernel<<<eb, TB>>>(row, col, ew, score2, score2 + NNODE * 4, alpha, denomB, NEDGE);
    rdenom_kernel<<<ceil_div(NNODE * 4, TB), TB>>>(denomB, NNODE * 4);
    cudaEventRecord(evR2, 0);
    cudaStreamWaitEvent(s1, evR2, 0);

    // ===== aggln2 / gemm3 half-pipelined =====
    aggln256_kernel<<<ceil_div(NSPLIT * 32, TB), TB>>>(
        h16, alpha, denomB, col, rptr, redges, b2, g2, be2, ahi, 0, NSPLIT);
    gemm_mma<128, 256><<<dim3(1, mtA), 256, SMEM>>>(
        ahi, wt3, h16, as3, ad3, score3, score3 + NNODE * 4, 1, 128, NNODE, 0);
    aggln256_kernel<<<ceil_div((NNODE - NSPLIT) * 32, TB), TB, 0, s1>>>(
        h16, alpha, denomB, col, rptr, redges, b2, g2, be2, ahi, NSPLIT, NNODE);
    gemm_mma<128, 256><<<dim3(1, mtB), 256, SMEM, s1>>>(
        ahi, wt3, h16, as3, ad3, score3, score3 + NNODE * 4, 1, 128, NNODE, mtA);
    cudaEventRecord(evG3B, s1);
    cudaStreamWaitEvent(0, evG3B, 0);

    // ===== Layer 3 tail =====
    edge_scores1_kernel<<<eb, TB>>>(row, col, ew, score3, score3 + NNODE * 4, alpha, denomC, NEDGE);
    rdenom_kernel<<<ceil_div(NNODE, TB), TB>>>(denomC, NNODE);
    aggln128_kernel<<<ceil_div(NNODE * 32, TB), TB>>>(
        h16, alpha, denomC, col, rptr, redges, b3, g3, be3, out, NNODE);
}